// round 1
// baseline (speedup 1.0000x reference)
#include <cuda_runtime.h>

// Problem constants
#define B_   16
#define C_   512
#define T_   1024            // H*W = 32*32
#define G_   32
#define CPG  (C_ / G_)       // 16 channels per group
#define EPS  1e-5f

// ---------------------------------------------------------------------------
// Scratch buffers (static __device__ — no allocation allowed)
// ---------------------------------------------------------------------------
__device__ float g_h[(size_t)B_ * C_ * T_];   // groupnorm output, [B, C, T]
__device__ float g_q[(size_t)B_ * T_ * C_];   // q, [B, T, C] (scaled by C^-1/2)
__device__ float g_k[(size_t)B_ * T_ * C_];   // k, [B, T, C]
__device__ float g_v[(size_t)B_ * T_ * C_];   // v, [B, T, C]
__device__ float g_w[(size_t)B_ * T_ * T_];   // attention scores, [B, T, T]
__device__ float g_a[(size_t)B_ * T_ * C_];   // attn output, [B, T, C]

// ---------------------------------------------------------------------------
// GroupNorm: one block per (b, g). Reduce 16*1024 = 16384 elements.
// ---------------------------------------------------------------------------
__global__ __launch_bounds__(256) void groupnorm_kernel(
    const float* __restrict__ x,
    const float* __restrict__ gamma,
    const float* __restrict__ beta,
    float* __restrict__ h)
{
    const int b = blockIdx.x >> 5;      // / G_
    const int g = blockIdx.x & 31;      // % G_
    const size_t base = ((size_t)b * C_ + (size_t)g * CPG) * T_;
    const float4* xp = (const float4*)(x + base);
    float4* hp = (float4*)(h + base);
    const int N4 = CPG * T_ / 4;        // 4096 float4s
    const int tid = threadIdx.x;

    float s = 0.f, s2 = 0.f;
    for (int i = tid; i < N4; i += 256) {
        float4 v = xp[i];
        s  += v.x + v.y + v.z + v.w;
        s2 += v.x * v.x + v.y * v.y + v.z * v.z + v.w * v.w;
    }
    // warp reduce
    #pragma unroll
    for (int o = 16; o > 0; o >>= 1) {
        s  += __shfl_xor_sync(0xffffffffu, s, o);
        s2 += __shfl_xor_sync(0xffffffffu, s2, o);
    }
    __shared__ float sh1[8], sh2[8];
    const int wid = tid >> 5, lane = tid & 31;
    if (lane == 0) { sh1[wid] = s; sh2[wid] = s2; }
    __syncthreads();
    if (tid == 0) {
        float a = 0.f, bb = 0.f;
        #pragma unroll
        for (int i = 0; i < 8; i++) { a += sh1[i]; bb += sh2[i]; }
        sh1[0] = a; sh2[0] = bb;
    }
    __syncthreads();
    const float inv_n = 1.0f / (float)(CPG * T_);
    const float mean = sh1[0] * inv_n;
    const float var  = sh2[0] * inv_n - mean * mean;
    const float inv  = rsqrtf(var + EPS);

    for (int i = tid; i < N4; i += 256) {
        const int c = g * CPG + (i >> 8);          // (i*4)/T_ ; T_/4 = 256
        const float ga = gamma[c] * inv;
        const float be = beta[c];
        float4 v = xp[i];
        v.x = (v.x - mean) * ga + be;
        v.y = (v.y - mean) * ga + be;
        v.z = (v.z - mean) * ga + be;
        v.w = (v.w - mean) * ga + be;
        hp[i] = v;
    }
}

// ---------------------------------------------------------------------------
// Generic batched SGEMM: C[m,n] = epilogue( sum_k A[m,k] * B[k,n] )
// 128x128 tile, Ktile=16, 256 threads, 8x8 per thread.
// Runtime strides; all problem dims are multiples of 128/16 so no bounds checks.
// Epilogue: out = (acc + bias) * alpha + resid, bias indexed by n or m.
// ---------------------------------------------------------------------------
__global__ __launch_bounds__(256) void gemm128(
    int M, int N, int K,
    const float* __restrict__ A, size_t Abs, int sam, int sak,
    const float* __restrict__ Bp, size_t Bbs, int sbk, int sbn,
    float* __restrict__ Cp, size_t Cbs,
    const float* __restrict__ bias, int bias_on_n,
    float alpha,
    const float* __restrict__ resid, size_t Rbs)
{
    const int bz = blockIdx.z;
    A  += (size_t)bz * Abs;
    Bp += (size_t)bz * Bbs;
    Cp += (size_t)bz * Cbs;
    if (resid) resid += (size_t)bz * Rbs;

    __shared__ float As[16][132];
    __shared__ float Bs[16][132];

    const int m0 = blockIdx.y * 128;
    const int n0 = blockIdx.x * 128;
    const int tid = threadIdx.x;
    const int tx = tid & 15;   // n direction
    const int ty = tid >> 4;   // m direction

    float acc[8][8];
    #pragma unroll
    for (int i = 0; i < 8; i++)
        #pragma unroll
        for (int j = 0; j < 8; j++) acc[i][j] = 0.f;

    for (int k0 = 0; k0 < K; k0 += 16) {
        // ---- load A tile: 128(m) x 16(k), 2048 elems, 8/thread ----
        if (sak == 1) {
            // k contiguous: consecutive tids walk k
            #pragma unroll
            for (int i = 0; i < 8; i++) {
                int idx = tid + i * 256;
                int m = idx >> 4, k = idx & 15;
                As[k][m] = A[(size_t)(m0 + m) * sam + (size_t)(k0 + k)];
            }
        } else {
            // m contiguous (sam==1): consecutive tids walk m
            #pragma unroll
            for (int i = 0; i < 8; i++) {
                int idx = tid + i * 256;
                int k = idx >> 7, m = idx & 127;
                As[k][m] = A[(size_t)(m0 + m) * sam + (size_t)(k0 + k) * sak];
            }
        }
        // ---- load B tile: 16(k) x 128(n) ----
        if (sbn == 1) {
            #pragma unroll
            for (int i = 0; i < 8; i++) {
                int idx = tid + i * 256;
                int k = idx >> 7, n = idx & 127;
                Bs[k][n] = Bp[(size_t)(k0 + k) * sbk + (size_t)(n0 + n)];
            }
        } else {
            // sbk == 1: consecutive tids walk k
            #pragma unroll
            for (int i = 0; i < 8; i++) {
                int idx = tid + i * 256;
                int n = idx >> 4, k = idx & 15;
                Bs[k][n] = Bp[(size_t)(k0 + k) + (size_t)(n0 + n) * sbn];
            }
        }
        __syncthreads();

        #pragma unroll
        for (int k = 0; k < 16; k++) {
            float a[8], bb[8];
            #pragma unroll
            for (int i = 0; i < 8; i++) a[i]  = As[k][ty * 8 + i];
            #pragma unroll
            for (int j = 0; j < 8; j++) bb[j] = Bs[k][tx * 8 + j];
            #pragma unroll
            for (int i = 0; i < 8; i++)
                #pragma unroll
                for (int j = 0; j < 8; j++)
                    acc[i][j] += a[i] * bb[j];
        }
        __syncthreads();
    }

    // ---- epilogue ----
    #pragma unroll
    for (int i = 0; i < 8; i++) {
        const int m = m0 + ty * 8 + i;
        float bm = 0.f;
        if (bias && !bias_on_n) bm = bias[m];
        #pragma unroll
        for (int j = 0; j < 8; j += 4) {
            const int n = n0 + tx * 8 + j;
            float4 v;
            v.x = acc[i][j + 0];
            v.y = acc[i][j + 1];
            v.z = acc[i][j + 2];
            v.w = acc[i][j + 3];
            if (bias) {
                if (bias_on_n) {
                    v.x += bias[n + 0]; v.y += bias[n + 1];
                    v.z += bias[n + 2]; v.w += bias[n + 3];
                } else {
                    v.x += bm; v.y += bm; v.z += bm; v.w += bm;
                }
            }
            v.x *= alpha; v.y *= alpha; v.z *= alpha; v.w *= alpha;
            if (resid) {
                const float4 r = *(const float4*)&resid[(size_t)m * N + n];
                v.x += r.x; v.y += r.y; v.z += r.z; v.w += r.w;
            }
            *(float4*)&Cp[(size_t)m * N + n] = v;
        }
    }
}

// ---------------------------------------------------------------------------
// Softmax over last dim (T=1024). One block per row; 256 threads, one
// float4 per thread — single global read + write.
// ---------------------------------------------------------------------------
__global__ __launch_bounds__(256) void softmax_kernel(float* __restrict__ wbuf)
{
    float4* p = (float4*)(wbuf + (size_t)blockIdx.x * T_);
    const int tid = threadIdx.x;
    float4 v = p[tid];

    float mx = fmaxf(fmaxf(v.x, v.y), fmaxf(v.z, v.w));
    #pragma unroll
    for (int o = 16; o > 0; o >>= 1)
        mx = fmaxf(mx, __shfl_xor_sync(0xffffffffu, mx, o));
    __shared__ float sh[8];
    const int wid = tid >> 5, lane = tid & 31;
    if (lane == 0) sh[wid] = mx;
    __syncthreads();
    if (tid == 0) {
        float m = sh[0];
        #pragma unroll
        for (int i = 1; i < 8; i++) m = fmaxf(m, sh[i]);
        sh[0] = m;
    }
    __syncthreads();
    mx = sh[0];
    __syncthreads();

    v.x = __expf(v.x - mx);
    v.y = __expf(v.y - mx);
    v.z = __expf(v.z - mx);
    v.w = __expf(v.w - mx);
    float s = v.x + v.y + v.z + v.w;
    #pragma unroll
    for (int o = 16; o > 0; o >>= 1)
        s += __shfl_xor_sync(0xffffffffu, s, o);
    if (lane == 0) sh[wid] = s;
    __syncthreads();
    if (tid == 0) {
        float a = 0.f;
        #pragma unroll
        for (int i = 0; i < 8; i++) a += sh[i];
        sh[0] = a;
    }
    __syncthreads();
    const float inv = 1.0f / sh[0];

    v.x *= inv; v.y *= inv; v.z *= inv; v.w *= inv;
    p[tid] = v;
}

// ---------------------------------------------------------------------------
// Launch
// ---------------------------------------------------------------------------
extern "C" void kernel_launch(void* const* d_in, const int* in_sizes, int n_in,
                              void* d_out, int out_size)
{
    const float* x     = (const float*)d_in[0];
    const float* gamma = (const float*)d_in[1];
    const float* beta  = (const float*)d_in[2];
    const float* Wq    = (const float*)d_in[3];
    const float* bq    = (const float*)d_in[4];
    const float* Wk    = (const float*)d_in[5];
    const float* bk    = (const float*)d_in[6];
    const float* Wv    = (const float*)d_in[7];
    const float* bv    = (const float*)d_in[8];
    const float* Wp    = (const float*)d_in[9];
    const float* bp    = (const float*)d_in[10];
    float* out = (float*)d_out;

    static float *p_h = nullptr, *p_q, *p_k, *p_v, *p_w, *p_a;
    if (!p_h) {
        cudaGetSymbolAddress((void**)&p_h, g_h);
        cudaGetSymbolAddress((void**)&p_q, g_q);
        cudaGetSymbolAddress((void**)&p_k, g_k);
        cudaGetSymbolAddress((void**)&p_v, g_v);
        cudaGetSymbolAddress((void**)&p_w, g_w);
        cudaGetSymbolAddress((void**)&p_a, g_a);
    }

    const size_t sBCT = (size_t)C_ * T_;   // per-batch stride of [C,T] / [T,C]
    const size_t sBTT = (size_t)T_ * T_;
    const float qscale = 0.04419417382415922f;  // 1/sqrt(512) = C^-1/2

    // 1) GroupNorm -> g_h [B, C, T]
    groupnorm_kernel<<<B_ * G_, 256>>>(x, gamma, beta, p_h);

    // 2) Q/K/V projections: out[b,t,o] = (sum_c h[b,c,t] * W[o,c] + b[o]) (*scale for q)
    //    A[m=t,k=c] = h: sam=1, sak=T.  B[k=c,n=o] = W: sbk=1, sbn=C.
    {
        dim3 grid(C_ / 128, T_ / 128, B_);
        gemm128<<<grid, 256>>>(T_, C_, C_,
                               p_h, sBCT, 1, T_,
                               Wq, 0, 1, C_,
                               p_q, sBCT,
                               bq, 1, qscale, nullptr, 0);
        gemm128<<<grid, 256>>>(T_, C_, C_,
                               p_h, sBCT, 1, T_,
                               Wk, 0, 1, C_,
                               p_k, sBCT,
                               bk, 1, 1.0f, nullptr, 0);
        gemm128<<<grid, 256>>>(T_, C_, C_,
                               p_h, sBCT, 1, T_,
                               Wv, 0, 1, C_,
                               p_v, sBCT,
                               bv, 1, 1.0f, nullptr, 0);
    }

    // 3) Scores: w[b,t,s] = sum_c q[b,t,c] * k[b,s,c]
    //    A[m=t,k=c]=q: sam=C, sak=1.  B[k=c,n=s]=k: sbk=1, sbn=C.
    {
        dim3 grid(T_ / 128, T_ / 128, B_);
        gemm128<<<grid, 256>>>(T_, T_, C_,
                               p_q, sBCT, C_, 1,
                               p_k, sBCT, 1, C_,
                               p_w, sBTT,
                               nullptr, 0, 1.0f, nullptr, 0);
    }

    // 4) Softmax over s
    softmax_kernel<<<B_ * T_, 256>>>(p_w);

    // 5) Attention apply: a[b,t,c] = sum_s w[b,t,s] * v[b,s,c]
    //    A[m=t,k=s]=w: sam=T, sak=1.  B[k=s,n=c]=v: sbk=C, sbn=1.
    {
        dim3 grid(C_ / 128, T_ / 128, B_);
        gemm128<<<grid, 256>>>(T_, C_, T_,
                               p_w, sBTT, T_, 1,
                               p_v, sBCT, C_, 1,
                               p_a, sBCT,
                               nullptr, 0, 1.0f, nullptr, 0);
    }

    // 6) Projection + residual: out[b,o,t] = x[b,o,t] + bp[o] + sum_c Wp[o,c]*a[b,t,c]
    //    A[m=o,k=c]=Wp: sam=C, sak=1 (batch stride 0).  B[k=c,n=t]=a: sbk=1, sbn=C.
    {
        dim3 grid(T_ / 128, C_ / 128, B_);
        gemm128<<<grid, 256>>>(C_, T_, C_,
                               Wp, 0, C_, 1,
                               p_a, sBCT, 1, C_,
                               out, sBCT,
                               bp, 0, 1.0f, x, sBCT);
    }
}

// round 2
// speedup vs baseline: 2.5483x; 2.5483x over previous
#include <cuda_runtime.h>
#include <cstdint>

// Problem constants
#define B_   16
#define C_   512
#define T_   1024            // H*W = 32*32
#define G_   32
#define CPG  (C_ / G_)       // 16 channels per group
#define EPS  1e-5f
#define QSCALE 0.04419417382415922f   // C^-1/2 = 1/sqrt(512)

// ---------------------------------------------------------------------------
// Scratch (static __device__ — no allocation allowed)
// ---------------------------------------------------------------------------
__device__ float g_h  [(size_t)B_ * C_ * T_];        // groupnorm out, [B, C, T]
__device__ float g_qkv[(size_t)B_ * T_ * 3 * C_];    // [B, T, 1536]: q|k|v
__device__ float g_w  [(size_t)B_ * T_ * T_];        // scores, [B, T, T]
__device__ float g_a  [(size_t)B_ * T_ * C_];        // attn out, [B, T, C]
__device__ float g_wt [(size_t)C_ * 3 * C_];         // packed W^T, [Cin, 3*Cout]
__device__ float g_bt [3 * C_];                      // packed bias

// ---------------------------------------------------------------------------
// GroupNorm: one block per (b, g). Reduce 16*1024 = 16384 elements.
// ---------------------------------------------------------------------------
__global__ __launch_bounds__(256) void groupnorm_kernel(
    const float* __restrict__ x,
    const float* __restrict__ gamma,
    const float* __restrict__ beta,
    float* __restrict__ h)
{
    const int b = blockIdx.x >> 5;
    const int g = blockIdx.x & 31;
    const size_t base = ((size_t)b * C_ + (size_t)g * CPG) * T_;
    const float4* xp = (const float4*)(x + base);
    float4* hp = (float4*)(h + base);
    const int N4 = CPG * T_ / 4;        // 4096
    const int tid = threadIdx.x;

    float s = 0.f, s2 = 0.f;
    for (int i = tid; i < N4; i += 256) {
        float4 v = xp[i];
        s  += v.x + v.y + v.z + v.w;
        s2 += v.x * v.x + v.y * v.y + v.z * v.z + v.w * v.w;
    }
    #pragma unroll
    for (int o = 16; o > 0; o >>= 1) {
        s  += __shfl_xor_sync(0xffffffffu, s, o);
        s2 += __shfl_xor_sync(0xffffffffu, s2, o);
    }
    __shared__ float sh1[8], sh2[8];
    const int wid = tid >> 5, lane = tid & 31;
    if (lane == 0) { sh1[wid] = s; sh2[wid] = s2; }
    __syncthreads();
    if (tid == 0) {
        float a = 0.f, bb = 0.f;
        #pragma unroll
        for (int i = 0; i < 8; i++) { a += sh1[i]; bb += sh2[i]; }
        sh1[0] = a; sh2[0] = bb;
    }
    __syncthreads();
    const float inv_n = 1.0f / (float)(CPG * T_);
    const float mean = sh1[0] * inv_n;
    const float var  = sh2[0] * inv_n - mean * mean;
    const float inv  = rsqrtf(var + EPS);

    for (int i = tid; i < N4; i += 256) {
        const int c = g * CPG + (i >> 8);
        const float ga = gamma[c] * inv;
        const float be = beta[c];
        float4 v = xp[i];
        v.x = (v.x - mean) * ga + be;
        v.y = (v.y - mean) * ga + be;
        v.z = (v.z - mean) * ga + be;
        v.w = (v.w - mean) * ga + be;
        hp[i] = v;
    }
}

// ---------------------------------------------------------------------------
// Pack Wq|Wk|Wv (transposed, q-scale folded) into Wt[Cin][3*Cout], bias too.
// ---------------------------------------------------------------------------
__global__ __launch_bounds__(256) void pack_qkv_kernel(
    const float* __restrict__ Wq, const float* __restrict__ bq,
    const float* __restrict__ Wk, const float* __restrict__ bk,
    const float* __restrict__ Wv, const float* __restrict__ bv,
    float* __restrict__ Wt, float* __restrict__ bt)
{
    const int idx = blockIdx.x * 256 + threadIdx.x;   // 512*1536 total
    const int c = idx & (C_ - 1);
    const int o = idx >> 9;                            // 0..1535
    float w;
    if (o < C_)          w = Wq[o * C_ + c] * QSCALE;
    else if (o < 2 * C_) w = Wk[(o - C_) * C_ + c];
    else                 w = Wv[(o - 2 * C_) * C_ + c];
    Wt[(size_t)c * (3 * C_) + o] = w;
    if (idx < 3 * C_) {
        bt[idx] = (idx < C_) ? bq[idx] * QSCALE
                : (idx < 2 * C_) ? bk[idx - C_] : bv[idx - 2 * C_];
    }
}

// ---------------------------------------------------------------------------
// tf32 tensor-core GEMM: C[m,n] = epi( sum_k A[m,k]*B[k,n] )
// 128x128 tile, BK=16, 256 threads (8 warps, each 64m x 32n of m16n8k8).
// Double-buffered smem, cvt.rna.tf32 on the smem-store path (unbiased).
// ---------------------------------------------------------------------------
__device__ __forceinline__ uint32_t f2tf(float f) {
    uint32_t u; asm("cvt.rna.tf32.f32 %0, %1;" : "=r"(u) : "f"(f)); return u;
}

__device__ __forceinline__ void mma8(float* c, const uint32_t* a, const uint32_t* b) {
    asm("mma.sync.aligned.m16n8k8.row.col.f32.tf32.tf32.f32 "
        "{%0,%1,%2,%3}, {%4,%5,%6,%7}, {%8,%9}, {%0,%1,%2,%3};"
        : "+f"(c[0]), "+f"(c[1]), "+f"(c[2]), "+f"(c[3])
        : "r"(a[0]), "r"(a[1]), "r"(a[2]), "r"(a[3]), "r"(b[0]), "r"(b[1]));
}

__global__ __launch_bounds__(256) void gemm_tc(
    int N, int K,
    const float* __restrict__ A, size_t Abs, int sam, int sak,
    const float* __restrict__ Bp, size_t Bbs, int sbk, int sbn,
    float* __restrict__ Cp, size_t Cbs,
    const float* __restrict__ bias, int bias_on_n,
    const float* __restrict__ resid, size_t Rbs)
{
    const int bz = blockIdx.z;
    A  += (size_t)bz * Abs;
    Bp += (size_t)bz * Bbs;
    Cp += (size_t)bz * Cbs;
    if (resid) resid += (size_t)bz * Rbs;

    __shared__ uint32_t As[2][16][132];
    __shared__ uint32_t Bs[2][16][132];

    const int tid = threadIdx.x;
    const int m0 = blockIdx.y * 128;
    const int n0 = blockIdx.x * 128;
    const int warp = tid >> 5, lane = tid & 31;
    const int wm = warp >> 2, wn = warp & 3;       // 2 x 4 warp grid
    const int gid = lane >> 2, tig = lane & 3;

    float acc[4][4][4];
    #pragma unroll
    for (int i = 0; i < 4; i++)
        #pragma unroll
        for (int j = 0; j < 4; j++)
            #pragma unroll
            for (int r = 0; r < 4; r++) acc[i][j][r] = 0.f;

    float ra[8], rb[8];

    auto ldA = [&](float* r, int k0) {
        if (sak == 1) {
            #pragma unroll
            for (int i = 0; i < 8; i++) {
                int idx = tid + (i << 8); int m = idx >> 4, k = idx & 15;
                r[i] = A[(size_t)(m0 + m) * sam + (size_t)(k0 + k)];
            }
        } else {  // sam == 1
            #pragma unroll
            for (int i = 0; i < 8; i++) {
                int idx = tid + (i << 8); int k = idx >> 7, m = idx & 127;
                r[i] = A[(size_t)(m0 + m) + (size_t)(k0 + k) * sak];
            }
        }
    };
    auto stA = [&](int buf, const float* r) {
        if (sak == 1) {
            #pragma unroll
            for (int i = 0; i < 8; i++) {
                int idx = tid + (i << 8);
                As[buf][idx & 15][idx >> 4] = f2tf(r[i]);
            }
        } else {
            #pragma unroll
            for (int i = 0; i < 8; i++) {
                int idx = tid + (i << 8);
                As[buf][idx >> 7][idx & 127] = f2tf(r[i]);
            }
        }
    };
    auto ldB = [&](float* r, int k0) {
        if (sbn == 1) {
            #pragma unroll
            for (int i = 0; i < 8; i++) {
                int idx = tid + (i << 8); int k = idx >> 7, n = idx & 127;
                r[i] = Bp[(size_t)(k0 + k) * sbk + (size_t)(n0 + n)];
            }
        } else {  // sbk == 1
            #pragma unroll
            for (int i = 0; i < 8; i++) {
                int idx = tid + (i << 8); int n = idx >> 4, k = idx & 15;
                r[i] = Bp[(size_t)(k0 + k) + (size_t)(n0 + n) * sbn];
            }
        }
    };
    auto stB = [&](int buf, const float* r) {
        if (sbn == 1) {
            #pragma unroll
            for (int i = 0; i < 8; i++) {
                int idx = tid + (i << 8);
                Bs[buf][idx >> 7][idx & 127] = f2tf(r[i]);
            }
        } else {
            #pragma unroll
            for (int i = 0; i < 8; i++) {
                int idx = tid + (i << 8);
                Bs[buf][idx & 15][idx >> 4] = f2tf(r[i]);
            }
        }
    };

    // prologue
    ldA(ra, 0); ldB(rb, 0);
    stA(0, ra); stB(0, rb);
    __syncthreads();

    const int nIter = K >> 4;
    for (int it = 0; it < nIter; ++it) {
        const int buf = it & 1;
        if (it + 1 < nIter) { ldA(ra, (it + 1) << 4); ldB(rb, (it + 1) << 4); }

        #pragma unroll
        for (int kk = 0; kk < 2; kk++) {
            uint32_t af[4][4], bf[4][2];
            #pragma unroll
            for (int mi = 0; mi < 4; mi++) {
                const int mr = wm * 64 + mi * 16 + gid;
                af[mi][0] = As[buf][kk * 8 + tig][mr];
                af[mi][1] = As[buf][kk * 8 + tig][mr + 8];
                af[mi][2] = As[buf][kk * 8 + tig + 4][mr];
                af[mi][3] = As[buf][kk * 8 + tig + 4][mr + 8];
            }
            #pragma unroll
            for (int nj = 0; nj < 4; nj++) {
                const int nc = wn * 32 + nj * 8 + gid;
                bf[nj][0] = Bs[buf][kk * 8 + tig][nc];
                bf[nj][1] = Bs[buf][kk * 8 + tig + 4][nc];
            }
            #pragma unroll
            for (int mi = 0; mi < 4; mi++)
                #pragma unroll
                for (int nj = 0; nj < 4; nj++)
                    mma8(acc[mi][nj], af[mi], bf[nj]);
        }

        if (it + 1 < nIter) { stA(buf ^ 1, ra); stB(buf ^ 1, rb); }
        __syncthreads();
    }

    // epilogue
    #pragma unroll
    for (int mi = 0; mi < 4; mi++) {
        #pragma unroll
        for (int nj = 0; nj < 4; nj++) {
            const int cc = n0 + wn * 32 + nj * 8 + tig * 2;
            float bn0 = 0.f, bn1 = 0.f;
            if (bias && bias_on_n) { bn0 = bias[cc]; bn1 = bias[cc + 1]; }
            #pragma unroll
            for (int hh = 0; hh < 2; hh++) {
                const int row = m0 + wm * 64 + mi * 16 + gid + hh * 8;
                float v0 = acc[mi][nj][hh * 2 + 0];
                float v1 = acc[mi][nj][hh * 2 + 1];
                if (bias) {
                    if (bias_on_n) { v0 += bn0; v1 += bn1; }
                    else { const float bm = bias[row]; v0 += bm; v1 += bm; }
                }
                if (resid) {
                    const float2 rr = *(const float2*)&resid[(size_t)row * N + cc];
                    v0 += rr.x; v1 += rr.y;
                }
                float2 o; o.x = v0; o.y = v1;
                *(float2*)&Cp[(size_t)row * N + cc] = o;
            }
        }
    }
}

// ---------------------------------------------------------------------------
// Softmax over last dim (T=1024). One block per row; one float4/thread.
// ---------------------------------------------------------------------------
__global__ __launch_bounds__(256) void softmax_kernel(float* __restrict__ wbuf)
{
    float4* p = (float4*)(wbuf + (size_t)blockIdx.x * T_);
    const int tid = threadIdx.x;
    float4 v = p[tid];

    float mx = fmaxf(fmaxf(v.x, v.y), fmaxf(v.z, v.w));
    #pragma unroll
    for (int o = 16; o > 0; o >>= 1)
        mx = fmaxf(mx, __shfl_xor_sync(0xffffffffu, mx, o));
    __shared__ float sh[8];
    const int wid = tid >> 5, lane = tid & 31;
    if (lane == 0) sh[wid] = mx;
    __syncthreads();
    if (tid == 0) {
        float m = sh[0];
        #pragma unroll
        for (int i = 1; i < 8; i++) m = fmaxf(m, sh[i]);
        sh[0] = m;
    }
    __syncthreads();
    mx = sh[0];
    __syncthreads();

    v.x = __expf(v.x - mx);
    v.y = __expf(v.y - mx);
    v.z = __expf(v.z - mx);
    v.w = __expf(v.w - mx);
    float s = v.x + v.y + v.z + v.w;
    #pragma unroll
    for (int o = 16; o > 0; o >>= 1)
        s += __shfl_xor_sync(0xffffffffu, s, o);
    if (lane == 0) sh[wid] = s;
    __syncthreads();
    if (tid == 0) {
        float a = 0.f;
        #pragma unroll
        for (int i = 0; i < 8; i++) a += sh[i];
        sh[0] = a;
    }
    __syncthreads();
    const float inv = 1.0f / sh[0];

    v.x *= inv; v.y *= inv; v.z *= inv; v.w *= inv;
    p[tid] = v;
}

// ---------------------------------------------------------------------------
// Launch
// ---------------------------------------------------------------------------
extern "C" void kernel_launch(void* const* d_in, const int* in_sizes, int n_in,
                              void* d_out, int out_size)
{
    const float* x     = (const float*)d_in[0];
    const float* gamma = (const float*)d_in[1];
    const float* beta  = (const float*)d_in[2];
    const float* Wq    = (const float*)d_in[3];
    const float* bq    = (const float*)d_in[4];
    const float* Wk    = (const float*)d_in[5];
    const float* bk    = (const float*)d_in[6];
    const float* Wv    = (const float*)d_in[7];
    const float* bv    = (const float*)d_in[8];
    const float* Wp    = (const float*)d_in[9];
    const float* bp    = (const float*)d_in[10];
    float* out = (float*)d_out;

    static float *p_h = nullptr, *p_qkv, *p_w, *p_a, *p_wt, *p_bt;
    if (!p_h) {
        cudaGetSymbolAddress((void**)&p_h,   g_h);
        cudaGetSymbolAddress((void**)&p_qkv, g_qkv);
        cudaGetSymbolAddress((void**)&p_w,   g_w);
        cudaGetSymbolAddress((void**)&p_a,   g_a);
        cudaGetSymbolAddress((void**)&p_wt,  g_wt);
        cudaGetSymbolAddress((void**)&p_bt,  g_bt);
    }

    const size_t sBCT = (size_t)C_ * T_;        // [C,T] batch stride
    const size_t sQKV = (size_t)T_ * 3 * C_;    // [T,1536] batch stride
    const size_t sBTT = (size_t)T_ * T_;

    // 1) GroupNorm -> g_h [B, C, T]
    groupnorm_kernel<<<B_ * G_, 256>>>(x, gamma, beta, p_h);

    // 2) Pack QKV weights (q-scale folded)
    pack_qkv_kernel<<<(C_ * 3 * C_) / 256, 256>>>(Wq, bq, Wk, bk, Wv, bv, p_wt, p_bt);

    // 3) Fused QKV: qkv[b,t,o'] = h[b,:,t] . Wt[:,o'] + bt[o']
    //    A = h [c][t]: sam=1, sak=T.   B = Wt [c][o']: sbk=1536, sbn=1.
    {
        dim3 grid((3 * C_) / 128, T_ / 128, B_);
        gemm_tc<<<grid, 256>>>(3 * C_, C_,
                               p_h, sBCT, 1, T_,
                               p_wt, 0, 3 * C_, 1,
                               p_qkv, sQKV,
                               p_bt, 1, nullptr, 0);
    }

    // 4) Scores: w[b,t,s] = q[b,t,:] . k[b,s,:]  (scale pre-folded into q)
    //    A = q: sam=1536, sak=1.   B = k: sbk=1, sbn=1536.
    {
        dim3 grid(T_ / 128, T_ / 128, B_);
        gemm_tc<<<grid, 256>>>(T_, C_,
                               p_qkv, sQKV, 3 * C_, 1,
                               p_qkv + C_, sQKV, 1, 3 * C_,
                               p_w, sBTT,
                               nullptr, 0, nullptr, 0);
    }

    // 5) Softmax over s
    softmax_kernel<<<B_ * T_, 256>>>(p_w);

    // 6) Apply: a[b,t,c] = sum_s w[b,t,s] * v[b,s,c]
    //    A = w: sam=T, sak=1.   B = v: sbk=1536, sbn=1.
    {
        dim3 grid(C_ / 128, T_ / 128, B_);
        gemm_tc<<<grid, 256>>>(C_, T_,
                               p_w, sBTT, T_, 1,
                               p_qkv + 2 * C_, sQKV, 3 * C_, 1,
                               p_a, (size_t)T_ * C_,
                               nullptr, 0, nullptr, 0);
    }

    // 7) Projection + residual: out[b,o,t] = x[b,o,t] + bp[o] + Wp[o,:] . a[b,t,:]
    //    A = Wp [o][c]: sam=C, sak=1 (Abs=0).  B = a [t][c]: sbk=1, sbn=C.
    {
        dim3 grid(T_ / 128, C_ / 128, B_);
        gemm_tc<<<grid, 256>>>(T_, C_,
                               Wp, 0, C_, 1,
                               p_a, (size_t)T_ * C_, 1, C_,
                               out, sBCT,
                               bp, 0, x, sBCT);
    }
}

// round 3
// speedup vs baseline: 4.4832x; 1.7593x over previous
#include <cuda_runtime.h>
#include <cuda_bf16.h>
#include <cstdint>

// Problem constants
#define B_   16
#define C_   512
#define T_   1024            // H*W = 32*32
#define G_   32
#define CPG  (C_ / G_)       // 16 channels per group
#define EPS  1e-5f
#define QSCALE 0.04419417382415922f   // C^-1/2 = 1/sqrt(512)

// ---------------------------------------------------------------------------
// Scratch (static __device__ — no allocation allowed)
// ---------------------------------------------------------------------------
__device__ float g_h  [(size_t)B_ * C_ * T_];        // groupnorm out, [B, C, T]
__device__ float g_qkv[(size_t)B_ * T_ * 3 * C_];    // [B, T, 1536]: q|k|v
__device__ float g_w  [(size_t)B_ * T_ * T_];        // scores, [B, T, T]
__device__ float g_a  [(size_t)B_ * T_ * C_];        // attn out, [B, T, C]
__device__ float g_wt [(size_t)3 * C_ * C_];         // packed W, [3*Cout][Cin]
__device__ float g_bt [3 * C_];                      // packed bias

// ---------------------------------------------------------------------------
// GroupNorm: one block per (b, g).
// ---------------------------------------------------------------------------
__global__ __launch_bounds__(256) void groupnorm_kernel(
    const float* __restrict__ x,
    const float* __restrict__ gamma,
    const float* __restrict__ beta,
    float* __restrict__ h)
{
    const int b = blockIdx.x >> 5;
    const int g = blockIdx.x & 31;
    const size_t base = ((size_t)b * C_ + (size_t)g * CPG) * T_;
    const float4* xp = (const float4*)(x + base);
    float4* hp = (float4*)(h + base);
    const int N4 = CPG * T_ / 4;        // 4096
    const int tid = threadIdx.x;

    float s = 0.f, s2 = 0.f;
    for (int i = tid; i < N4; i += 256) {
        float4 v = xp[i];
        s  += v.x + v.y + v.z + v.w;
        s2 += v.x * v.x + v.y * v.y + v.z * v.z + v.w * v.w;
    }
    #pragma unroll
    for (int o = 16; o > 0; o >>= 1) {
        s  += __shfl_xor_sync(0xffffffffu, s, o);
        s2 += __shfl_xor_sync(0xffffffffu, s2, o);
    }
    __shared__ float sh1[8], sh2[8];
    const int wid = tid >> 5, lane = tid & 31;
    if (lane == 0) { sh1[wid] = s; sh2[wid] = s2; }
    __syncthreads();
    if (tid == 0) {
        float a = 0.f, bb = 0.f;
        #pragma unroll
        for (int i = 0; i < 8; i++) { a += sh1[i]; bb += sh2[i]; }
        sh1[0] = a; sh2[0] = bb;
    }
    __syncthreads();
    const float inv_n = 1.0f / (float)(CPG * T_);
    const float mean = sh1[0] * inv_n;
    const float var  = sh2[0] * inv_n - mean * mean;
    const float inv  = rsqrtf(var + EPS);

    for (int i = tid; i < N4; i += 256) {
        const int c = g * CPG + (i >> 8);
        const float ga = gamma[c] * inv;
        const float be = beta[c];
        float4 v = xp[i];
        v.x = (v.x - mean) * ga + be;
        v.y = (v.y - mean) * ga + be;
        v.z = (v.z - mean) * ga + be;
        v.w = (v.w - mean) * ga + be;
        hp[i] = v;
    }
}

// ---------------------------------------------------------------------------
// Pack Wq|Wk|Wv rows (no transpose; q scaled) into Wt[3*Cout][Cin].
// ---------------------------------------------------------------------------
__global__ __launch_bounds__(256) void pack_qkv_kernel(
    const float* __restrict__ Wq, const float* __restrict__ bq,
    const float* __restrict__ Wk, const float* __restrict__ bk,
    const float* __restrict__ Wv, const float* __restrict__ bv,
    float* __restrict__ Wt, float* __restrict__ bt)
{
    const int idx = blockIdx.x * 256 + threadIdx.x;   // float4 index, 1536*128
    const int o  = idx >> 7;
    const int c4 = idx & 127;
    const float* src; float s = 1.f;
    if (o < C_)          { src = Wq + (size_t)o * C_;            s = QSCALE; }
    else if (o < 2 * C_) { src = Wk + (size_t)(o - C_) * C_; }
    else                 { src = Wv + (size_t)(o - 2 * C_) * C_; }
    float4 v = *(const float4*)(src + c4 * 4);
    v.x *= s; v.y *= s; v.z *= s; v.w *= s;
    *(float4*)(Wt + (size_t)o * C_ + c4 * 4) = v;
    if (idx < 3 * C_) {
        bt[idx] = (idx < C_) ? bq[idx] * QSCALE
                : (idx < 2 * C_) ? bk[idx - C_] : bv[idx - 2 * C_];
    }
}

// ---------------------------------------------------------------------------
// bf16 tensor-core GEMM with ldmatrix. Block 128x128, BK=32, 256 threads.
// 8 warps (2x4), warp tile 64x32, mma.m16n8k16.
// AT: 0 = A global [m][k] (k contig), 1 = A global [k][m] (m contig, trans)
// BT: 0 = B global [n][k] (k contig), 1 = B global [k][n] (n contig, trans)
// ---------------------------------------------------------------------------
__device__ __forceinline__ uint32_t pk2(float a, float b) {
    __nv_bfloat162 t = __floats2bfloat162_rn(a, b);
    return *reinterpret_cast<uint32_t*>(&t);
}
__device__ __forceinline__ void ldsm4(uint32_t* r, uint32_t a) {
    asm volatile("ldmatrix.sync.aligned.m8n8.x4.shared.b16 {%0,%1,%2,%3}, [%4];"
                 : "=r"(r[0]), "=r"(r[1]), "=r"(r[2]), "=r"(r[3]) : "r"(a));
}
__device__ __forceinline__ void ldsm4t(uint32_t* r, uint32_t a) {
    asm volatile("ldmatrix.sync.aligned.m8n8.x4.trans.shared.b16 {%0,%1,%2,%3}, [%4];"
                 : "=r"(r[0]), "=r"(r[1]), "=r"(r[2]), "=r"(r[3]) : "r"(a));
}
__device__ __forceinline__ void mma16(float* c, const uint32_t* a, const uint32_t* b) {
    asm volatile("mma.sync.aligned.m16n8k16.row.col.f32.bf16.bf16.f32 "
                 "{%0,%1,%2,%3},{%4,%5,%6,%7},{%8,%9},{%0,%1,%2,%3};"
                 : "+f"(c[0]), "+f"(c[1]), "+f"(c[2]), "+f"(c[3])
                 : "r"(a[0]), "r"(a[1]), "r"(a[2]), "r"(a[3]), "r"(b[0]), "r"(b[1]));
}

// smem layout per buffer: A region 10240 B, B region 10240 B.
//   NT tiles: 128 rows x 80 B pitch (32 bf16 + 8 pad)
//   NN tiles:  32 rows x 272 B pitch (128 bf16 + 8 pad)
#define ABUF_OFF 0
#define BBUF_OFF 10240
#define BUFSTEP  20480

template<int AT, int BT>
__global__ __launch_bounds__(256) void gemm_bf16(
    int N, int K,
    const float* __restrict__ A, size_t Abs, int lda,
    const float* __restrict__ Bp, size_t Bbs, int ldb,
    float* __restrict__ Cp, size_t Cbs,
    const float* __restrict__ bias, int bias_on_n,
    const float* __restrict__ resid, size_t Rbs)
{
    const int bz = blockIdx.z;
    A  += (size_t)bz * Abs;
    Bp += (size_t)bz * Bbs;
    Cp += (size_t)bz * Cbs;
    if (resid) resid += (size_t)bz * Rbs;

    __shared__ __align__(16) unsigned char sm[2 * BUFSTEP];
    const uint32_t sb = (uint32_t)__cvta_generic_to_shared(sm);

    const int tid = threadIdx.x;
    const int m0 = blockIdx.y * 128;
    const int n0 = blockIdx.x * 128;
    const int warp = tid >> 5, lane = tid & 31;
    const int wm = warp >> 2, wn = warp & 3;
    const int gid = lane >> 2, tig = lane & 3;

    float acc[4][4][4];
    #pragma unroll
    for (int i = 0; i < 4; i++)
        #pragma unroll
        for (int j = 0; j < 4; j++)
            #pragma unroll
            for (int r = 0; r < 4; r++) acc[i][j][r] = 0.f;

    // precomputed ldmatrix base addresses (buffer 0)
    const uint32_t aBase = (AT == 0)
        ? sb + ABUF_OFF + (uint32_t)(wm * 64 + (lane & 15)) * 80 + ((lane >> 4) & 1) * 16
        : sb + ABUF_OFF + (uint32_t)(((lane >> 4) & 1) * 8 + (lane & 7)) * 272
                        + (uint32_t)(wm * 64 + ((lane >> 3) & 1) * 8) * 2;
    const uint32_t bBase = (BT == 0)
        ? sb + BBUF_OFF + (uint32_t)(wn * 32 + ((lane >> 4) & 1) * 8 + (lane & 7)) * 80
                        + ((lane >> 3) & 1) * 16
        : sb + BBUF_OFF + (uint32_t)(((lane >> 3) & 1) * 8 + (lane & 7)) * 272
                        + (uint32_t)(wn * 32 + ((lane >> 4) & 1) * 8) * 2;

    float4 ra[4], rb[4];

    auto ldGA = [&](int k0) {
        if (AT == 0) {
            #pragma unroll
            for (int i = 0; i < 4; i++) {
                int idx = tid + (i << 8); int m = idx >> 3, kq = idx & 7;
                ra[i] = *(const float4*)(A + (size_t)(m0 + m) * lda + k0 + kq * 4);
            }
        } else {
            #pragma unroll
            for (int i = 0; i < 4; i++) {
                int idx = tid + (i << 8); int k = idx >> 5, mq = idx & 31;
                ra[i] = *(const float4*)(A + (size_t)(k0 + k) * lda + m0 + mq * 4);
            }
        }
    };
    auto stSA = [&](int buf) {
        unsigned char* base = sm + buf * BUFSTEP + ABUF_OFF;
        #pragma unroll
        for (int i = 0; i < 4; i++) {
            int idx = tid + (i << 8);
            uint2 p; p.x = pk2(ra[i].x, ra[i].y); p.y = pk2(ra[i].z, ra[i].w);
            if (AT == 0) { int m = idx >> 3, kq = idx & 7;  *(uint2*)(base + m * 80 + kq * 8) = p; }
            else         { int k = idx >> 5, mq = idx & 31; *(uint2*)(base + k * 272 + mq * 8) = p; }
        }
    };
    auto ldGB = [&](int k0) {
        if (BT == 0) {
            #pragma unroll
            for (int i = 0; i < 4; i++) {
                int idx = tid + (i << 8); int n = idx >> 3, kq = idx & 7;
                rb[i] = *(const float4*)(Bp + (size_t)(n0 + n) * ldb + k0 + kq * 4);
            }
        } else {
            #pragma unroll
            for (int i = 0; i < 4; i++) {
                int idx = tid + (i << 8); int k = idx >> 5, nq = idx & 31;
                rb[i] = *(const float4*)(Bp + (size_t)(k0 + k) * ldb + n0 + nq * 4);
            }
        }
    };
    auto stSB = [&](int buf) {
        unsigned char* base = sm + buf * BUFSTEP + BBUF_OFF;
        #pragma unroll
        for (int i = 0; i < 4; i++) {
            int idx = tid + (i << 8);
            uint2 p; p.x = pk2(rb[i].x, rb[i].y); p.y = pk2(rb[i].z, rb[i].w);
            if (BT == 0) { int n = idx >> 3, kq = idx & 7;  *(uint2*)(base + n * 80 + kq * 8) = p; }
            else         { int k = idx >> 5, nq = idx & 31; *(uint2*)(base + k * 272 + nq * 8) = p; }
        }
    };

    // prologue
    ldGA(0); ldGB(0);
    stSA(0); stSB(0);
    __syncthreads();

    const int nIter = K >> 5;
    for (int it = 0; it < nIter; ++it) {
        const int buf = it & 1;
        if (it + 1 < nIter) { ldGA((it + 1) << 5); ldGB((it + 1) << 5); }

        const uint32_t aB = aBase + buf * BUFSTEP;
        const uint32_t bB = bBase + buf * BUFSTEP;
        #pragma unroll
        for (int kk = 0; kk < 2; kk++) {
            uint32_t af[4][4], bfr[2][4];
            #pragma unroll
            for (int mi = 0; mi < 4; mi++) {
                const uint32_t ad = (AT == 0) ? aB + mi * 1280 + kk * 32
                                              : aB + kk * 4352 + mi * 32;
                if (AT == 0) ldsm4(af[mi], ad); else ldsm4t(af[mi], ad);
            }
            #pragma unroll
            for (int np = 0; np < 2; np++) {
                const uint32_t bd = (BT == 0) ? bB + np * 1280 + kk * 32
                                              : bB + kk * 4352 + np * 32;
                if (BT == 0) ldsm4(bfr[np], bd); else ldsm4t(bfr[np], bd);
            }
            #pragma unroll
            for (int mi = 0; mi < 4; mi++)
                #pragma unroll
                for (int nj = 0; nj < 4; nj++)
                    mma16(acc[mi][nj], af[mi], &bfr[nj >> 1][(nj & 1) * 2]);
        }

        if (it + 1 < nIter) { stSA(buf ^ 1); stSB(buf ^ 1); }
        __syncthreads();
    }

    // epilogue
    #pragma unroll
    for (int mi = 0; mi < 4; mi++) {
        #pragma unroll
        for (int nj = 0; nj < 4; nj++) {
            const int cc = n0 + wn * 32 + nj * 8 + tig * 2;
            float bn0 = 0.f, bn1 = 0.f;
            if (bias && bias_on_n) { bn0 = bias[cc]; bn1 = bias[cc + 1]; }
            #pragma unroll
            for (int hh = 0; hh < 2; hh++) {
                const int row = m0 + wm * 64 + mi * 16 + gid + hh * 8;
                float v0 = acc[mi][nj][hh * 2 + 0];
                float v1 = acc[mi][nj][hh * 2 + 1];
                if (bias) {
                    if (bias_on_n) { v0 += bn0; v1 += bn1; }
                    else { const float bm = bias[row]; v0 += bm; v1 += bm; }
                }
                if (resid) {
                    const float2 rr = *(const float2*)&resid[(size_t)row * N + cc];
                    v0 += rr.x; v1 += rr.y;
                }
                float2 o; o.x = v0; o.y = v1;
                *(float2*)&Cp[(size_t)row * N + cc] = o;
            }
        }
    }
}

// ---------------------------------------------------------------------------
// Softmax over last dim (T=1024). One block per row; one float4/thread.
// ---------------------------------------------------------------------------
__global__ __launch_bounds__(256) void softmax_kernel(float* __restrict__ wbuf)
{
    float4* p = (float4*)(wbuf + (size_t)blockIdx.x * T_);
    const int tid = threadIdx.x;
    float4 v = p[tid];

    float mx = fmaxf(fmaxf(v.x, v.y), fmaxf(v.z, v.w));
    #pragma unroll
    for (int o = 16; o > 0; o >>= 1)
        mx = fmaxf(mx, __shfl_xor_sync(0xffffffffu, mx, o));
    __shared__ float sh[8];
    const int wid = tid >> 5, lane = tid & 31;
    if (lane == 0) sh[wid] = mx;
    __syncthreads();
    if (tid == 0) {
        float m = sh[0];
        #pragma unroll
        for (int i = 1; i < 8; i++) m = fmaxf(m, sh[i]);
        sh[0] = m;
    }
    __syncthreads();
    mx = sh[0];
    __syncthreads();

    v.x = __expf(v.x - mx);
    v.y = __expf(v.y - mx);
    v.z = __expf(v.z - mx);
    v.w = __expf(v.w - mx);
    float s = v.x + v.y + v.z + v.w;
    #pragma unroll
    for (int o = 16; o > 0; o >>= 1)
        s += __shfl_xor_sync(0xffffffffu, s, o);
    if (lane == 0) sh[wid] = s;
    __syncthreads();
    if (tid == 0) {
        float a = 0.f;
        #pragma unroll
        for (int i = 0; i < 8; i++) a += sh[i];
        sh[0] = a;
    }
    __syncthreads();
    const float inv = 1.0f / sh[0];

    v.x *= inv; v.y *= inv; v.z *= inv; v.w *= inv;
    p[tid] = v;
}

// ---------------------------------------------------------------------------
// Launch
// ---------------------------------------------------------------------------
extern "C" void kernel_launch(void* const* d_in, const int* in_sizes, int n_in,
                              void* d_out, int out_size)
{
    const float* x     = (const float*)d_in[0];
    const float* gamma = (const float*)d_in[1];
    const float* beta  = (const float*)d_in[2];
    const float* Wq    = (const float*)d_in[3];
    const float* bq    = (const float*)d_in[4];
    const float* Wk    = (const float*)d_in[5];
    const float* bk    = (const float*)d_in[6];
    const float* Wv    = (const float*)d_in[7];
    const float* bv    = (const float*)d_in[8];
    const float* Wp    = (const float*)d_in[9];
    const float* bp    = (const float*)d_in[10];
    float* out = (float*)d_out;

    static float *p_h = nullptr, *p_qkv, *p_w, *p_a, *p_wt, *p_bt;
    if (!p_h) {
        cudaGetSymbolAddress((void**)&p_h,   g_h);
        cudaGetSymbolAddress((void**)&p_qkv, g_qkv);
        cudaGetSymbolAddress((void**)&p_w,   g_w);
        cudaGetSymbolAddress((void**)&p_a,   g_a);
        cudaGetSymbolAddress((void**)&p_wt,  g_wt);
        cudaGetSymbolAddress((void**)&p_bt,  g_bt);
    }

    const size_t sBCT = (size_t)C_ * T_;        // [C,T] batch stride
    const size_t sQKV = (size_t)T_ * 3 * C_;    // [T,1536] batch stride
    const size_t sBTT = (size_t)T_ * T_;
    const size_t sBTC = (size_t)T_ * C_;

    // 1) GroupNorm -> g_h [B, C, T]
    groupnorm_kernel<<<B_ * G_, 256>>>(x, gamma, beta, p_h);

    // 2) Pack QKV weights [1536][512] (q-scale folded)
    pack_qkv_kernel<<<(3 * C_ * C_ / 4) / 256, 256>>>(Wq, bq, Wk, bk, Wv, bv, p_wt, p_bt);

    // 3) Fused QKV: qkv[b,t,o] = sum_c h[b,c,t] * Wt[o,c] + bt[o]
    //    A = h [k=c][m=t] (trans), lda=T.  B = Wt [n=o][k=c], ldb=C.
    {
        dim3 grid((3 * C_) / 128, T_ / 128, B_);
        gemm_bf16<1, 0><<<grid, 256>>>(3 * C_, C_,
                                       p_h, sBCT, T_,
                                       p_wt, 0, C_,
                                       p_qkv, sQKV,
                                       p_bt, 1, nullptr, 0);
    }

    // 4) Scores: w[b,t,s] = q[b,t,:].k[b,s,:]   (scale folded into q)
    //    A = q [m=t][k=c], lda=1536.  B = k [n=s][k=c], ldb=1536 (ptr +C).
    {
        dim3 grid(T_ / 128, T_ / 128, B_);
        gemm_bf16<0, 0><<<grid, 256>>>(T_, C_,
                                       p_qkv, sQKV, 3 * C_,
                                       p_qkv + C_, sQKV, 3 * C_,
                                       p_w, sBTT,
                                       nullptr, 0, nullptr, 0);
    }

    // 5) Softmax over s
    softmax_kernel<<<B_ * T_, 256>>>(p_w);

    // 6) Apply: a[b,t,c] = sum_s w[b,t,s] * v[b,s,c]
    //    A = w [m=t][k=s], lda=T.  B = v [k=s][n=c] (trans), ldb=1536 (ptr +2C).
    {
        dim3 grid(C_ / 128, T_ / 128, B_);
        gemm_bf16<0, 1><<<grid, 256>>>(C_, T_,
                                       p_w, sBTT, T_,
                                       p_qkv + 2 * C_, sQKV, 3 * C_,
                                       p_a, sBTC,
                                       nullptr, 0, nullptr, 0);
    }

    // 7) Projection + residual: out[b,o,t] = x[b,o,t] + bp[o] + Wp[o,:].a[b,t,:]
    //    A = Wp [m=o][k=c], lda=C (Abs=0).  B = a [n=t][k=c], ldb=C.
    {
        dim3 grid(T_ / 128, C_ / 128, B_);
        gemm_bf16<0, 0><<<grid, 256>>>(T_, C_,
                                       Wp, 0, C_,
                                       p_a, sBTC, C_,
                                       out, sBCT,
                                       bp, 0, x, sBCT);
    }
}

// round 4
// speedup vs baseline: 7.6905x; 1.7154x over previous
#include <cuda_runtime.h>
#include <cuda_bf16.h>
#include <cstdint>

#define B_   16
#define C_   512
#define T_   1024
#define G_   32
#define CPG  (C_ / G_)
#define EPS  1e-5f
#define QSCALE 0.04419417382415922f   // C^-1/2

// ---------------------------------------------------------------------------
// Scratch (static __device__ — no allocation allowed)
// ---------------------------------------------------------------------------
__device__ __nv_bfloat16 g_hb [(size_t)B_ * C_ * T_];        // GN out [B,C,T]
__device__ __nv_bfloat16 g_qkv[(size_t)B_ * T_ * 3 * C_];    // [B,T,1536]
__device__ float         g_w  [(size_t)B_ * T_ * T_];        // scores fp32
__device__ __nv_bfloat16 g_wb [(size_t)B_ * T_ * T_];        // softmax out bf16
__device__ __nv_bfloat16 g_ab [(size_t)B_ * T_ * C_];        // attn out [B,T,C]
__device__ __nv_bfloat16 g_wtb[(size_t)3 * C_ * C_];         // qkv weights [3C][C]
__device__ __nv_bfloat16 g_wpb[(size_t)C_ * C_];             // proj weight [C][C]
__device__ float         g_bt [3 * C_];

__device__ __forceinline__ uint32_t pk2(float a, float b) {
    __nv_bfloat162 t = __floats2bfloat162_rn(a, b);
    return *reinterpret_cast<uint32_t*>(&t);
}

// ---------------------------------------------------------------------------
// GroupNorm: fp32 in, bf16 out.
// ---------------------------------------------------------------------------
__global__ __launch_bounds__(256) void groupnorm_kernel(
    const float* __restrict__ x,
    const float* __restrict__ gamma,
    const float* __restrict__ beta,
    __nv_bfloat16* __restrict__ h)
{
    const int b = blockIdx.x >> 5;
    const int g = blockIdx.x & 31;
    const size_t base = ((size_t)b * C_ + (size_t)g * CPG) * T_;
    const float4* xp = (const float4*)(x + base);
    const int N4 = CPG * T_ / 4;
    const int tid = threadIdx.x;

    float s = 0.f, s2 = 0.f;
    for (int i = tid; i < N4; i += 256) {
        float4 v = xp[i];
        s  += v.x + v.y + v.z + v.w;
        s2 += v.x * v.x + v.y * v.y + v.z * v.z + v.w * v.w;
    }
    #pragma unroll
    for (int o = 16; o > 0; o >>= 1) {
        s  += __shfl_xor_sync(0xffffffffu, s, o);
        s2 += __shfl_xor_sync(0xffffffffu, s2, o);
    }
    __shared__ float sh1[8], sh2[8];
    const int wid = tid >> 5, lane = tid & 31;
    if (lane == 0) { sh1[wid] = s; sh2[wid] = s2; }
    __syncthreads();
    if (tid == 0) {
        float a = 0.f, bb = 0.f;
        #pragma unroll
        for (int i = 0; i < 8; i++) { a += sh1[i]; bb += sh2[i]; }
        sh1[0] = a; sh2[0] = bb;
    }
    __syncthreads();
    const float inv_n = 1.0f / (float)(CPG * T_);
    const float mean = sh1[0] * inv_n;
    const float var  = sh2[0] * inv_n - mean * mean;
    const float inv  = rsqrtf(var + EPS);

    for (int i = tid; i < N4; i += 256) {
        const int c = g * CPG + (i >> 8);
        const float ga = gamma[c] * inv;
        const float be = beta[c];
        float4 v = xp[i];
        uint2 o;
        o.x = pk2((v.x - mean) * ga + be, (v.y - mean) * ga + be);
        o.y = pk2((v.z - mean) * ga + be, (v.w - mean) * ga + be);
        *(uint2*)(h + base + (size_t)i * 4) = o;
    }
}

// ---------------------------------------------------------------------------
// Pack all weights to bf16: Wq(scaled)|Wk|Wv -> g_wtb, Wp -> g_wpb.
// ---------------------------------------------------------------------------
__global__ __launch_bounds__(256) void pack_w_kernel(
    const float* __restrict__ Wq, const float* __restrict__ bq,
    const float* __restrict__ Wk, const float* __restrict__ bk,
    const float* __restrict__ Wv, const float* __restrict__ bv,
    const float* __restrict__ Wp,
    __nv_bfloat16* __restrict__ Wt, __nv_bfloat16* __restrict__ Wpb,
    float* __restrict__ bt)
{
    const int idx = blockIdx.x * 256 + threadIdx.x;   // float4 idx, 2048*128
    const int o  = idx >> 7;
    const int c4 = idx & 127;
    const float* src; float s = 1.f; __nv_bfloat16* dst;
    if (o < C_)          { src = Wq + (size_t)o * C_; s = QSCALE; dst = Wt + (size_t)o * C_; }
    else if (o < 2 * C_) { src = Wk + (size_t)(o - C_) * C_;      dst = Wt + (size_t)o * C_; }
    else if (o < 3 * C_) { src = Wv + (size_t)(o - 2 * C_) * C_;  dst = Wt + (size_t)o * C_; }
    else                 { src = Wp + (size_t)(o - 3 * C_) * C_;  dst = Wpb + (size_t)(o - 3 * C_) * C_; }
    float4 v = *(const float4*)(src + c4 * 4);
    uint2 p; p.x = pk2(v.x * s, v.y * s); p.y = pk2(v.z * s, v.w * s);
    *(uint2*)(dst + c4 * 4) = p;
    if (idx < 3 * C_) {
        bt[idx] = (idx < C_) ? bq[idx] * QSCALE
                : (idx < 2 * C_) ? bk[idx - C_] : bv[idx - 2 * C_];
    }
}

// ---------------------------------------------------------------------------
// bf16 GEMM, cp.async 4-stage pipeline. Block 128x128, BK=32, 256 thr.
// 8 warps (2x4), warp tile 64x32, mma.m16n8k16, ldmatrix.x4.
// AT/BT: 0 = [row][k] k-contig, 1 = [k][row] row-contig (trans ldmatrix).
// OUTBF: 1 = bf16 output, 0 = fp32 output.
// ---------------------------------------------------------------------------
__device__ __forceinline__ void ldsm4(uint32_t* r, uint32_t a) {
    asm volatile("ldmatrix.sync.aligned.m8n8.x4.shared.b16 {%0,%1,%2,%3}, [%4];"
                 : "=r"(r[0]), "=r"(r[1]), "=r"(r[2]), "=r"(r[3]) : "r"(a));
}
__device__ __forceinline__ void ldsm4t(uint32_t* r, uint32_t a) {
    asm volatile("ldmatrix.sync.aligned.m8n8.x4.trans.shared.b16 {%0,%1,%2,%3}, [%4];"
                 : "=r"(r[0]), "=r"(r[1]), "=r"(r[2]), "=r"(r[3]) : "r"(a));
}
__device__ __forceinline__ void mma16(float* c, const uint32_t* a, const uint32_t* b) {
    asm volatile("mma.sync.aligned.m16n8k16.row.col.f32.bf16.bf16.f32 "
                 "{%0,%1,%2,%3},{%4,%5,%6,%7},{%8,%9},{%0,%1,%2,%3};"
                 : "+f"(c[0]), "+f"(c[1]), "+f"(c[2]), "+f"(c[3])
                 : "r"(a[0]), "r"(a[1]), "r"(a[2]), "r"(a[3]), "r"(b[0]), "r"(b[1]));
}
__device__ __forceinline__ void cpa16(uint32_t dst, const void* src) {
    asm volatile("cp.async.cg.shared.global [%0], [%1], 16;" :: "r"(dst), "l"(src));
}
#define CP_COMMIT() asm volatile("cp.async.commit_group;")
#define CP_WAIT2()  asm volatile("cp.async.wait_group 2;")

#define ABUF_OFF 0
#define BBUF_OFF 10240
#define BUFSTEP  20480
#define STAGES   4
#define SMEM_DYN (STAGES * BUFSTEP)

template<int AT, int BT, int OUTBF>
__global__ __launch_bounds__(256) void gemm_ca(
    int N, int K,
    const __nv_bfloat16* __restrict__ A, size_t Abs, int lda,
    const __nv_bfloat16* __restrict__ Bp, size_t Bbs, int ldb,
    void* __restrict__ Cvp, size_t Cbs,
    const float* __restrict__ bias, int bias_on_n,
    const float* __restrict__ resid, size_t Rbs)
{
    const int bz = blockIdx.z;
    A  += (size_t)bz * Abs;
    Bp += (size_t)bz * Bbs;
    if (resid) resid += (size_t)bz * Rbs;

    extern __shared__ __align__(16) unsigned char sm[];
    const uint32_t sb = (uint32_t)__cvta_generic_to_shared(sm);

    const int tid = threadIdx.x;
    const int m0 = blockIdx.y * 128;
    const int n0 = blockIdx.x * 128;
    const int warp = tid >> 5, lane = tid & 31;
    const int wm = warp >> 2, wn = warp & 3;
    const int gid = lane >> 2, tig = lane & 3;

    float acc[4][4][4];
    #pragma unroll
    for (int i = 0; i < 4; i++)
        #pragma unroll
        for (int j = 0; j < 4; j++)
            #pragma unroll
            for (int r = 0; r < 4; r++) acc[i][j][r] = 0.f;

    // --- per-thread cp.async source pointers (advance by kstep per stage) ---
    const __nv_bfloat16 *aS0, *aS1, *bS0, *bS1;
    uint32_t aD0, aD1, bD0, bD1;      // dst offsets within a stage buffer
    size_t aStep, bStep;
    {
        int i0 = tid, i1 = tid + 256;
        if (AT == 0) {
            aS0 = A + (size_t)(m0 + (i0 >> 2)) * lda + (i0 & 3) * 8;
            aS1 = A + (size_t)(m0 + (i1 >> 2)) * lda + (i1 & 3) * 8;
            aD0 = ABUF_OFF + (i0 >> 2) * 80 + (i0 & 3) * 16;
            aD1 = ABUF_OFF + (i1 >> 2) * 80 + (i1 & 3) * 16;
            aStep = 32;
        } else {
            aS0 = A + (size_t)(i0 >> 4) * lda + m0 + (i0 & 15) * 8;
            aS1 = A + (size_t)(i1 >> 4) * lda + m0 + (i1 & 15) * 8;
            aD0 = ABUF_OFF + (i0 >> 4) * 272 + (i0 & 15) * 16;
            aD1 = ABUF_OFF + (i1 >> 4) * 272 + (i1 & 15) * 16;
            aStep = (size_t)32 * lda;
        }
        if (BT == 0) {
            bS0 = Bp + (size_t)(n0 + (i0 >> 2)) * ldb + (i0 & 3) * 8;
            bS1 = Bp + (size_t)(n0 + (i1 >> 2)) * ldb + (i1 & 3) * 8;
            bD0 = BBUF_OFF + (i0 >> 2) * 80 + (i0 & 3) * 16;
            bD1 = BBUF_OFF + (i1 >> 2) * 80 + (i1 & 3) * 16;
            bStep = 32;
        } else {
            bS0 = Bp + (size_t)(i0 >> 4) * ldb + n0 + (i0 & 15) * 8;
            bS1 = Bp + (size_t)(i1 >> 4) * ldb + n0 + (i1 & 15) * 8;
            bD0 = BBUF_OFF + (i0 >> 4) * 272 + (i0 & 15) * 16;
            bD1 = BBUF_OFF + (i1 >> 4) * 272 + (i1 & 15) * 16;
            bStep = (size_t)32 * ldb;
        }
    }
    auto issue = [&](int stage) {
        const uint32_t bufb = sb + (stage & (STAGES - 1)) * BUFSTEP;
        cpa16(bufb + aD0, aS0); cpa16(bufb + aD1, aS1);
        cpa16(bufb + bD0, bS0); cpa16(bufb + bD1, bS1);
        aS0 += aStep; aS1 += aStep; bS0 += bStep; bS1 += bStep;
    };

    // ldmatrix base addresses (buffer 0)
    const uint32_t aBase = (AT == 0)
        ? sb + ABUF_OFF + (uint32_t)(wm * 64 + (lane & 15)) * 80 + ((lane >> 4) & 1) * 16
        : sb + ABUF_OFF + (uint32_t)(((lane >> 4) & 1) * 8 + (lane & 7)) * 272
                        + (uint32_t)(wm * 64 + ((lane >> 3) & 1) * 8) * 2;
    const uint32_t bBase = (BT == 0)
        ? sb + BBUF_OFF + (uint32_t)(wn * 32 + ((lane >> 4) & 1) * 8 + (lane & 7)) * 80
                        + ((lane >> 3) & 1) * 16
        : sb + BBUF_OFF + (uint32_t)(((lane >> 3) & 1) * 8 + (lane & 7)) * 272
                        + (uint32_t)(wn * 32 + ((lane >> 4) & 1) * 8) * 2;

    const int nIter = K >> 5;
    // prologue: stages 0..2
    issue(0); CP_COMMIT();
    issue(1); CP_COMMIT();
    issue(2); CP_COMMIT();

    for (int it = 0; it < nIter; ++it) {
        CP_WAIT2();
        __syncthreads();
        if (it + 3 < nIter) issue(it + 3);
        CP_COMMIT();

        const uint32_t aB = aBase + (it & (STAGES - 1)) * BUFSTEP;
        const uint32_t bB = bBase + (it & (STAGES - 1)) * BUFSTEP;
        #pragma unroll
        for (int kk = 0; kk < 2; kk++) {
            uint32_t af[4][4], bfr[2][4];
            #pragma unroll
            for (int mi = 0; mi < 4; mi++) {
                const uint32_t ad = (AT == 0) ? aB + mi * 1280 + kk * 32
                                              : aB + kk * 4352 + mi * 32;
                if (AT == 0) ldsm4(af[mi], ad); else ldsm4t(af[mi], ad);
            }
            #pragma unroll
            for (int np = 0; np < 2; np++) {
                const uint32_t bd = (BT == 0) ? bB + np * 1280 + kk * 32
                                              : bB + kk * 4352 + np * 32;
                if (BT == 0) ldsm4(bfr[np], bd); else ldsm4t(bfr[np], bd);
            }
            #pragma unroll
            for (int mi = 0; mi < 4; mi++)
                #pragma unroll
                for (int nj = 0; nj < 4; nj++)
                    mma16(acc[mi][nj], af[mi], &bfr[nj >> 1][(nj & 1) * 2]);
        }
        __syncthreads();
    }

    // epilogue
    #pragma unroll
    for (int mi = 0; mi < 4; mi++) {
        #pragma unroll
        for (int nj = 0; nj < 4; nj++) {
            const int cc = n0 + wn * 32 + nj * 8 + tig * 2;
            float bn0 = 0.f, bn1 = 0.f;
            if (bias && bias_on_n) { bn0 = bias[cc]; bn1 = bias[cc + 1]; }
            #pragma unroll
            for (int hh = 0; hh < 2; hh++) {
                const int row = m0 + wm * 64 + mi * 16 + gid + hh * 8;
                float v0 = acc[mi][nj][hh * 2 + 0];
                float v1 = acc[mi][nj][hh * 2 + 1];
                if (bias) {
                    if (bias_on_n) { v0 += bn0; v1 += bn1; }
                    else { const float bm = bias[row]; v0 += bm; v1 += bm; }
                }
                if (resid) {
                    const float2 rr = *(const float2*)&resid[(size_t)row * N + cc];
                    v0 += rr.x; v1 += rr.y;
                }
                if (OUTBF) {
                    __nv_bfloat16* Cb = (__nv_bfloat16*)Cvp + (size_t)bz * Cbs;
                    *(uint32_t*)&Cb[(size_t)row * N + cc] = pk2(v0, v1);
                } else {
                    float* Cf = (float*)Cvp + (size_t)bz * Cbs;
                    float2 o; o.x = v0; o.y = v1;
                    *(float2*)&Cf[(size_t)row * N + cc] = o;
                }
            }
        }
    }
}

// ---------------------------------------------------------------------------
// Softmax: fp32 in -> bf16 out. One block per row.
// ---------------------------------------------------------------------------
__global__ __launch_bounds__(256) void softmax_kernel(
    const float* __restrict__ win, __nv_bfloat16* __restrict__ wout)
{
    const float4* p = (const float4*)(win + (size_t)blockIdx.x * T_);
    const int tid = threadIdx.x;
    float4 v = p[tid];

    float mx = fmaxf(fmaxf(v.x, v.y), fmaxf(v.z, v.w));
    #pragma unroll
    for (int o = 16; o > 0; o >>= 1)
        mx = fmaxf(mx, __shfl_xor_sync(0xffffffffu, mx, o));
    __shared__ float sh[8];
    const int wid = tid >> 5, lane = tid & 31;
    if (lane == 0) sh[wid] = mx;
    __syncthreads();
    if (tid == 0) {
        float m = sh[0];
        #pragma unroll
        for (int i = 1; i < 8; i++) m = fmaxf(m, sh[i]);
        sh[0] = m;
    }
    __syncthreads();
    mx = sh[0];
    __syncthreads();

    v.x = __expf(v.x - mx);
    v.y = __expf(v.y - mx);
    v.z = __expf(v.z - mx);
    v.w = __expf(v.w - mx);
    float s = v.x + v.y + v.z + v.w;
    #pragma unroll
    for (int o = 16; o > 0; o >>= 1)
        s += __shfl_xor_sync(0xffffffffu, s, o);
    if (lane == 0) sh[wid] = s;
    __syncthreads();
    if (tid == 0) {
        float a = 0.f;
        #pragma unroll
        for (int i = 0; i < 8; i++) a += sh[i];
        sh[0] = a;
    }
    __syncthreads();
    const float inv = 1.0f / sh[0];

    uint2 o;
    o.x = pk2(v.x * inv, v.y * inv);
    o.y = pk2(v.z * inv, v.w * inv);
    *(uint2*)(wout + (size_t)blockIdx.x * T_ + tid * 4) = o;
}

// ---------------------------------------------------------------------------
// Launch
// ---------------------------------------------------------------------------
extern "C" void kernel_launch(void* const* d_in, const int* in_sizes, int n_in,
                              void* d_out, int out_size)
{
    const float* x     = (const float*)d_in[0];
    const float* gamma = (const float*)d_in[1];
    const float* beta  = (const float*)d_in[2];
    const float* Wq    = (const float*)d_in[3];
    const float* bq    = (const float*)d_in[4];
    const float* Wk    = (const float*)d_in[5];
    const float* bk    = (const float*)d_in[6];
    const float* Wv    = (const float*)d_in[7];
    const float* bv    = (const float*)d_in[8];
    const float* Wp    = (const float*)d_in[9];
    const float* bp    = (const float*)d_in[10];
    float* out = (float*)d_out;

    static bool inited = false;
    static __nv_bfloat16 *p_hb, *p_qkv, *p_wb, *p_ab, *p_wtb, *p_wpb;
    static float *p_w, *p_bt;
    if (!inited) {
        cudaGetSymbolAddress((void**)&p_hb,  g_hb);
        cudaGetSymbolAddress((void**)&p_qkv, g_qkv);
        cudaGetSymbolAddress((void**)&p_w,   g_w);
        cudaGetSymbolAddress((void**)&p_wb,  g_wb);
        cudaGetSymbolAddress((void**)&p_ab,  g_ab);
        cudaGetSymbolAddress((void**)&p_wtb, g_wtb);
        cudaGetSymbolAddress((void**)&p_wpb, g_wpb);
        cudaGetSymbolAddress((void**)&p_bt,  g_bt);
        cudaFuncSetAttribute(gemm_ca<1, 0, 1>, cudaFuncAttributeMaxDynamicSharedMemorySize, SMEM_DYN);
        cudaFuncSetAttribute(gemm_ca<0, 0, 0>, cudaFuncAttributeMaxDynamicSharedMemorySize, SMEM_DYN);
        cudaFuncSetAttribute(gemm_ca<0, 1, 1>, cudaFuncAttributeMaxDynamicSharedMemorySize, SMEM_DYN);
        inited = true;
    }

    const size_t sBCT = (size_t)C_ * T_;
    const size_t sQKV = (size_t)T_ * 3 * C_;
    const size_t sBTT = (size_t)T_ * T_;
    const size_t sBTC = (size_t)T_ * C_;

    // 1) GroupNorm -> bf16 h [B,C,T]
    groupnorm_kernel<<<B_ * G_, 256>>>(x, gamma, beta, p_hb);

    // 2) Pack all weights to bf16
    pack_w_kernel<<<(4 * C_ * C_ / 4) / 256, 256>>>(Wq, bq, Wk, bk, Wv, bv, Wp,
                                                    p_wtb, p_wpb, p_bt);

    // 3) QKV: qkv[b,t,o] = sum_c h[b,c,t]*Wt[o,c] + bt[o]
    //    A = h [k=c][m=t] trans (lda=T), B = Wt [n=o][k=c] (ldb=C). Out bf16.
    {
        dim3 grid((3 * C_) / 128, T_ / 128, B_);
        gemm_ca<1, 0, 1><<<grid, 256, SMEM_DYN>>>(3 * C_, C_,
            p_hb, sBCT, T_,  p_wtb, 0, C_,
            p_qkv, sQKV, p_bt, 1, nullptr, 0);
    }

    // 4) Scores: w = q.k^T (scale folded), out fp32.
    {
        dim3 grid(T_ / 128, T_ / 128, B_);
        gemm_ca<0, 0, 0><<<grid, 256, SMEM_DYN>>>(T_, C_,
            p_qkv, sQKV, 3 * C_,  p_qkv + C_, sQKV, 3 * C_,
            p_w, sBTT, nullptr, 0, nullptr, 0);
    }

    // 5) Softmax fp32 -> bf16
    softmax_kernel<<<B_ * T_, 256>>>(p_w, p_wb);

    // 6) Apply: a[b,t,c] = sum_s wb[b,t,s]*v[b,s,c]
    //    A = wb [m=t][k=s] (lda=T), B = v [k=s][n=c] trans (ldb=1536). Out bf16.
    {
        dim3 grid(C_ / 128, T_ / 128, B_);
        gemm_ca<0, 1, 1><<<grid, 256, SMEM_DYN>>>(C_, T_,
            p_wb, sBTT, T_,  p_qkv + 2 * C_, sQKV, 3 * C_,
            p_ab, sBTC, nullptr, 0, nullptr, 0);
    }

    // 7) Proj + residual: out[b,o,t] = x[b,o,t] + bp[o] + Wp[o,:].a[b,t,:]
    //    A = Wp [m=o][k=c] (lda=C, Abs=0), B = a [n=t][k=c] (ldb=C). Out fp32.
    {
        dim3 grid(T_ / 128, C_ / 128, B_);
        gemm_ca<0, 0, 0><<<grid, 256, SMEM_DYN>>>(T_, C_,
            p_wpb, 0, C_,  p_ab, sBTC, C_,
            out, sBCT, bp, 0, x, sBCT);
    }
}

// round 5
// speedup vs baseline: 8.4358x; 1.0969x over previous
#include <cuda_runtime.h>
#include <cuda_bf16.h>
#include <cstdint>

#define B_   16
#define C_   512
#define T_   1024
#define G_   32
#define CPG  (C_ / G_)
#define EPS  1e-5f
#define QSCALE 0.04419417382415922f   // C^-1/2

// ---------------------------------------------------------------------------
// Scratch (static __device__ — no allocation allowed)
// ---------------------------------------------------------------------------
__device__ __nv_bfloat16 g_hb [(size_t)B_ * C_ * T_];        // GN out [B,C,T]
__device__ __nv_bfloat16 g_qkv[(size_t)B_ * T_ * 3 * C_];    // [B,T,1536]
__device__ float         g_w  [(size_t)B_ * T_ * T_];        // scores fp32
__device__ __nv_bfloat16 g_wb [(size_t)B_ * T_ * T_];        // softmax out bf16
__device__ __nv_bfloat16 g_ab [(size_t)B_ * T_ * C_];        // attn out [B,T,C]
__device__ __nv_bfloat16 g_wtb[(size_t)3 * C_ * C_];         // qkv weights [3C][C]
__device__ __nv_bfloat16 g_wpb[(size_t)C_ * C_];             // proj weight [C][C]
__device__ float         g_bt [3 * C_];

__device__ __forceinline__ uint32_t pk2(float a, float b) {
    __nv_bfloat162 t = __floats2bfloat162_rn(a, b);
    return *reinterpret_cast<uint32_t*>(&t);
}

// ---------------------------------------------------------------------------
// GroupNorm: fp32 in, bf16 out.
// ---------------------------------------------------------------------------
__global__ __launch_bounds__(256) void groupnorm_kernel(
    const float* __restrict__ x,
    const float* __restrict__ gamma,
    const float* __restrict__ beta,
    __nv_bfloat16* __restrict__ h)
{
    const int b = blockIdx.x >> 5;
    const int g = blockIdx.x & 31;
    const size_t base = ((size_t)b * C_ + (size_t)g * CPG) * T_;
    const float4* xp = (const float4*)(x + base);
    const int N4 = CPG * T_ / 4;
    const int tid = threadIdx.x;

    float s = 0.f, s2 = 0.f;
    for (int i = tid; i < N4; i += 256) {
        float4 v = xp[i];
        s  += v.x + v.y + v.z + v.w;
        s2 += v.x * v.x + v.y * v.y + v.z * v.z + v.w * v.w;
    }
    #pragma unroll
    for (int o = 16; o > 0; o >>= 1) {
        s  += __shfl_xor_sync(0xffffffffu, s, o);
        s2 += __shfl_xor_sync(0xffffffffu, s2, o);
    }
    __shared__ float sh1[8], sh2[8];
    const int wid = tid >> 5, lane = tid & 31;
    if (lane == 0) { sh1[wid] = s; sh2[wid] = s2; }
    __syncthreads();
    if (tid == 0) {
        float a = 0.f, bb = 0.f;
        #pragma unroll
        for (int i = 0; i < 8; i++) { a += sh1[i]; bb += sh2[i]; }
        sh1[0] = a; sh2[0] = bb;
    }
    __syncthreads();
    const float inv_n = 1.0f / (float)(CPG * T_);
    const float mean = sh1[0] * inv_n;
    const float var  = sh2[0] * inv_n - mean * mean;
    const float inv  = rsqrtf(var + EPS);

    for (int i = tid; i < N4; i += 256) {
        const int c = g * CPG + (i >> 8);
        const float ga = gamma[c] * inv;
        const float be = beta[c];
        float4 v = xp[i];
        uint2 o;
        o.x = pk2((v.x - mean) * ga + be, (v.y - mean) * ga + be);
        o.y = pk2((v.z - mean) * ga + be, (v.w - mean) * ga + be);
        *(uint2*)(h + base + (size_t)i * 4) = o;
    }
}

// ---------------------------------------------------------------------------
// Pack all weights to bf16: Wq(scaled)|Wk|Wv -> g_wtb, Wp -> g_wpb.
// ---------------------------------------------------------------------------
__global__ __launch_bounds__(256) void pack_w_kernel(
    const float* __restrict__ Wq, const float* __restrict__ bq,
    const float* __restrict__ Wk, const float* __restrict__ bk,
    const float* __restrict__ Wv, const float* __restrict__ bv,
    const float* __restrict__ Wp,
    __nv_bfloat16* __restrict__ Wt, __nv_bfloat16* __restrict__ Wpb,
    float* __restrict__ bt)
{
    const int idx = blockIdx.x * 256 + threadIdx.x;   // float4 idx, 2048*128
    const int o  = idx >> 7;
    const int c4 = idx & 127;
    const float* src; float s = 1.f; __nv_bfloat16* dst;
    if (o < C_)          { src = Wq + (size_t)o * C_; s = QSCALE; dst = Wt + (size_t)o * C_; }
    else if (o < 2 * C_) { src = Wk + (size_t)(o - C_) * C_;      dst = Wt + (size_t)o * C_; }
    else if (o < 3 * C_) { src = Wv + (size_t)(o - 2 * C_) * C_;  dst = Wt + (size_t)o * C_; }
    else                 { src = Wp + (size_t)(o - 3 * C_) * C_;  dst = Wpb + (size_t)(o - 3 * C_) * C_; }
    float4 v = *(const float4*)(src + c4 * 4);
    uint2 p; p.x = pk2(v.x * s, v.y * s); p.y = pk2(v.z * s, v.w * s);
    *(uint2*)(dst + c4 * 4) = p;
    if (idx < 3 * C_) {
        bt[idx] = (idx < C_) ? bq[idx] * QSCALE
                : (idx < 2 * C_) ? bk[idx - C_] : bv[idx - 2 * C_];
    }
}

// ---------------------------------------------------------------------------
// bf16 GEMM, cp.async 4-stage pipeline, ONE barrier per k-iteration.
// Block 128x128, BK=32, 256 thr, 8 warps (2x4), warp tile 64x32, m16n8k16.
// AT/BT: 0 = [row][k] k-contig, 1 = [k][row] row-contig (trans ldmatrix).
// OUTBF: 1 = bf16 output, 0 = fp32 output.
// ---------------------------------------------------------------------------
__device__ __forceinline__ void ldsm4(uint32_t* r, uint32_t a) {
    asm volatile("ldmatrix.sync.aligned.m8n8.x4.shared.b16 {%0,%1,%2,%3}, [%4];"
                 : "=r"(r[0]), "=r"(r[1]), "=r"(r[2]), "=r"(r[3]) : "r"(a));
}
__device__ __forceinline__ void ldsm4t(uint32_t* r, uint32_t a) {
    asm volatile("ldmatrix.sync.aligned.m8n8.x4.trans.shared.b16 {%0,%1,%2,%3}, [%4];"
                 : "=r"(r[0]), "=r"(r[1]), "=r"(r[2]), "=r"(r[3]) : "r"(a));
}
__device__ __forceinline__ void mma16(float* c, const uint32_t* a, const uint32_t* b) {
    asm volatile("mma.sync.aligned.m16n8k16.row.col.f32.bf16.bf16.f32 "
                 "{%0,%1,%2,%3},{%4,%5,%6,%7},{%8,%9},{%0,%1,%2,%3};"
                 : "+f"(c[0]), "+f"(c[1]), "+f"(c[2]), "+f"(c[3])
                 : "r"(a[0]), "r"(a[1]), "r"(a[2]), "r"(a[3]), "r"(b[0]), "r"(b[1]));
}
__device__ __forceinline__ void cpa16(uint32_t dst, const void* src) {
    asm volatile("cp.async.cg.shared.global [%0], [%1], 16;" :: "r"(dst), "l"(src));
}
#define CP_COMMIT() asm volatile("cp.async.commit_group;")
#define CP_WAIT2()  asm volatile("cp.async.wait_group 2;")

#define ABUF_OFF 0
#define BBUF_OFF 10240
#define BUFSTEP  20480
#define STAGES   4
#define SMEM_DYN (STAGES * BUFSTEP)

template<int AT, int BT, int OUTBF>
__global__ __launch_bounds__(256, 2) void gemm_ca(
    int N, int K,
    const __nv_bfloat16* __restrict__ A, size_t Abs, int lda,
    const __nv_bfloat16* __restrict__ Bp, size_t Bbs, int ldb,
    void* __restrict__ Cvp, size_t Cbs,
    const float* __restrict__ bias, int bias_on_n,
    const float* __restrict__ resid, size_t Rbs)
{
    const int bz = blockIdx.z;
    A  += (size_t)bz * Abs;
    Bp += (size_t)bz * Bbs;
    if (resid) resid += (size_t)bz * Rbs;

    extern __shared__ __align__(16) unsigned char sm[];
    const uint32_t sb = (uint32_t)__cvta_generic_to_shared(sm);

    const int tid = threadIdx.x;
    const int m0 = blockIdx.y * 128;
    const int n0 = blockIdx.x * 128;
    const int warp = tid >> 5, lane = tid & 31;
    const int wm = warp >> 2, wn = warp & 3;
    const int gid = lane >> 2, tig = lane & 3;

    float acc[4][4][4];
    #pragma unroll
    for (int i = 0; i < 4; i++)
        #pragma unroll
        for (int j = 0; j < 4; j++)
            #pragma unroll
            for (int r = 0; r < 4; r++) acc[i][j][r] = 0.f;

    // --- per-thread cp.async source pointers ---
    const __nv_bfloat16 *aS0, *aS1, *bS0, *bS1;
    uint32_t aD0, aD1, bD0, bD1;
    size_t aStep, bStep;
    {
        int i0 = tid, i1 = tid + 256;
        if (AT == 0) {
            aS0 = A + (size_t)(m0 + (i0 >> 2)) * lda + (i0 & 3) * 8;
            aS1 = A + (size_t)(m0 + (i1 >> 2)) * lda + (i1 & 3) * 8;
            aD0 = ABUF_OFF + (i0 >> 2) * 80 + (i0 & 3) * 16;
            aD1 = ABUF_OFF + (i1 >> 2) * 80 + (i1 & 3) * 16;
            aStep = 32;
        } else {
            aS0 = A + (size_t)(i0 >> 4) * lda + m0 + (i0 & 15) * 8;
            aS1 = A + (size_t)(i1 >> 4) * lda + m0 + (i1 & 15) * 8;
            aD0 = ABUF_OFF + (i0 >> 4) * 272 + (i0 & 15) * 16;
            aD1 = ABUF_OFF + (i1 >> 4) * 272 + (i1 & 15) * 16;
            aStep = (size_t)32 * lda;
        }
        if (BT == 0) {
            bS0 = Bp + (size_t)(n0 + (i0 >> 2)) * ldb + (i0 & 3) * 8;
            bS1 = Bp + (size_t)(n0 + (i1 >> 2)) * ldb + (i1 & 3) * 8;
            bD0 = BBUF_OFF + (i0 >> 2) * 80 + (i0 & 3) * 16;
            bD1 = BBUF_OFF + (i1 >> 2) * 80 + (i1 & 3) * 16;
            bStep = 32;
        } else {
            bS0 = Bp + (size_t)(i0 >> 4) * ldb + n0 + (i0 & 15) * 8;
            bS1 = Bp + (size_t)(i1 >> 4) * ldb + n0 + (i1 & 15) * 8;
            bD0 = BBUF_OFF + (i0 >> 4) * 272 + (i0 & 15) * 16;
            bD1 = BBUF_OFF + (i1 >> 4) * 272 + (i1 & 15) * 16;
            bStep = (size_t)32 * ldb;
        }
    }
    auto issueBuf = [&](uint32_t bufb) {
        cpa16(bufb + aD0, aS0); cpa16(bufb + aD1, aS1);
        cpa16(bufb + bD0, bS0); cpa16(bufb + bD1, bS1);
        aS0 += aStep; aS1 += aStep; bS0 += bStep; bS1 += bStep;
    };

    // ldmatrix base addresses (buffer 0)
    const uint32_t aBase = (AT == 0)
        ? sb + ABUF_OFF + (uint32_t)(wm * 64 + (lane & 15)) * 80 + ((lane >> 4) & 1) * 16
        : sb + ABUF_OFF + (uint32_t)(((lane >> 4) & 1) * 8 + (lane & 7)) * 272
                        + (uint32_t)(wm * 64 + ((lane >> 3) & 1) * 8) * 2;
    const uint32_t bBase = (BT == 0)
        ? sb + BBUF_OFF + (uint32_t)(wn * 32 + ((lane >> 4) & 1) * 8 + (lane & 7)) * 80
                        + ((lane >> 3) & 1) * 16
        : sb + BBUF_OFF + (uint32_t)(((lane >> 3) & 1) * 8 + (lane & 7)) * 272
                        + (uint32_t)(wn * 32 + ((lane >> 4) & 1) * 8) * 2;

    const int nIter = K >> 5;     // multiple of 4 for all our shapes
    issueBuf(sb + 0 * BUFSTEP); CP_COMMIT();
    issueBuf(sb + 1 * BUFSTEP); CP_COMMIT();
    issueBuf(sb + 2 * BUFSTEP); CP_COMMIT();

    for (int itb = 0; itb < nIter; itb += 4) {
        #pragma unroll
        for (int u = 0; u < 4; u++) {
            const int it = itb + u;
            CP_WAIT2();
            __syncthreads();
            // issue stage it+3 into buffer (it+3)&3 == (u+3)&3 (compile-time).
            // Safe: the barrier above proves every warp finished the MMA slab
            // of iteration it-1, whose buffer (it-1)&3 == (u+3)&3 this rewrites.
            if (it + 3 < nIter) issueBuf(sb + ((u + 3) & 3) * BUFSTEP);
            CP_COMMIT();

            const uint32_t aB = aBase + u * BUFSTEP;
            const uint32_t bB = bBase + u * BUFSTEP;
            #pragma unroll
            for (int kk = 0; kk < 2; kk++) {
                uint32_t af[4][4], bfr[2][4];
                #pragma unroll
                for (int mi = 0; mi < 4; mi++) {
                    const uint32_t ad = (AT == 0) ? aB + mi * 1280 + kk * 32
                                                  : aB + kk * 4352 + mi * 32;
                    if (AT == 0) ldsm4(af[mi], ad); else ldsm4t(af[mi], ad);
                }
                #pragma unroll
                for (int np = 0; np < 2; np++) {
                    const uint32_t bd = (BT == 0) ? bB + np * 1280 + kk * 32
                                                  : bB + kk * 4352 + np * 32;
                    if (BT == 0) ldsm4(bfr[np], bd); else ldsm4t(bfr[np], bd);
                }
                #pragma unroll
                for (int mi = 0; mi < 4; mi++)
                    #pragma unroll
                    for (int nj = 0; nj < 4; nj++)
                        mma16(acc[mi][nj], af[mi], &bfr[nj >> 1][(nj & 1) * 2]);
            }
            // NOTE: no trailing barrier — next iteration's top barrier provides
            // the producer/consumer ordering for buffer reuse.
        }
    }

    // epilogue
    #pragma unroll
    for (int mi = 0; mi < 4; mi++) {
        #pragma unroll
        for (int nj = 0; nj < 4; nj++) {
            const int cc = n0 + wn * 32 + nj * 8 + tig * 2;
            float bn0 = 0.f, bn1 = 0.f;
            if (bias && bias_on_n) { bn0 = bias[cc]; bn1 = bias[cc + 1]; }
            #pragma unroll
            for (int hh = 0; hh < 2; hh++) {
                const int row = m0 + wm * 64 + mi * 16 + gid + hh * 8;
                float v0 = acc[mi][nj][hh * 2 + 0];
                float v1 = acc[mi][nj][hh * 2 + 1];
                if (bias) {
                    if (bias_on_n) { v0 += bn0; v1 += bn1; }
                    else { const float bm = bias[row]; v0 += bm; v1 += bm; }
                }
                if (resid) {
                    const float2 rr = *(const float2*)&resid[(size_t)row * N + cc];
                    v0 += rr.x; v1 += rr.y;
                }
                if (OUTBF) {
                    __nv_bfloat16* Cb = (__nv_bfloat16*)Cvp + (size_t)bz * Cbs;
                    *(uint32_t*)&Cb[(size_t)row * N + cc] = pk2(v0, v1);
                } else {
                    float* Cf = (float*)Cvp + (size_t)bz * Cbs;
                    float2 o; o.x = v0; o.y = v1;
                    *(float2*)&Cf[(size_t)row * N + cc] = o;
                }
            }
        }
    }
}

// ---------------------------------------------------------------------------
// Softmax: fp32 in -> bf16 out. One block per row.
// ---------------------------------------------------------------------------
__global__ __launch_bounds__(256) void softmax_kernel(
    const float* __restrict__ win, __nv_bfloat16* __restrict__ wout)
{
    const float4* p = (const float4*)(win + (size_t)blockIdx.x * T_);
    const int tid = threadIdx.x;
    float4 v = p[tid];

    float mx = fmaxf(fmaxf(v.x, v.y), fmaxf(v.z, v.w));
    #pragma unroll
    for (int o = 16; o > 0; o >>= 1)
        mx = fmaxf(mx, __shfl_xor_sync(0xffffffffu, mx, o));
    __shared__ float sh[8];
    const int wid = tid >> 5, lane = tid & 31;
    if (lane == 0) sh[wid] = mx;
    __syncthreads();
    if (tid == 0) {
        float m = sh[0];
        #pragma unroll
        for (int i = 1; i < 8; i++) m = fmaxf(m, sh[i]);
        sh[0] = m;
    }
    __syncthreads();
    mx = sh[0];
    __syncthreads();

    v.x = __expf(v.x - mx);
    v.y = __expf(v.y - mx);
    v.z = __expf(v.z - mx);
    v.w = __expf(v.w - mx);
    float s = v.x + v.y + v.z + v.w;
    #pragma unroll
    for (int o = 16; o > 0; o >>= 1)
        s += __shfl_xor_sync(0xffffffffu, s, o);
    if (lane == 0) sh[wid] = s;
    __syncthreads();
    if (tid == 0) {
        float a = 0.f;
        #pragma unroll
        for (int i = 0; i < 8; i++) a += sh[i];
        sh[0] = a;
    }
    __syncthreads();
    const float inv = 1.0f / sh[0];

    uint2 o;
    o.x = pk2(v.x * inv, v.y * inv);
    o.y = pk2(v.z * inv, v.w * inv);
    *(uint2*)(wout + (size_t)blockIdx.x * T_ + tid * 4) = o;
}

// ---------------------------------------------------------------------------
// Launch
// ---------------------------------------------------------------------------
extern "C" void kernel_launch(void* const* d_in, const int* in_sizes, int n_in,
                              void* d_out, int out_size)
{
    const float* x     = (const float*)d_in[0];
    const float* gamma = (const float*)d_in[1];
    const float* beta  = (const float*)d_in[2];
    const float* Wq    = (const float*)d_in[3];
    const float* bq    = (const float*)d_in[4];
    const float* Wk    = (const float*)d_in[5];
    const float* bk    = (const float*)d_in[6];
    const float* Wv    = (const float*)d_in[7];
    const float* bv    = (const float*)d_in[8];
    const float* Wp    = (const float*)d_in[9];
    const float* bp    = (const float*)d_in[10];
    float* out = (float*)d_out;

    static bool inited = false;
    static __nv_bfloat16 *p_hb, *p_qkv, *p_wb, *p_ab, *p_wtb, *p_wpb;
    static float *p_w, *p_bt;
    if (!inited) {
        cudaGetSymbolAddress((void**)&p_hb,  g_hb);
        cudaGetSymbolAddress((void**)&p_qkv, g_qkv);
        cudaGetSymbolAddress((void**)&p_w,   g_w);
        cudaGetSymbolAddress((void**)&p_wb,  g_wb);
        cudaGetSymbolAddress((void**)&p_ab,  g_ab);
        cudaGetSymbolAddress((void**)&p_wtb, g_wtb);
        cudaGetSymbolAddress((void**)&p_wpb, g_wpb);
        cudaGetSymbolAddress((void**)&p_bt,  g_bt);
        cudaFuncSetAttribute(gemm_ca<1, 0, 1>, cudaFuncAttributeMaxDynamicSharedMemorySize, SMEM_DYN);
        cudaFuncSetAttribute(gemm_ca<0, 0, 0>, cudaFuncAttributeMaxDynamicSharedMemorySize, SMEM_DYN);
        cudaFuncSetAttribute(gemm_ca<0, 1, 1>, cudaFuncAttributeMaxDynamicSharedMemorySize, SMEM_DYN);
        inited = true;
    }

    const size_t sBCT = (size_t)C_ * T_;
    const size_t sQKV = (size_t)T_ * 3 * C_;
    const size_t sBTT = (size_t)T_ * T_;
    const size_t sBTC = (size_t)T_ * C_;

    // 1) GroupNorm -> bf16 h [B,C,T]
    groupnorm_kernel<<<B_ * G_, 256>>>(x, gamma, beta, p_hb);

    // 2) Pack all weights to bf16
    pack_w_kernel<<<(4 * C_ * C_ / 4) / 256, 256>>>(Wq, bq, Wk, bk, Wv, bv, Wp,
                                                    p_wtb, p_wpb, p_bt);

    // 3) QKV: qkv[b,t,o] = sum_c h[b,c,t]*Wt[o,c] + bt[o]
    {
        dim3 grid((3 * C_) / 128, T_ / 128, B_);
        gemm_ca<1, 0, 1><<<grid, 256, SMEM_DYN>>>(3 * C_, C_,
            p_hb, sBCT, T_,  p_wtb, 0, C_,
            p_qkv, sQKV, p_bt, 1, nullptr, 0);
    }

    // 4) Scores: w = q.k^T (scale folded), out fp32.
    {
        dim3 grid(T_ / 128, T_ / 128, B_);
        gemm_ca<0, 0, 0><<<grid, 256, SMEM_DYN>>>(T_, C_,
            p_qkv, sQKV, 3 * C_,  p_qkv + C_, sQKV, 3 * C_,
            p_w, sBTT, nullptr, 0, nullptr, 0);
    }

    // 5) Softmax fp32 -> bf16
    softmax_kernel<<<B_ * T_, 256>>>(p_w, p_wb);

    // 6) Apply: a[b,t,c] = sum_s wb[b,t,s]*v[b,s,c]
    {
        dim3 grid(C_ / 128, T_ / 128, B_);
        gemm_ca<0, 1, 1><<<grid, 256, SMEM_DYN>>>(C_, T_,
            p_wb, sBTT, T_,  p_qkv + 2 * C_, sQKV, 3 * C_,
            p_ab, sBTC, nullptr, 0, nullptr, 0);
    }

    // 7) Proj + residual
    {
        dim3 grid(T_ / 128, C_ / 128, B_);
        gemm_ca<0, 0, 0><<<grid, 256, SMEM_DYN>>>(T_, C_,
            p_wpb, 0, C_,  p_ab, sBTC, C_,
            out, sBCT, bp, 0, x, sBCT);
    }
}

// round 7
// speedup vs baseline: 8.5450x; 1.0129x over previous
#include <cuda_runtime.h>
#include <cuda_bf16.h>
#include <cstdint>

#define B_   16
#define C_   512
#define T_   1024
#define G_   32
#define CPG  (C_ / G_)
#define EPS  1e-5f
#define QSCALE 0.04419417382415922f   // C^-1/2

// ---------------------------------------------------------------------------
// Scratch (static __device__ — no allocation allowed)
// ---------------------------------------------------------------------------
__device__ __nv_bfloat16 g_hb [(size_t)B_ * C_ * T_];        // GN out [B,C,T]
__device__ __nv_bfloat16 g_qkv[(size_t)B_ * T_ * 3 * C_];    // [B,T,1536]
__device__ float         g_w  [(size_t)B_ * T_ * T_];        // scores fp32
__device__ __nv_bfloat16 g_wb [(size_t)B_ * T_ * T_];        // softmax out bf16
__device__ __nv_bfloat16 g_ab [(size_t)B_ * T_ * C_];        // attn out [B,T,C]
__device__ __nv_bfloat16 g_wtb[(size_t)3 * C_ * C_];         // qkv weights [3C][C]
__device__ __nv_bfloat16 g_wpb[(size_t)C_ * C_];             // proj weight [C][C]
__device__ float         g_bt [3 * C_];

__device__ __forceinline__ uint32_t pk2(float a, float b) {
    __nv_bfloat162 t = __floats2bfloat162_rn(a, b);
    return *reinterpret_cast<uint32_t*>(&t);
}

// ---------------------------------------------------------------------------
// GroupNorm: fp32 in, bf16 out.
// ---------------------------------------------------------------------------
__global__ __launch_bounds__(256) void groupnorm_kernel(
    const float* __restrict__ x,
    const float* __restrict__ gamma,
    const float* __restrict__ beta,
    __nv_bfloat16* __restrict__ h)
{
    const int b = blockIdx.x >> 5;
    const int g = blockIdx.x & 31;
    const size_t base = ((size_t)b * C_ + (size_t)g * CPG) * T_;
    const float4* xp = (const float4*)(x + base);
    const int N4 = CPG * T_ / 4;
    const int tid = threadIdx.x;

    float s = 0.f, s2 = 0.f;
    for (int i = tid; i < N4; i += 256) {
        float4 v = xp[i];
        s  += v.x + v.y + v.z + v.w;
        s2 += v.x * v.x + v.y * v.y + v.z * v.z + v.w * v.w;
    }
    #pragma unroll
    for (int o = 16; o > 0; o >>= 1) {
        s  += __shfl_xor_sync(0xffffffffu, s, o);
        s2 += __shfl_xor_sync(0xffffffffu, s2, o);
    }
    __shared__ float sh1[8], sh2[8];
    const int wid = tid >> 5, lane = tid & 31;
    if (lane == 0) { sh1[wid] = s; sh2[wid] = s2; }
    __syncthreads();
    if (tid == 0) {
        float a = 0.f, bb = 0.f;
        #pragma unroll
        for (int i = 0; i < 8; i++) { a += sh1[i]; bb += sh2[i]; }
        sh1[0] = a; sh2[0] = bb;
    }
    __syncthreads();
    const float inv_n = 1.0f / (float)(CPG * T_);
    const float mean = sh1[0] * inv_n;
    const float var  = sh2[0] * inv_n - mean * mean;
    const float inv  = rsqrtf(var + EPS);

    for (int i = tid; i < N4; i += 256) {
        const int c = g * CPG + (i >> 8);
        const float ga = gamma[c] * inv;
        const float be = beta[c];
        float4 v = xp[i];
        uint2 o;
        o.x = pk2((v.x - mean) * ga + be, (v.y - mean) * ga + be);
        o.y = pk2((v.z - mean) * ga + be, (v.w - mean) * ga + be);
        *(uint2*)(h + base + (size_t)i * 4) = o;
    }
}

// ---------------------------------------------------------------------------
// Pack all weights to bf16: Wq(scaled)|Wk|Wv -> g_wtb, Wp -> g_wpb.
// ---------------------------------------------------------------------------
__global__ __launch_bounds__(256) void pack_w_kernel(
    const float* __restrict__ Wq, const float* __restrict__ bq,
    const float* __restrict__ Wk, const float* __restrict__ bk,
    const float* __restrict__ Wv, const float* __restrict__ bv,
    const float* __restrict__ Wp,
    __nv_bfloat16* __restrict__ Wt, __nv_bfloat16* __restrict__ Wpb,
    float* __restrict__ bt)
{
    const int idx = blockIdx.x * 256 + threadIdx.x;   // float4 idx, 2048*128
    const int o  = idx >> 7;
    const int c4 = idx & 127;
    const float* src; float s = 1.f; __nv_bfloat16* dst;
    if (o < C_)          { src = Wq + (size_t)o * C_; s = QSCALE; dst = Wt + (size_t)o * C_; }
    else if (o < 2 * C_) { src = Wk + (size_t)(o - C_) * C_;      dst = Wt + (size_t)o * C_; }
    else if (o < 3 * C_) { src = Wv + (size_t)(o - 2 * C_) * C_;  dst = Wt + (size_t)o * C_; }
    else                 { src = Wp + (size_t)(o - 3 * C_) * C_;  dst = Wpb + (size_t)(o - 3 * C_) * C_; }
    float4 v = *(const float4*)(src + c4 * 4);
    uint2 p; p.x = pk2(v.x * s, v.y * s); p.y = pk2(v.z * s, v.w * s);
    *(uint2*)(dst + c4 * 4) = p;
    if (idx < 3 * C_) {
        bt[idx] = (idx < C_) ? bq[idx] * QSCALE
                : (idx < 2 * C_) ? bk[idx - C_] : bv[idx - 2 * C_];
    }
}

// ---------------------------------------------------------------------------
// bf16 GEMM, cp.async 4-stage pipeline, ONE barrier per k-iteration,
// fragment-level software pipelining (both kk fragment sets loaded before
// the MMA slab — LDSM latency exposed once per iteration).
// Block 128x128, BK=32, 256 thr, 8 warps (2x4), warp tile 64x32, m16n8k16.
// AT/BT: 0 = [row][k] k-contig, 1 = [k][row] row-contig (trans ldmatrix).
// OUTBF: 1 = bf16 output, 0 = fp32 output.
// ---------------------------------------------------------------------------
__device__ __forceinline__ void ldsm4(uint32_t* r, uint32_t a) {
    asm volatile("ldmatrix.sync.aligned.m8n8.x4.shared.b16 {%0,%1,%2,%3}, [%4];"
                 : "=r"(r[0]), "=r"(r[1]), "=r"(r[2]), "=r"(r[3]) : "r"(a));
}
__device__ __forceinline__ void ldsm4t(uint32_t* r, uint32_t a) {
    asm volatile("ldmatrix.sync.aligned.m8n8.x4.trans.shared.b16 {%0,%1,%2,%3}, [%4];"
                 : "=r"(r[0]), "=r"(r[1]), "=r"(r[2]), "=r"(r[3]) : "r"(a));
}
__device__ __forceinline__ void mma16(float* c, const uint32_t* a, const uint32_t* b) {
    asm volatile("mma.sync.aligned.m16n8k16.row.col.f32.bf16.bf16.f32 "
                 "{%0,%1,%2,%3},{%4,%5,%6,%7},{%8,%9},{%0,%1,%2,%3};"
                 : "+f"(c[0]), "+f"(c[1]), "+f"(c[2]), "+f"(c[3])
                 : "r"(a[0]), "r"(a[1]), "r"(a[2]), "r"(a[3]), "r"(b[0]), "r"(b[1]));
}
__device__ __forceinline__ void cpa16(uint32_t dst, const void* src) {
    asm volatile("cp.async.cg.shared.global [%0], [%1], 16;" :: "r"(dst), "l"(src));
}
#define CP_COMMIT() asm volatile("cp.async.commit_group;")
#define CP_WAIT2()  asm volatile("cp.async.wait_group 2;")

#define ABUF_OFF 0
#define BBUF_OFF 10240
#define BUFSTEP  20480
#define STAGES   4
#define SMEM_DYN (STAGES * BUFSTEP)

template<int AT, int BT, int OUTBF>
__global__ __launch_bounds__(256, 2) void gemm_ca(
    int N, int K,
    const __nv_bfloat16* __restrict__ A, size_t Abs, int lda,
    const __nv_bfloat16* __restrict__ Bp, size_t Bbs, int ldb,
    void* __restrict__ Cvp, size_t Cbs,
    const float* __restrict__ bias, int bias_on_n,
    const float* __restrict__ resid, size_t Rbs)
{
    const int bz = blockIdx.z;
    A  += (size_t)bz * Abs;
    Bp += (size_t)bz * Bbs;
    if (resid) resid += (size_t)bz * Rbs;

    extern __shared__ __align__(16) unsigned char sm[];
    const uint32_t sb = (uint32_t)__cvta_generic_to_shared(sm);

    const int tid = threadIdx.x;
    const int m0 = blockIdx.y * 128;
    const int n0 = blockIdx.x * 128;
    const int warp = tid >> 5, lane = tid & 31;
    const int wm = warp >> 2, wn = warp & 3;
    const int gid = lane >> 2, tig = lane & 3;

    float acc[4][4][4];
    #pragma unroll
    for (int i = 0; i < 4; i++)
        #pragma unroll
        for (int j = 0; j < 4; j++)
            #pragma unroll
            for (int r = 0; r < 4; r++) acc[i][j][r] = 0.f;

    // --- per-thread cp.async source pointers ---
    const __nv_bfloat16 *aS0, *aS1, *bS0, *bS1;
    uint32_t aD0, aD1, bD0, bD1;
    size_t aStep, bStep;
    {
        int i0 = tid, i1 = tid + 256;
        if (AT == 0) {
            aS0 = A + (size_t)(m0 + (i0 >> 2)) * lda + (i0 & 3) * 8;
            aS1 = A + (size_t)(m0 + (i1 >> 2)) * lda + (i1 & 3) * 8;
            aD0 = ABUF_OFF + (i0 >> 2) * 80 + (i0 & 3) * 16;
            aD1 = ABUF_OFF + (i1 >> 2) * 80 + (i1 & 3) * 16;
            aStep = 32;
        } else {
            aS0 = A + (size_t)(i0 >> 4) * lda + m0 + (i0 & 15) * 8;
            aS1 = A + (size_t)(i1 >> 4) * lda + m0 + (i1 & 15) * 8;
            aD0 = ABUF_OFF + (i0 >> 4) * 272 + (i0 & 15) * 16;
            aD1 = ABUF_OFF + (i1 >> 4) * 272 + (i1 & 15) * 16;
            aStep = (size_t)32 * lda;
        }
        if (BT == 0) {
            bS0 = Bp + (size_t)(n0 + (i0 >> 2)) * ldb + (i0 & 3) * 8;
            bS1 = Bp + (size_t)(n0 + (i1 >> 2)) * ldb + (i1 & 3) * 8;
            bD0 = BBUF_OFF + (i0 >> 2) * 80 + (i0 & 3) * 16;
            bD1 = BBUF_OFF + (i1 >> 2) * 80 + (i1 & 3) * 16;
            bStep = 32;
        } else {
            bS0 = Bp + (size_t)(i0 >> 4) * ldb + n0 + (i0 & 15) * 8;
            bS1 = Bp + (size_t)(i1 >> 4) * ldb + n0 + (i1 & 15) * 8;
            bD0 = BBUF_OFF + (i0 >> 4) * 272 + (i0 & 15) * 16;
            bD1 = BBUF_OFF + (i1 >> 4) * 272 + (i1 & 15) * 16;
            bStep = (size_t)32 * ldb;
        }
    }
    auto issueBuf = [&](uint32_t bufb) {
        cpa16(bufb + aD0, aS0); cpa16(bufb + aD1, aS1);
        cpa16(bufb + bD0, bS0); cpa16(bufb + bD1, bS1);
        aS0 += aStep; aS1 += aStep; bS0 += bStep; bS1 += bStep;
    };

    // ldmatrix base addresses (buffer 0)
    const uint32_t aBase = (AT == 0)
        ? sb + ABUF_OFF + (uint32_t)(wm * 64 + (lane & 15)) * 80 + ((lane >> 4) & 1) * 16
        : sb + ABUF_OFF + (uint32_t)(((lane >> 4) & 1) * 8 + (lane & 7)) * 272
                        + (uint32_t)(wm * 64 + ((lane >> 3) & 1) * 8) * 2;
    const uint32_t bBase = (BT == 0)
        ? sb + BBUF_OFF + (uint32_t)(wn * 32 + ((lane >> 4) & 1) * 8 + (lane & 7)) * 80
                        + ((lane >> 3) & 1) * 16
        : sb + BBUF_OFF + (uint32_t)(((lane >> 3) & 1) * 8 + (lane & 7)) * 272
                        + (uint32_t)(wn * 32 + ((lane >> 4) & 1) * 8) * 2;

    const int nIter = K >> 5;     // multiple of 4 for all our shapes
    issueBuf(sb + 0 * BUFSTEP); CP_COMMIT();
    issueBuf(sb + 1 * BUFSTEP); CP_COMMIT();
    issueBuf(sb + 2 * BUFSTEP); CP_COMMIT();

    for (int itb = 0; itb < nIter; itb += 4) {
        #pragma unroll
        for (int u = 0; u < 4; u++) {
            const int it = itb + u;
            CP_WAIT2();
            __syncthreads();

            const uint32_t aB = aBase + u * BUFSTEP;
            const uint32_t bB = bBase + u * BUFSTEP;

            // ---- load ALL fragments for both kk halves up front ----
            uint32_t af[2][4][4], bfr[2][2][4];
            #pragma unroll
            for (int mi = 0; mi < 4; mi++) {
                const uint32_t ad = (AT == 0) ? aB + mi * 1280 : aB + mi * 32;
                if (AT == 0) ldsm4(af[0][mi], ad); else ldsm4t(af[0][mi], ad);
            }
            #pragma unroll
            for (int np = 0; np < 2; np++) {
                const uint32_t bd = (BT == 0) ? bB + np * 1280 : bB + np * 32;
                if (BT == 0) ldsm4(bfr[0][np], bd); else ldsm4t(bfr[0][np], bd);
            }
            // refill cp.async for stage it+3 while kk=0 LDSMs are in flight
            // (buffer (it+3)&3 == (u+3)&3; safe — barrier above proved the MMA
            //  slab of iteration it-1 on that buffer is complete in all warps)
            if (it + 3 < nIter) issueBuf(sb + ((u + 3) & 3) * BUFSTEP);
            CP_COMMIT();
            #pragma unroll
            for (int mi = 0; mi < 4; mi++) {
                const uint32_t ad = (AT == 0) ? aB + mi * 1280 + 32
                                              : aB + 4352 + mi * 32;
                if (AT == 0) ldsm4(af[1][mi], ad); else ldsm4t(af[1][mi], ad);
            }
            #pragma unroll
            for (int np = 0; np < 2; np++) {
                const uint32_t bd = (BT == 0) ? bB + np * 1280 + 32
                                              : bB + 4352 + np * 32;
                if (BT == 0) ldsm4(bfr[1][np], bd); else ldsm4t(bfr[1][np], bd);
            }

            // ---- 64 MMAs back-to-back ----
            #pragma unroll
            for (int kk = 0; kk < 2; kk++)
                #pragma unroll
                for (int mi = 0; mi < 4; mi++)
                    #pragma unroll
                    for (int nj = 0; nj < 4; nj++)
                        mma16(acc[mi][nj], af[kk][mi], &bfr[kk][nj >> 1][(nj & 1) * 2]);
            // no trailing barrier — next iteration's top barrier orders reuse
        }
    }

    // epilogue
    #pragma unroll
    for (int mi = 0; mi < 4; mi++) {
        #pragma unroll
        for (int nj = 0; nj < 4; nj++) {
            const int cc = n0 + wn * 32 + nj * 8 + tig * 2;
            float bn0 = 0.f, bn1 = 0.f;
            if (bias && bias_on_n) { bn0 = bias[cc]; bn1 = bias[cc + 1]; }
            #pragma unroll
            for (int hh = 0; hh < 2; hh++) {
                const int row = m0 + wm * 64 + mi * 16 + gid + hh * 8;
                float v0 = acc[mi][nj][hh * 2 + 0];
                float v1 = acc[mi][nj][hh * 2 + 1];
                if (bias) {
                    if (bias_on_n) { v0 += bn0; v1 += bn1; }
                    else { const float bm = bias[row]; v0 += bm; v1 += bm; }
                }
                if (resid) {
                    const float2 rr = *(const float2*)&resid[(size_t)row * N + cc];
                    v0 += rr.x; v1 += rr.y;
                }
                if (OUTBF) {
                    __nv_bfloat16* Cb = (__nv_bfloat16*)Cvp + (size_t)bz * Cbs;
                    *(uint32_t*)&Cb[(size_t)row * N + cc] = pk2(v0, v1);
                } else {
                    float* Cf = (float*)Cvp + (size_t)bz * Cbs;
                    float2 o; o.x = v0; o.y = v1;
                    *(float2*)&Cf[(size_t)row * N + cc] = o;
                }
            }
        }
    }
}

// ---------------------------------------------------------------------------
// Softmax: fp32 in -> bf16 out. One block per row.
// ---------------------------------------------------------------------------
__global__ __launch_bounds__(256) void softmax_kernel(
    const float* __restrict__ win, __nv_bfloat16* __restrict__ wout)
{
    const float4* p = (const float4*)(win + (size_t)blockIdx.x * T_);
    const int tid = threadIdx.x;
    float4 v = p[tid];

    float mx = fmaxf(fmaxf(v.x, v.y), fmaxf(v.z, v.w));
    #pragma unroll
    for (int o = 16; o > 0; o >>= 1)
        mx = fmaxf(mx, __shfl_xor_sync(0xffffffffu, mx, o));
    __shared__ float sh[8];
    const int wid = tid >> 5, lane = tid & 31;
    if (lane == 0) sh[wid] = mx;
    __syncthreads();
    if (tid == 0) {
        float m = sh[0];
        #pragma unroll
        for (int i = 1; i < 8; i++) m = fmaxf(m, sh[i]);
        sh[0] = m;
    }
    __syncthreads();
    mx = sh[0];
    __syncthreads();

    v.x = __expf(v.x - mx);
    v.y = __expf(v.y - mx);
    v.z = __expf(v.z - mx);
    v.w = __expf(v.w - mx);
    float s = v.x + v.y + v.z + v.w;
    #pragma unroll
    for (int o = 16; o > 0; o >>= 1)
        s += __shfl_xor_sync(0xffffffffu, s, o);
    if (lane == 0) sh[wid] = s;
    __syncthreads();
    if (tid == 0) {
        float a = 0.f;
        #pragma unroll
        for (int i = 0; i < 8; i++) a += sh[i];
        sh[0] = a;
    }
    __syncthreads();
    const float inv = 1.0f / sh[0];

    uint2 o;
    o.x = pk2(v.x * inv, v.y * inv);
    o.y = pk2(v.z * inv, v.w * inv);
    *(uint2*)(wout + (size_t)blockIdx.x * T_ + tid * 4) = o;
}

// ---------------------------------------------------------------------------
// Launch
// ---------------------------------------------------------------------------
extern "C" void kernel_launch(void* const* d_in, const int* in_sizes, int n_in,
                              void* d_out, int out_size)
{
    const float* x     = (const float*)d_in[0];
    const float* gamma = (const float*)d_in[1];
    const float* beta  = (const float*)d_in[2];
    const float* Wq    = (const float*)d_in[3];
    const float* bq    = (const float*)d_in[4];
    const float* Wk    = (const float*)d_in[5];
    const float* bk    = (const float*)d_in[6];
    const float* Wv    = (const float*)d_in[7];
    const float* bv    = (const float*)d_in[8];
    const float* Wp    = (const float*)d_in[9];
    const float* bp    = (const float*)d_in[10];
    float* out = (float*)d_out;

    static bool inited = false;
    static __nv_bfloat16 *p_hb, *p_qkv, *p_wb, *p_ab, *p_wtb, *p_wpb;
    static float *p_w, *p_bt;
    if (!inited) {
        cudaGetSymbolAddress((void**)&p_hb,  g_hb);
        cudaGetSymbolAddress((void**)&p_qkv, g_qkv);
        cudaGetSymbolAddress((void**)&p_w,   g_w);
        cudaGetSymbolAddress((void**)&p_wb,  g_wb);
        cudaGetSymbolAddress((void**)&p_ab,  g_ab);
        cudaGetSymbolAddress((void**)&p_wtb, g_wtb);
        cudaGetSymbolAddress((void**)&p_wpb, g_wpb);
        cudaGetSymbolAddress((void**)&p_bt,  g_bt);
        cudaFuncSetAttribute(gemm_ca<1, 0, 1>, cudaFuncAttributeMaxDynamicSharedMemorySize, SMEM_DYN);
        cudaFuncSetAttribute(gemm_ca<0, 0, 0>, cudaFuncAttributeMaxDynamicSharedMemorySize, SMEM_DYN);
        cudaFuncSetAttribute(gemm_ca<0, 1, 1>, cudaFuncAttributeMaxDynamicSharedMemorySize, SMEM_DYN);
        inited = true;
    }

    const size_t sBCT = (size_t)C_ * T_;
    const size_t sQKV = (size_t)T_ * 3 * C_;
    const size_t sBTT = (size_t)T_ * T_;
    const size_t sBTC = (size_t)T_ * C_;

    // 1) GroupNorm -> bf16 h [B,C,T]
    groupnorm_kernel<<<B_ * G_, 256>>>(x, gamma, beta, p_hb);

    // 2) Pack all weights to bf16
    pack_w_kernel<<<(4 * C_ * C_ / 4) / 256, 256>>>(Wq, bq, Wk, bk, Wv, bv, Wp,
                                                    p_wtb, p_wpb, p_bt);

    // 3) QKV: qkv[b,t,o] = sum_c h[b,c,t]*Wt[o,c] + bt[o]
    {
        dim3 grid((3 * C_) / 128, T_ / 128, B_);
        gemm_ca<1, 0, 1><<<grid, 256, SMEM_DYN>>>(3 * C_, C_,
            p_hb, sBCT, T_,  p_wtb, 0, C_,
            p_qkv, sQKV, p_bt, 1, nullptr, 0);
    }

    // 4) Scores: w = q.k^T (scale folded), out fp32.
    {
        dim3 grid(T_ / 128, T_ / 128, B_);
        gemm_ca<0, 0, 0><<<grid, 256, SMEM_DYN>>>(T_, C_,
            p_qkv, sQKV, 3 * C_,  p_qkv + C_, sQKV, 3 * C_,
            p_w, sBTT, nullptr, 0, nullptr, 0);
    }

    // 5) Softmax fp32 -> bf16
    softmax_kernel<<<B_ * T_, 256>>>(p_w, p_wb);

    // 6) Apply: a[b,t,c] = sum_s wb[b,t,s]*v[b,s,c]
    {
        dim3 grid(C_ / 128, T_ / 128, B_);
        gemm_ca<0, 1, 1><<<grid, 256, SMEM_DYN>>>(C_, T_,
            p_wb, sBTT, T_,  p_qkv + 2 * C_, sQKV, 3 * C_,
            p_ab, sBTC, nullptr, 0, nullptr, 0);
    }

    // 7) Proj + residual
    {
        dim3 grid(T_ / 128, C_ / 128, B_);
        gemm_ca<0, 0, 0><<<grid, 256, SMEM_DYN>>>(T_, C_,
            p_wpb, 0, C_,  p_ab, sBTC, C_,
            out, sBCT, bp, 0, x, sBCT);
    }
}

// round 8
// speedup vs baseline: 8.7816x; 1.0277x over previous
#include <cuda_runtime.h>
#include <cuda_bf16.h>
#include <cstdint>

#define B_   16
#define C_   512
#define T_   1024
#define G_   32
#define CPG  (C_ / G_)
#define EPS  1e-5f
#define QSCALE 0.04419417382415922f   // C^-1/2

// ---------------------------------------------------------------------------
// Scratch (static __device__ — no allocation allowed)
// ---------------------------------------------------------------------------
__device__ __nv_bfloat16 g_hb [(size_t)B_ * C_ * T_];        // GN out [B,C,T]
__device__ __nv_bfloat16 g_qkv[(size_t)B_ * T_ * 3 * C_];    // [B,T,1536]
__device__ float         g_w  [(size_t)B_ * T_ * T_];        // scores fp32
__device__ __nv_bfloat16 g_wb [(size_t)B_ * T_ * T_];        // softmax out bf16
__device__ __nv_bfloat16 g_ab [(size_t)B_ * T_ * C_];        // attn out [B,T,C]
__device__ __nv_bfloat16 g_wtb[(size_t)3 * C_ * C_];         // qkv weights [3C][C]
__device__ __nv_bfloat16 g_wpb[(size_t)C_ * C_];             // proj weight [C][C]
__device__ float         g_bt [3 * C_];

__device__ __forceinline__ uint32_t pk2(float a, float b) {
    __nv_bfloat162 t = __floats2bfloat162_rn(a, b);
    return *reinterpret_cast<uint32_t*>(&t);
}

// ---------------------------------------------------------------------------
// GroupNorm: fp32 in, bf16 out.
// ---------------------------------------------------------------------------
__global__ __launch_bounds__(256) void groupnorm_kernel(
    const float* __restrict__ x,
    const float* __restrict__ gamma,
    const float* __restrict__ beta,
    __nv_bfloat16* __restrict__ h)
{
    const int b = blockIdx.x >> 5;
    const int g = blockIdx.x & 31;
    const size_t base = ((size_t)b * C_ + (size_t)g * CPG) * T_;
    const float4* xp = (const float4*)(x + base);
    const int N4 = CPG * T_ / 4;
    const int tid = threadIdx.x;

    float s = 0.f, s2 = 0.f;
    for (int i = tid; i < N4; i += 256) {
        float4 v = xp[i];
        s  += v.x + v.y + v.z + v.w;
        s2 += v.x * v.x + v.y * v.y + v.z * v.z + v.w * v.w;
    }
    #pragma unroll
    for (int o = 16; o > 0; o >>= 1) {
        s  += __shfl_xor_sync(0xffffffffu, s, o);
        s2 += __shfl_xor_sync(0xffffffffu, s2, o);
    }
    __shared__ float sh1[8], sh2[8];
    const int wid = tid >> 5, lane = tid & 31;
    if (lane == 0) { sh1[wid] = s; sh2[wid] = s2; }
    __syncthreads();
    if (tid == 0) {
        float a = 0.f, bb = 0.f;
        #pragma unroll
        for (int i = 0; i < 8; i++) { a += sh1[i]; bb += sh2[i]; }
        sh1[0] = a; sh2[0] = bb;
    }
    __syncthreads();
    const float inv_n = 1.0f / (float)(CPG * T_);
    const float mean = sh1[0] * inv_n;
    const float var  = sh2[0] * inv_n - mean * mean;
    const float inv  = rsqrtf(var + EPS);

    for (int i = tid; i < N4; i += 256) {
        const int c = g * CPG + (i >> 8);
        const float ga = gamma[c] * inv;
        const float be = beta[c];
        float4 v = xp[i];
        uint2 o;
        o.x = pk2((v.x - mean) * ga + be, (v.y - mean) * ga + be);
        o.y = pk2((v.z - mean) * ga + be, (v.w - mean) * ga + be);
        *(uint2*)(h + base + (size_t)i * 4) = o;
    }
}

// ---------------------------------------------------------------------------
// Pack all weights to bf16: Wq(scaled)|Wk|Wv -> g_wtb, Wp -> g_wpb.
// ---------------------------------------------------------------------------
__global__ __launch_bounds__(256) void pack_w_kernel(
    const float* __restrict__ Wq, const float* __restrict__ bq,
    const float* __restrict__ Wk, const float* __restrict__ bk,
    const float* __restrict__ Wv, const float* __restrict__ bv,
    const float* __restrict__ Wp,
    __nv_bfloat16* __restrict__ Wt, __nv_bfloat16* __restrict__ Wpb,
    float* __restrict__ bt)
{
    const int idx = blockIdx.x * 256 + threadIdx.x;   // float4 idx, 2048*128
    const int o  = idx >> 7;
    const int c4 = idx & 127;
    const float* src; float s = 1.f; __nv_bfloat16* dst;
    if (o < C_)          { src = Wq + (size_t)o * C_; s = QSCALE; dst = Wt + (size_t)o * C_; }
    else if (o < 2 * C_) { src = Wk + (size_t)(o - C_) * C_;      dst = Wt + (size_t)o * C_; }
    else if (o < 3 * C_) { src = Wv + (size_t)(o - 2 * C_) * C_;  dst = Wt + (size_t)o * C_; }
    else                 { src = Wp + (size_t)(o - 3 * C_) * C_;  dst = Wpb + (size_t)(o - 3 * C_) * C_; }
    float4 v = *(const float4*)(src + c4 * 4);
    uint2 p; p.x = pk2(v.x * s, v.y * s); p.y = pk2(v.z * s, v.w * s);
    *(uint2*)(dst + c4 * 4) = p;
    if (idx < 3 * C_) {
        bt[idx] = (idx < C_) ? bq[idx] * QSCALE
                : (idx < 2 * C_) ? bk[idx - C_] : bv[idx - 2 * C_];
    }
}

// ---------------------------------------------------------------------------
// bf16 GEMM, cp.async 4-stage pipeline. Block tile 128x128, BK=32,
// 128 threads / 4 warps (2x2), warp tile 64x64 — 1.5x less LDSM traffic
// per MAC; 2 CTAs/SM with independent barriers stagger smem/tensor phases.
// AT/BT: 0 = [row][k] k-contig, 1 = [k][row] row-contig (trans ldmatrix).
// OUTBF: 1 = bf16 output, 0 = fp32 output.
// ---------------------------------------------------------------------------
__device__ __forceinline__ void ldsm4(uint32_t* r, uint32_t a) {
    asm volatile("ldmatrix.sync.aligned.m8n8.x4.shared.b16 {%0,%1,%2,%3}, [%4];"
                 : "=r"(r[0]), "=r"(r[1]), "=r"(r[2]), "=r"(r[3]) : "r"(a));
}
__device__ __forceinline__ void ldsm4t(uint32_t* r, uint32_t a) {
    asm volatile("ldmatrix.sync.aligned.m8n8.x4.trans.shared.b16 {%0,%1,%2,%3}, [%4];"
                 : "=r"(r[0]), "=r"(r[1]), "=r"(r[2]), "=r"(r[3]) : "r"(a));
}
__device__ __forceinline__ void mma16(float* c, const uint32_t* a, const uint32_t* b) {
    asm volatile("mma.sync.aligned.m16n8k16.row.col.f32.bf16.bf16.f32 "
                 "{%0,%1,%2,%3},{%4,%5,%6,%7},{%8,%9},{%0,%1,%2,%3};"
                 : "+f"(c[0]), "+f"(c[1]), "+f"(c[2]), "+f"(c[3])
                 : "r"(a[0]), "r"(a[1]), "r"(a[2]), "r"(a[3]), "r"(b[0]), "r"(b[1]));
}
__device__ __forceinline__ void cpa16(uint32_t dst, const void* src) {
    asm volatile("cp.async.cg.shared.global [%0], [%1], 16;" :: "r"(dst), "l"(src));
}
#define CP_COMMIT() asm volatile("cp.async.commit_group;")
#define CP_WAIT2()  asm volatile("cp.async.wait_group 2;")

#define ABUF_OFF 0
#define BBUF_OFF 10240
#define BUFSTEP  20480
#define STAGES   4
#define SMEM_DYN (STAGES * BUFSTEP)

template<int AT, int BT, int OUTBF>
__global__ __launch_bounds__(128, 2) void gemm_ca(
    int N, int K,
    const __nv_bfloat16* __restrict__ A, size_t Abs, int lda,
    const __nv_bfloat16* __restrict__ Bp, size_t Bbs, int ldb,
    void* __restrict__ Cvp, size_t Cbs,
    const float* __restrict__ bias, int bias_on_n,
    const float* __restrict__ resid, size_t Rbs)
{
    const int bz = blockIdx.z;
    A  += (size_t)bz * Abs;
    Bp += (size_t)bz * Bbs;
    if (resid) resid += (size_t)bz * Rbs;

    extern __shared__ __align__(16) unsigned char sm[];
    const uint32_t sb = (uint32_t)__cvta_generic_to_shared(sm);

    const int tid = threadIdx.x;
    const int m0 = blockIdx.y * 128;
    const int n0 = blockIdx.x * 128;
    const int warp = tid >> 5, lane = tid & 31;
    const int wm = warp >> 1, wn = warp & 1;     // 2x2 warp grid, 64x64 tiles
    const int gid = lane >> 2, tig = lane & 3;

    float acc[4][8][4];
    #pragma unroll
    for (int i = 0; i < 4; i++)
        #pragma unroll
        for (int j = 0; j < 8; j++)
            #pragma unroll
            for (int r = 0; r < 4; r++) acc[i][j][r] = 0.f;

    // --- cp.async: 128 threads, 4 passes each for A (8KB) and B (8KB) ---
    const __nv_bfloat16 *aS, *bS;
    uint32_t aD, bD;
    size_t aStep, bStep, aPassS, bPassS;
    uint32_t aPassD, bPassD;
    if (AT == 0) {
        aS = A + (size_t)(m0 + (tid >> 2)) * lda + (tid & 3) * 8;
        aD = ABUF_OFF + (tid >> 2) * 80 + (tid & 3) * 16;
        aPassS = (size_t)32 * lda; aPassD = 32 * 80;
        aStep = 32;
    } else {
        aS = A + (size_t)(tid >> 4) * lda + m0 + (tid & 15) * 8;
        aD = ABUF_OFF + (tid >> 4) * 272 + (tid & 15) * 16;
        aPassS = (size_t)8 * lda; aPassD = 8 * 272;
        aStep = (size_t)32 * lda;
    }
    if (BT == 0) {
        bS = Bp + (size_t)(n0 + (tid >> 2)) * ldb + (tid & 3) * 8;
        bD = BBUF_OFF + (tid >> 2) * 80 + (tid & 3) * 16;
        bPassS = (size_t)32 * ldb; bPassD = 32 * 80;
        bStep = 32;
    } else {
        bS = Bp + (size_t)(tid >> 4) * ldb + n0 + (tid & 15) * 8;
        bD = BBUF_OFF + (tid >> 4) * 272 + (tid & 15) * 16;
        bPassS = (size_t)8 * ldb; bPassD = 8 * 272;
        bStep = (size_t)32 * ldb;
    }
    auto issueBuf = [&](uint32_t bufb) {
        #pragma unroll
        for (int p = 0; p < 4; p++)
            cpa16(bufb + aD + p * aPassD, aS + p * aPassS);
        #pragma unroll
        for (int p = 0; p < 4; p++)
            cpa16(bufb + bD + p * bPassD, bS + p * bPassS);
        aS += aStep; bS += bStep;
    };

    // ldmatrix base addresses (buffer 0)
    const uint32_t aBase = (AT == 0)
        ? sb + ABUF_OFF + (uint32_t)(wm * 64 + (lane & 15)) * 80 + ((lane >> 4) & 1) * 16
        : sb + ABUF_OFF + (uint32_t)(((lane >> 4) & 1) * 8 + (lane & 7)) * 272
                        + (uint32_t)(wm * 64 + ((lane >> 3) & 1) * 8) * 2;
    const uint32_t bBase = (BT == 0)
        ? sb + BBUF_OFF + (uint32_t)(wn * 64 + ((lane >> 4) & 1) * 8 + (lane & 7)) * 80
                        + ((lane >> 3) & 1) * 16
        : sb + BBUF_OFF + (uint32_t)(((lane >> 3) & 1) * 8 + (lane & 7)) * 272
                        + (uint32_t)(wn * 64 + ((lane >> 4) & 1) * 8) * 2;

    const int nIter = K >> 5;     // multiple of 4 for all our shapes
    issueBuf(sb + 0 * BUFSTEP); CP_COMMIT();
    issueBuf(sb + 1 * BUFSTEP); CP_COMMIT();
    issueBuf(sb + 2 * BUFSTEP); CP_COMMIT();

    for (int itb = 0; itb < nIter; itb += 4) {
        #pragma unroll
        for (int u = 0; u < 4; u++) {
            const int it = itb + u;
            CP_WAIT2();
            __syncthreads();

            const uint32_t aB = aBase + u * BUFSTEP;
            const uint32_t bB = bBase + u * BUFSTEP;

            // ---- load all fragments (both kk halves) up front ----
            uint32_t af[2][4][4], bf[2][4][4];
            #pragma unroll
            for (int mi = 0; mi < 4; mi++) {
                const uint32_t ad = (AT == 0) ? aB + mi * 1280 : aB + mi * 32;
                if (AT == 0) ldsm4(af[0][mi], ad); else ldsm4t(af[0][mi], ad);
            }
            #pragma unroll
            for (int np = 0; np < 4; np++) {
                const uint32_t bd = (BT == 0) ? bB + np * 1280 : bB + np * 32;
                if (BT == 0) ldsm4(bf[0][np], bd); else ldsm4t(bf[0][np], bd);
            }
            // refill stage it+3 (buffer (u+3)&3) while kk=0 LDSMs in flight;
            // safe: barrier above proved MMAs of it-1 (same buffer) complete.
            if (it + 3 < nIter) issueBuf(sb + ((u + 3) & 3) * BUFSTEP);
            CP_COMMIT();
            #pragma unroll
            for (int mi = 0; mi < 4; mi++) {
                const uint32_t ad = (AT == 0) ? aB + mi * 1280 + 32
                                              : aB + 4352 + mi * 32;
                if (AT == 0) ldsm4(af[1][mi], ad); else ldsm4t(af[1][mi], ad);
            }
            #pragma unroll
            for (int np = 0; np < 4; np++) {
                const uint32_t bd = (BT == 0) ? bB + np * 1280 + 32
                                              : bB + 4352 + np * 32;
                if (BT == 0) ldsm4(bf[1][np], bd); else ldsm4t(bf[1][np], bd);
            }

            // ---- 128 MMAs back-to-back ----
            #pragma unroll
            for (int kk = 0; kk < 2; kk++)
                #pragma unroll
                for (int mi = 0; mi < 4; mi++)
                    #pragma unroll
                    for (int nj = 0; nj < 8; nj++)
                        mma16(acc[mi][nj], af[kk][mi], &bf[kk][nj >> 1][(nj & 1) * 2]);
        }
    }

    // epilogue
    #pragma unroll
    for (int mi = 0; mi < 4; mi++) {
        #pragma unroll
        for (int nj = 0; nj < 8; nj++) {
            const int cc = n0 + wn * 64 + nj * 8 + tig * 2;
            float bn0 = 0.f, bn1 = 0.f;
            if (bias && bias_on_n) { bn0 = bias[cc]; bn1 = bias[cc + 1]; }
            #pragma unroll
            for (int hh = 0; hh < 2; hh++) {
                const int row = m0 + wm * 64 + mi * 16 + gid + hh * 8;
                float v0 = acc[mi][nj][hh * 2 + 0];
                float v1 = acc[mi][nj][hh * 2 + 1];
                if (bias) {
                    if (bias_on_n) { v0 += bn0; v1 += bn1; }
                    else { const float bm = bias[row]; v0 += bm; v1 += bm; }
                }
                if (resid) {
                    const float2 rr = *(const float2*)&resid[(size_t)row * N + cc];
                    v0 += rr.x; v1 += rr.y;
                }
                if (OUTBF) {
                    __nv_bfloat16* Cb = (__nv_bfloat16*)Cvp + (size_t)bz * Cbs;
                    *(uint32_t*)&Cb[(size_t)row * N + cc] = pk2(v0, v1);
                } else {
                    float* Cf = (float*)Cvp + (size_t)bz * Cbs;
                    float2 o; o.x = v0; o.y = v1;
                    *(float2*)&Cf[(size_t)row * N + cc] = o;
                }
            }
        }
    }
}

// ---------------------------------------------------------------------------
// Softmax: fp32 in -> bf16 out. One block per row.
// ---------------------------------------------------------------------------
__global__ __launch_bounds__(256) void softmax_kernel(
    const float* __restrict__ win, __nv_bfloat16* __restrict__ wout)
{
    const float4* p = (const float4*)(win + (size_t)blockIdx.x * T_);
    const int tid = threadIdx.x;
    float4 v = p[tid];

    float mx = fmaxf(fmaxf(v.x, v.y), fmaxf(v.z, v.w));
    #pragma unroll
    for (int o = 16; o > 0; o >>= 1)
        mx = fmaxf(mx, __shfl_xor_sync(0xffffffffu, mx, o));
    __shared__ float sh[8];
    const int wid = tid >> 5, lane = tid & 31;
    if (lane == 0) sh[wid] = mx;
    __syncthreads();
    if (tid == 0) {
        float m = sh[0];
        #pragma unroll
        for (int i = 1; i < 8; i++) m = fmaxf(m, sh[i]);
        sh[0] = m;
    }
    __syncthreads();
    mx = sh[0];
    __syncthreads();

    v.x = __expf(v.x - mx);
    v.y = __expf(v.y - mx);
    v.z = __expf(v.z - mx);
    v.w = __expf(v.w - mx);
    float s = v.x + v.y + v.z + v.w;
    #pragma unroll
    for (int o = 16; o > 0; o >>= 1)
        s += __shfl_xor_sync(0xffffffffu, s, o);
    if (lane == 0) sh[wid] = s;
    __syncthreads();
    if (tid == 0) {
        float a = 0.f;
        #pragma unroll
        for (int i = 0; i < 8; i++) a += sh[i];
        sh[0] = a;
    }
    __syncthreads();
    const float inv = 1.0f / sh[0];

    uint2 o;
    o.x = pk2(v.x * inv, v.y * inv);
    o.y = pk2(v.z * inv, v.w * inv);
    *(uint2*)(wout + (size_t)blockIdx.x * T_ + tid * 4) = o;
}

// ---------------------------------------------------------------------------
// Launch
// ---------------------------------------------------------------------------
extern "C" void kernel_launch(void* const* d_in, const int* in_sizes, int n_in,
                              void* d_out, int out_size)
{
    const float* x     = (const float*)d_in[0];
    const float* gamma = (const float*)d_in[1];
    const float* beta  = (const float*)d_in[2];
    const float* Wq    = (const float*)d_in[3];
    const float* bq    = (const float*)d_in[4];
    const float* Wk    = (const float*)d_in[5];
    const float* bk    = (const float*)d_in[6];
    const float* Wv    = (const float*)d_in[7];
    const float* bv    = (const float*)d_in[8];
    const float* Wp    = (const float*)d_in[9];
    const float* bp    = (const float*)d_in[10];
    float* out = (float*)d_out;

    static bool inited = false;
    static __nv_bfloat16 *p_hb, *p_qkv, *p_wb, *p_ab, *p_wtb, *p_wpb;
    static float *p_w, *p_bt;
    if (!inited) {
        cudaGetSymbolAddress((void**)&p_hb,  g_hb);
        cudaGetSymbolAddress((void**)&p_qkv, g_qkv);
        cudaGetSymbolAddress((void**)&p_w,   g_w);
        cudaGetSymbolAddress((void**)&p_wb,  g_wb);
        cudaGetSymbolAddress((void**)&p_ab,  g_ab);
        cudaGetSymbolAddress((void**)&p_wtb, g_wtb);
        cudaGetSymbolAddress((void**)&p_wpb, g_wpb);
        cudaGetSymbolAddress((void**)&p_bt,  g_bt);
        cudaFuncSetAttribute(gemm_ca<1, 0, 1>, cudaFuncAttributeMaxDynamicSharedMemorySize, SMEM_DYN);
        cudaFuncSetAttribute(gemm_ca<0, 0, 0>, cudaFuncAttributeMaxDynamicSharedMemorySize, SMEM_DYN);
        cudaFuncSetAttribute(gemm_ca<0, 1, 1>, cudaFuncAttributeMaxDynamicSharedMemorySize, SMEM_DYN);
        inited = true;
    }

    const size_t sBCT = (size_t)C_ * T_;
    const size_t sQKV = (size_t)T_ * 3 * C_;
    const size_t sBTT = (size_t)T_ * T_;
    const size_t sBTC = (size_t)T_ * C_;

    // 1) GroupNorm -> bf16 h [B,C,T]
    groupnorm_kernel<<<B_ * G_, 256>>>(x, gamma, beta, p_hb);

    // 2) Pack all weights to bf16
    pack_w_kernel<<<(4 * C_ * C_ / 4) / 256, 256>>>(Wq, bq, Wk, bk, Wv, bv, Wp,
                                                    p_wtb, p_wpb, p_bt);

    // 3) QKV: qkv[b,t,o] = sum_c h[b,c,t]*Wt[o,c] + bt[o]
    {
        dim3 grid((3 * C_) / 128, T_ / 128, B_);
        gemm_ca<1, 0, 1><<<grid, 128, SMEM_DYN>>>(3 * C_, C_,
            p_hb, sBCT, T_,  p_wtb, 0, C_,
            p_qkv, sQKV, p_bt, 1, nullptr, 0);
    }

    // 4) Scores: w = q.k^T (scale folded), out fp32.
    {
        dim3 grid(T_ / 128, T_ / 128, B_);
        gemm_ca<0, 0, 0><<<grid, 128, SMEM_DYN>>>(T_, C_,
            p_qkv, sQKV, 3 * C_,  p_qkv + C_, sQKV, 3 * C_,
            p_w, sBTT, nullptr, 0, nullptr, 0);
    }

    // 5) Softmax fp32 -> bf16
    softmax_kernel<<<B_ * T_, 256>>>(p_w, p_wb);

    // 6) Apply: a[b,t,c] = sum_s wb[b,t,s]*v[b,s,c]
    {
        dim3 grid(C_ / 128, T_ / 128, B_);
        gemm_ca<0, 1, 1><<<grid, 128, SMEM_DYN>>>(C_, T_,
            p_wb, sBTT, T_,  p_qkv + 2 * C_, sQKV, 3 * C_,
            p_ab, sBTC, nullptr, 0, nullptr, 0);
    }

    // 7) Proj + residual
    {
        dim3 grid(T_ / 128, C_ / 128, B_);
        gemm_ca<0, 0, 0><<<grid, 128, SMEM_DYN>>>(T_, C_,
            p_wpb, 0, C_,  p_ab, sBTC, C_,
            out, sBCT, bp, 0, x, sBCT);
    }
}

// round 9
// speedup vs baseline: 9.2809x; 1.0569x over previous
#include <cuda_runtime.h>
#include <cuda_bf16.h>
#include <cstdint>

#define B_   16
#define C_   512
#define T_   1024
#define G_   32
#define CPG  (C_ / G_)
#define EPS  1e-5f
#define QSCALE 0.04419417382415922f   // C^-1/2

// ---------------------------------------------------------------------------
// Scratch (static __device__ — no allocation allowed)
// ---------------------------------------------------------------------------
__device__ __nv_bfloat16 g_hb [(size_t)B_ * C_ * T_];        // GN out [B,C,T]
__device__ __nv_bfloat16 g_qkv[(size_t)B_ * T_ * 3 * C_];    // [B,T,1536]
__device__ __nv_bfloat16 g_wb [(size_t)B_ * T_ * T_];        // exp(scores) bf16
__device__ float         g_rs [(size_t)B_ * T_];             // softmax row sums
__device__ __nv_bfloat16 g_ab [(size_t)B_ * T_ * C_];        // attn out [B,T,C]
__device__ __nv_bfloat16 g_wtb[(size_t)3 * C_ * C_];         // qkv weights [3C][C]
__device__ __nv_bfloat16 g_wpb[(size_t)C_ * C_];             // proj weight [C][C]
__device__ float         g_bt [3 * C_];

__device__ __forceinline__ uint32_t pk2(float a, float b) {
    __nv_bfloat162 t = __floats2bfloat162_rn(a, b);
    return *reinterpret_cast<uint32_t*>(&t);
}

// ---------------------------------------------------------------------------
// GroupNorm: fp32 in, bf16 out.
// ---------------------------------------------------------------------------
__global__ __launch_bounds__(256) void groupnorm_kernel(
    const float* __restrict__ x,
    const float* __restrict__ gamma,
    const float* __restrict__ beta,
    __nv_bfloat16* __restrict__ h)
{
    const int b = blockIdx.x >> 5;
    const int g = blockIdx.x & 31;
    const size_t base = ((size_t)b * C_ + (size_t)g * CPG) * T_;
    const float4* xp = (const float4*)(x + base);
    const int N4 = CPG * T_ / 4;
    const int tid = threadIdx.x;

    float s = 0.f, s2 = 0.f;
    for (int i = tid; i < N4; i += 256) {
        float4 v = xp[i];
        s  += v.x + v.y + v.z + v.w;
        s2 += v.x * v.x + v.y * v.y + v.z * v.z + v.w * v.w;
    }
    #pragma unroll
    for (int o = 16; o > 0; o >>= 1) {
        s  += __shfl_xor_sync(0xffffffffu, s, o);
        s2 += __shfl_xor_sync(0xffffffffu, s2, o);
    }
    __shared__ float sh1[8], sh2[8];
    const int wid = tid >> 5, lane = tid & 31;
    if (lane == 0) { sh1[wid] = s; sh2[wid] = s2; }
    __syncthreads();
    if (tid == 0) {
        float a = 0.f, bb = 0.f;
        #pragma unroll
        for (int i = 0; i < 8; i++) { a += sh1[i]; bb += sh2[i]; }
        sh1[0] = a; sh2[0] = bb;
    }
    __syncthreads();
    const float inv_n = 1.0f / (float)(CPG * T_);
    const float mean = sh1[0] * inv_n;
    const float var  = sh2[0] * inv_n - mean * mean;
    const float inv  = rsqrtf(var + EPS);

    for (int i = tid; i < N4; i += 256) {
        const int c = g * CPG + (i >> 8);
        const float ga = gamma[c] * inv;
        const float be = beta[c];
        float4 v = xp[i];
        uint2 o;
        o.x = pk2((v.x - mean) * ga + be, (v.y - mean) * ga + be);
        o.y = pk2((v.z - mean) * ga + be, (v.w - mean) * ga + be);
        *(uint2*)(h + base + (size_t)i * 4) = o;
    }
}

// ---------------------------------------------------------------------------
// Pack all weights to bf16: Wq(scaled)|Wk|Wv -> g_wtb, Wp -> g_wpb.
// ---------------------------------------------------------------------------
__global__ __launch_bounds__(256) void pack_w_kernel(
    const float* __restrict__ Wq, const float* __restrict__ bq,
    const float* __restrict__ Wk, const float* __restrict__ bk,
    const float* __restrict__ Wv, const float* __restrict__ bv,
    const float* __restrict__ Wp,
    __nv_bfloat16* __restrict__ Wt, __nv_bfloat16* __restrict__ Wpb,
    float* __restrict__ bt)
{
    const int idx = blockIdx.x * 256 + threadIdx.x;   // float4 idx, 2048*128
    const int o  = idx >> 7;
    const int c4 = idx & 127;
    const float* src; float s = 1.f; __nv_bfloat16* dst;
    if (o < C_)          { src = Wq + (size_t)o * C_; s = QSCALE; dst = Wt + (size_t)o * C_; }
    else if (o < 2 * C_) { src = Wk + (size_t)(o - C_) * C_;      dst = Wt + (size_t)o * C_; }
    else if (o < 3 * C_) { src = Wv + (size_t)(o - 2 * C_) * C_;  dst = Wt + (size_t)o * C_; }
    else                 { src = Wp + (size_t)(o - 3 * C_) * C_;  dst = Wpb + (size_t)(o - 3 * C_) * C_; }
    float4 v = *(const float4*)(src + c4 * 4);
    uint2 p; p.x = pk2(v.x * s, v.y * s); p.y = pk2(v.z * s, v.w * s);
    *(uint2*)(dst + c4 * 4) = p;
    if (idx < 3 * C_) {
        bt[idx] = (idx < C_) ? bq[idx] * QSCALE
                : (idx < 2 * C_) ? bk[idx - C_] : bv[idx - 2 * C_];
    }
}

// ---------------------------------------------------------------------------
// bf16 GEMM, cp.async 4-stage pipeline. Block tile 128x128, BK=32,
// 128 threads / 4 warps (2x2), warp tile 64x64. 2 CTAs/SM.
// AT/BT: 0 = [row][k] k-contig, 1 = [k][row] row-contig (trans ldmatrix).
// OUTBF: bf16 output.  EXPO: epilogue exp + row-sum atomics into rsum.
// NORM: epilogue multiplies by 1/rsum[row] (softmax normalization).
// ---------------------------------------------------------------------------
__device__ __forceinline__ void ldsm4(uint32_t* r, uint32_t a) {
    asm volatile("ldmatrix.sync.aligned.m8n8.x4.shared.b16 {%0,%1,%2,%3}, [%4];"
                 : "=r"(r[0]), "=r"(r[1]), "=r"(r[2]), "=r"(r[3]) : "r"(a));
}
__device__ __forceinline__ void ldsm4t(uint32_t* r, uint32_t a) {
    asm volatile("ldmatrix.sync.aligned.m8n8.x4.trans.shared.b16 {%0,%1,%2,%3}, [%4];"
                 : "=r"(r[0]), "=r"(r[1]), "=r"(r[2]), "=r"(r[3]) : "r"(a));
}
__device__ __forceinline__ void mma16(float* c, const uint32_t* a, const uint32_t* b) {
    asm volatile("mma.sync.aligned.m16n8k16.row.col.f32.bf16.bf16.f32 "
                 "{%0,%1,%2,%3},{%4,%5,%6,%7},{%8,%9},{%0,%1,%2,%3};"
                 : "+f"(c[0]), "+f"(c[1]), "+f"(c[2]), "+f"(c[3])
                 : "r"(a[0]), "r"(a[1]), "r"(a[2]), "r"(a[3]), "r"(b[0]), "r"(b[1]));
}
__device__ __forceinline__ void cpa16(uint32_t dst, const void* src) {
    asm volatile("cp.async.cg.shared.global [%0], [%1], 16;" :: "r"(dst), "l"(src));
}
#define CP_COMMIT() asm volatile("cp.async.commit_group;")
#define CP_WAIT2()  asm volatile("cp.async.wait_group 2;")

#define ABUF_OFF 0
#define BBUF_OFF 10240
#define BUFSTEP  20480
#define STAGES   4
#define SMEM_DYN (STAGES * BUFSTEP)

template<int AT, int BT, int OUTBF, int EXPO, int NORM>
__global__ __launch_bounds__(128, 2) void gemm_ca(
    int N, int K,
    const __nv_bfloat16* __restrict__ A, size_t Abs, int lda,
    const __nv_bfloat16* __restrict__ Bp, size_t Bbs, int ldb,
    void* __restrict__ Cvp, size_t Cbs,
    const float* __restrict__ bias, int bias_on_n,
    const float* __restrict__ resid, size_t Rbs,
    float* __restrict__ rsum)
{
    const int bz = blockIdx.z;
    A  += (size_t)bz * Abs;
    Bp += (size_t)bz * Bbs;
    if (resid) resid += (size_t)bz * Rbs;

    extern __shared__ __align__(16) unsigned char sm[];
    const uint32_t sb = (uint32_t)__cvta_generic_to_shared(sm);

    const int tid = threadIdx.x;
    const int m0 = blockIdx.y * 128;
    const int n0 = blockIdx.x * 128;
    const int warp = tid >> 5, lane = tid & 31;
    const int wm = warp >> 1, wn = warp & 1;     // 2x2 warp grid, 64x64 tiles
    const int gid = lane >> 2, tig = lane & 3;

    float acc[4][8][4];
    #pragma unroll
    for (int i = 0; i < 4; i++)
        #pragma unroll
        for (int j = 0; j < 8; j++)
            #pragma unroll
            for (int r = 0; r < 4; r++) acc[i][j][r] = 0.f;

    // --- cp.async: 128 threads, 4 passes each for A (8KB) and B (8KB) ---
    const __nv_bfloat16 *aS, *bS;
    uint32_t aD, bD;
    size_t aStep, bStep, aPassS, bPassS;
    uint32_t aPassD, bPassD;
    if (AT == 0) {
        aS = A + (size_t)(m0 + (tid >> 2)) * lda + (tid & 3) * 8;
        aD = ABUF_OFF + (tid >> 2) * 80 + (tid & 3) * 16;
        aPassS = (size_t)32 * lda; aPassD = 32 * 80;
        aStep = 32;
    } else {
        aS = A + (size_t)(tid >> 4) * lda + m0 + (tid & 15) * 8;
        aD = ABUF_OFF + (tid >> 4) * 272 + (tid & 15) * 16;
        aPassS = (size_t)8 * lda; aPassD = 8 * 272;
        aStep = (size_t)32 * lda;
    }
    if (BT == 0) {
        bS = Bp + (size_t)(n0 + (tid >> 2)) * ldb + (tid & 3) * 8;
        bD = BBUF_OFF + (tid >> 2) * 80 + (tid & 3) * 16;
        bPassS = (size_t)32 * ldb; bPassD = 32 * 80;
        bStep = 32;
    } else {
        bS = Bp + (size_t)(tid >> 4) * ldb + n0 + (tid & 15) * 8;
        bD = BBUF_OFF + (tid >> 4) * 272 + (tid & 15) * 16;
        bPassS = (size_t)8 * ldb; bPassD = 8 * 272;
        bStep = (size_t)32 * ldb;
    }
    auto issueBuf = [&](uint32_t bufb) {
        #pragma unroll
        for (int p = 0; p < 4; p++)
            cpa16(bufb + aD + p * aPassD, aS + p * aPassS);
        #pragma unroll
        for (int p = 0; p < 4; p++)
            cpa16(bufb + bD + p * bPassD, bS + p * bPassS);
        aS += aStep; bS += bStep;
    };

    // ldmatrix base addresses (buffer 0)
    const uint32_t aBase = (AT == 0)
        ? sb + ABUF_OFF + (uint32_t)(wm * 64 + (lane & 15)) * 80 + ((lane >> 4) & 1) * 16
        : sb + ABUF_OFF + (uint32_t)(((lane >> 4) & 1) * 8 + (lane & 7)) * 272
                        + (uint32_t)(wm * 64 + ((lane >> 3) & 1) * 8) * 2;
    const uint32_t bBase = (BT == 0)
        ? sb + BBUF_OFF + (uint32_t)(wn * 64 + ((lane >> 4) & 1) * 8 + (lane & 7)) * 80
                        + ((lane >> 3) & 1) * 16
        : sb + BBUF_OFF + (uint32_t)(((lane >> 3) & 1) * 8 + (lane & 7)) * 272
                        + (uint32_t)(wn * 64 + ((lane >> 4) & 1) * 8) * 2;

    const int nIter = K >> 5;     // multiple of 4 for all our shapes
    issueBuf(sb + 0 * BUFSTEP); CP_COMMIT();
    issueBuf(sb + 1 * BUFSTEP); CP_COMMIT();
    issueBuf(sb + 2 * BUFSTEP); CP_COMMIT();

    for (int itb = 0; itb < nIter; itb += 4) {
        #pragma unroll
        for (int u = 0; u < 4; u++) {
            const int it = itb + u;
            CP_WAIT2();
            __syncthreads();

            const uint32_t aB = aBase + u * BUFSTEP;
            const uint32_t bB = bBase + u * BUFSTEP;

            // ---- load all fragments (both kk halves) up front ----
            uint32_t af[2][4][4], bf[2][4][4];
            #pragma unroll
            for (int mi = 0; mi < 4; mi++) {
                const uint32_t ad = (AT == 0) ? aB + mi * 1280 : aB + mi * 32;
                if (AT == 0) ldsm4(af[0][mi], ad); else ldsm4t(af[0][mi], ad);
            }
            #pragma unroll
            for (int np = 0; np < 4; np++) {
                const uint32_t bd = (BT == 0) ? bB + np * 1280 : bB + np * 32;
                if (BT == 0) ldsm4(bf[0][np], bd); else ldsm4t(bf[0][np], bd);
            }
            if (it + 3 < nIter) issueBuf(sb + ((u + 3) & 3) * BUFSTEP);
            CP_COMMIT();
            #pragma unroll
            for (int mi = 0; mi < 4; mi++) {
                const uint32_t ad = (AT == 0) ? aB + mi * 1280 + 32
                                              : aB + 4352 + mi * 32;
                if (AT == 0) ldsm4(af[1][mi], ad); else ldsm4t(af[1][mi], ad);
            }
            #pragma unroll
            for (int np = 0; np < 4; np++) {
                const uint32_t bd = (BT == 0) ? bB + np * 1280 + 32
                                              : bB + 4352 + np * 32;
                if (BT == 0) ldsm4(bf[1][np], bd); else ldsm4t(bf[1][np], bd);
            }

            // ---- 128 MMAs back-to-back ----
            #pragma unroll
            for (int kk = 0; kk < 2; kk++)
                #pragma unroll
                for (int mi = 0; mi < 4; mi++)
                    #pragma unroll
                    for (int nj = 0; nj < 8; nj++)
                        mma16(acc[mi][nj], af[kk][mi], &bf[kk][nj >> 1][(nj & 1) * 2]);
        }
    }

    // ---- epilogue ----
    #pragma unroll
    for (int mi = 0; mi < 4; mi++) {
        float rs[2] = {0.f, 0.f};
        float invr[2] = {1.f, 1.f};
        if (NORM) {
            #pragma unroll
            for (int hh = 0; hh < 2; hh++) {
                const int row = m0 + wm * 64 + mi * 16 + gid + hh * 8;
                invr[hh] = 1.0f / rsum[(size_t)bz * T_ + row];
            }
        }
        #pragma unroll
        for (int nj = 0; nj < 8; nj++) {
            const int cc = n0 + wn * 64 + nj * 8 + tig * 2;
            float bn0 = 0.f, bn1 = 0.f;
            if (bias && bias_on_n) { bn0 = bias[cc]; bn1 = bias[cc + 1]; }
            #pragma unroll
            for (int hh = 0; hh < 2; hh++) {
                const int row = m0 + wm * 64 + mi * 16 + gid + hh * 8;
                float v0 = acc[mi][nj][hh * 2 + 0];
                float v1 = acc[mi][nj][hh * 2 + 1];
                if (bias) {
                    if (bias_on_n) { v0 += bn0; v1 += bn1; }
                    else { const float bm = bias[row]; v0 += bm; v1 += bm; }
                }
                if (EXPO) {
                    v0 = __expf(v0); v1 = __expf(v1);
                    rs[hh] += v0 + v1;
                }
                if (NORM) { v0 *= invr[hh]; v1 *= invr[hh]; }
                if (resid) {
                    const float2 rr = *(const float2*)&resid[(size_t)row * N + cc];
                    v0 += rr.x; v1 += rr.y;
                }
                if (OUTBF) {
                    __nv_bfloat16* Cb = (__nv_bfloat16*)Cvp + (size_t)bz * Cbs;
                    *(uint32_t*)&Cb[(size_t)row * N + cc] = pk2(v0, v1);
                } else {
                    float* Cf = (float*)Cvp + (size_t)bz * Cbs;
                    float2 o; o.x = v0; o.y = v1;
                    *(float2*)&Cf[(size_t)row * N + cc] = o;
                }
            }
        }
        if (EXPO) {
            // reduce over tig (lanes gid*4 + tig), one atomic per row per warp
            #pragma unroll
            for (int hh = 0; hh < 2; hh++) {
                float v = rs[hh];
                v += __shfl_xor_sync(0xffffffffu, v, 1);
                v += __shfl_xor_sync(0xffffffffu, v, 2);
                if (tig == 0) {
                    const int row = m0 + wm * 64 + mi * 16 + gid + hh * 8;
                    atomicAdd(&rsum[(size_t)bz * T_ + row], v);
                }
            }
        }
    }
}

// ---------------------------------------------------------------------------
// Launch
// ---------------------------------------------------------------------------
extern "C" void kernel_launch(void* const* d_in, const int* in_sizes, int n_in,
                              void* d_out, int out_size)
{
    const float* x     = (const float*)d_in[0];
    const float* gamma = (const float*)d_in[1];
    const float* beta  = (const float*)d_in[2];
    const float* Wq    = (const float*)d_in[3];
    const float* bq    = (const float*)d_in[4];
    const float* Wk    = (const float*)d_in[5];
    const float* bk    = (const float*)d_in[6];
    const float* Wv    = (const float*)d_in[7];
    const float* bv    = (const float*)d_in[8];
    const float* Wp    = (const float*)d_in[9];
    const float* bp    = (const float*)d_in[10];
    float* out = (float*)d_out;

    static bool inited = false;
    static __nv_bfloat16 *p_hb, *p_qkv, *p_wb, *p_ab, *p_wtb, *p_wpb;
    static float *p_rs, *p_bt;
    if (!inited) {
        cudaGetSymbolAddress((void**)&p_hb,  g_hb);
        cudaGetSymbolAddress((void**)&p_qkv, g_qkv);
        cudaGetSymbolAddress((void**)&p_wb,  g_wb);
        cudaGetSymbolAddress((void**)&p_rs,  g_rs);
        cudaGetSymbolAddress((void**)&p_ab,  g_ab);
        cudaGetSymbolAddress((void**)&p_wtb, g_wtb);
        cudaGetSymbolAddress((void**)&p_wpb, g_wpb);
        cudaGetSymbolAddress((void**)&p_bt,  g_bt);
        cudaFuncSetAttribute(gemm_ca<1, 0, 1, 0, 0>, cudaFuncAttributeMaxDynamicSharedMemorySize, SMEM_DYN);
        cudaFuncSetAttribute(gemm_ca<0, 0, 1, 1, 0>, cudaFuncAttributeMaxDynamicSharedMemorySize, SMEM_DYN);
        cudaFuncSetAttribute(gemm_ca<0, 1, 1, 0, 1>, cudaFuncAttributeMaxDynamicSharedMemorySize, SMEM_DYN);
        cudaFuncSetAttribute(gemm_ca<0, 0, 0, 0, 0>, cudaFuncAttributeMaxDynamicSharedMemorySize, SMEM_DYN);
        inited = true;
    }

    const size_t sBCT = (size_t)C_ * T_;
    const size_t sQKV = (size_t)T_ * 3 * C_;
    const size_t sBTT = (size_t)T_ * T_;
    const size_t sBTC = (size_t)T_ * C_;

    // 0) zero softmax row-sum accumulators (memset node in the graph)
    cudaMemsetAsync(p_rs, 0, (size_t)B_ * T_ * sizeof(float));

    // 1) GroupNorm -> bf16 h [B,C,T]
    groupnorm_kernel<<<B_ * G_, 256>>>(x, gamma, beta, p_hb);

    // 2) Pack all weights to bf16
    pack_w_kernel<<<(4 * C_ * C_ / 4) / 256, 256>>>(Wq, bq, Wk, bk, Wv, bv, Wp,
                                                    p_wtb, p_wpb, p_bt);

    // 3) QKV: qkv[b,t,o] = sum_c h[b,c,t]*Wt[o,c] + bt[o]
    {
        dim3 grid((3 * C_) / 128, T_ / 128, B_);
        gemm_ca<1, 0, 1, 0, 0><<<grid, 128, SMEM_DYN>>>(3 * C_, C_,
            p_hb, sBCT, T_,  p_wtb, 0, C_,
            p_qkv, sQKV, p_bt, 1, nullptr, 0, nullptr);
    }

    // 4) Scores + exp fused: wb = exp(q.k^T) bf16, row sums -> g_rs.
    //    (no max-subtraction: scores are O(10), fp32 exp is safe; result is
    //     mathematically identical to softmax after normalization)
    {
        dim3 grid(T_ / 128, T_ / 128, B_);
        gemm_ca<0, 0, 1, 1, 0><<<grid, 128, SMEM_DYN>>>(T_, C_,
            p_qkv, sQKV, 3 * C_,  p_qkv + C_, sQKV, 3 * C_,
            p_wb, sBTT, nullptr, 0, nullptr, 0, p_rs);
    }

    // 5) Apply + normalize: a[b,t,c] = (sum_s wb[b,t,s]*v[b,s,c]) / rs[b,t]
    {
        dim3 grid(C_ / 128, T_ / 128, B_);
        gemm_ca<0, 1, 1, 0, 1><<<grid, 128, SMEM_DYN>>>(C_, T_,
            p_wb, sBTT, T_,  p_qkv + 2 * C_, sQKV, 3 * C_,
            p_ab, sBTC, nullptr, 0, nullptr, 0, p_rs);
    }

    // 6) Proj + residual
    {
        dim3 grid(T_ / 128, C_ / 128, B_);
        gemm_ca<0, 0, 0, 0, 0><<<grid, 128, SMEM_DYN>>>(T_, C_,
            p_wpb, 0, C_,  p_ab, sBTC, C_,
            out, sBCT, bp, 0, x, sBCT, nullptr);
    }
}

// round 10
// speedup vs baseline: 10.1199x; 1.0904x over previous
#include <cuda_runtime.h>
#include <cuda_bf16.h>
#include <cstdint>

#define B_   16
#define C_   512
#define T_   1024
#define G_   32
#define CPG  (C_ / G_)
#define EPS  1e-5f
#define QSCALE 0.04419417382415922f   // C^-1/2
#define BH_  (B_ / 2)                 // batches per stream group

// ---------------------------------------------------------------------------
// Scratch (static __device__ — no allocation allowed)
// ---------------------------------------------------------------------------
__device__ __nv_bfloat16 g_hb [(size_t)B_ * C_ * T_];        // GN out [B,C,T]
__device__ __nv_bfloat16 g_qkv[(size_t)B_ * T_ * 3 * C_];    // [B,T,1536]
__device__ __nv_bfloat16 g_wb [(size_t)B_ * T_ * T_];        // exp(scores) bf16
__device__ float         g_rs [(size_t)B_ * T_];             // softmax row sums
__device__ __nv_bfloat16 g_ab [(size_t)B_ * T_ * C_];        // attn out [B,T,C]
__device__ __nv_bfloat16 g_wtb[(size_t)3 * C_ * C_];         // qkv weights [3C][C]
__device__ __nv_bfloat16 g_wpb[(size_t)C_ * C_];             // proj weight [C][C]
__device__ float         g_bt [3 * C_];

__device__ __forceinline__ uint32_t pk2(float a, float b) {
    __nv_bfloat162 t = __floats2bfloat162_rn(a, b);
    return *reinterpret_cast<uint32_t*>(&t);
}

// ---------------------------------------------------------------------------
// GroupNorm: fp32 in, bf16 out.
// ---------------------------------------------------------------------------
__global__ __launch_bounds__(256) void groupnorm_kernel(
    const float* __restrict__ x,
    const float* __restrict__ gamma,
    const float* __restrict__ beta,
    __nv_bfloat16* __restrict__ h)
{
    const int b = blockIdx.x >> 5;
    const int g = blockIdx.x & 31;
    const size_t base = ((size_t)b * C_ + (size_t)g * CPG) * T_;
    const float4* xp = (const float4*)(x + base);
    const int N4 = CPG * T_ / 4;
    const int tid = threadIdx.x;

    float s = 0.f, s2 = 0.f;
    for (int i = tid; i < N4; i += 256) {
        float4 v = xp[i];
        s  += v.x + v.y + v.z + v.w;
        s2 += v.x * v.x + v.y * v.y + v.z * v.z + v.w * v.w;
    }
    #pragma unroll
    for (int o = 16; o > 0; o >>= 1) {
        s  += __shfl_xor_sync(0xffffffffu, s, o);
        s2 += __shfl_xor_sync(0xffffffffu, s2, o);
    }
    __shared__ float sh1[8], sh2[8];
    const int wid = tid >> 5, lane = tid & 31;
    if (lane == 0) { sh1[wid] = s; sh2[wid] = s2; }
    __syncthreads();
    if (tid == 0) {
        float a = 0.f, bb = 0.f;
        #pragma unroll
        for (int i = 0; i < 8; i++) { a += sh1[i]; bb += sh2[i]; }
        sh1[0] = a; sh2[0] = bb;
    }
    __syncthreads();
    const float inv_n = 1.0f / (float)(CPG * T_);
    const float mean = sh1[0] * inv_n;
    const float var  = sh2[0] * inv_n - mean * mean;
    const float inv  = rsqrtf(var + EPS);

    for (int i = tid; i < N4; i += 256) {
        const int c = g * CPG + (i >> 8);
        const float ga = gamma[c] * inv;
        const float be = beta[c];
        float4 v = xp[i];
        uint2 o;
        o.x = pk2((v.x - mean) * ga + be, (v.y - mean) * ga + be);
        o.y = pk2((v.z - mean) * ga + be, (v.w - mean) * ga + be);
        *(uint2*)(h + base + (size_t)i * 4) = o;
    }
}

// ---------------------------------------------------------------------------
// Pack all weights to bf16: Wq(scaled)|Wk|Wv -> g_wtb, Wp -> g_wpb.
// ---------------------------------------------------------------------------
__global__ __launch_bounds__(256) void pack_w_kernel(
    const float* __restrict__ Wq, const float* __restrict__ bq,
    const float* __restrict__ Wk, const float* __restrict__ bk,
    const float* __restrict__ Wv, const float* __restrict__ bv,
    const float* __restrict__ Wp,
    __nv_bfloat16* __restrict__ Wt, __nv_bfloat16* __restrict__ Wpb,
    float* __restrict__ bt)
{
    const int idx = blockIdx.x * 256 + threadIdx.x;   // float4 idx, 2048*128
    const int o  = idx >> 7;
    const int c4 = idx & 127;
    const float* src; float s = 1.f; __nv_bfloat16* dst;
    if (o < C_)          { src = Wq + (size_t)o * C_; s = QSCALE; dst = Wt + (size_t)o * C_; }
    else if (o < 2 * C_) { src = Wk + (size_t)(o - C_) * C_;      dst = Wt + (size_t)o * C_; }
    else if (o < 3 * C_) { src = Wv + (size_t)(o - 2 * C_) * C_;  dst = Wt + (size_t)o * C_; }
    else                 { src = Wp + (size_t)(o - 3 * C_) * C_;  dst = Wpb + (size_t)(o - 3 * C_) * C_; }
    float4 v = *(const float4*)(src + c4 * 4);
    uint2 p; p.x = pk2(v.x * s, v.y * s); p.y = pk2(v.z * s, v.w * s);
    *(uint2*)(dst + c4 * 4) = p;
    if (idx < 3 * C_) {
        bt[idx] = (idx < C_) ? bq[idx] * QSCALE
                : (idx < 2 * C_) ? bk[idx - C_] : bv[idx - 2 * C_];
    }
}

// ---------------------------------------------------------------------------
// bf16 GEMM, cp.async 4-stage pipeline. Block tile 128x128, BK=32,
// 128 threads / 4 warps (2x2), warp tile 64x64. 2 CTAs/SM.
// AT/BT: 0 = [row][k] k-contig, 1 = [k][row] row-contig (trans ldmatrix).
// OUTBF: bf16 output.  EXPO: epilogue exp + row-sum atomics into rsum.
// NORM: epilogue multiplies by 1/rsum[row] (softmax normalization).
// ---------------------------------------------------------------------------
__device__ __forceinline__ void ldsm4(uint32_t* r, uint32_t a) {
    asm volatile("ldmatrix.sync.aligned.m8n8.x4.shared.b16 {%0,%1,%2,%3}, [%4];"
                 : "=r"(r[0]), "=r"(r[1]), "=r"(r[2]), "=r"(r[3]) : "r"(a));
}
__device__ __forceinline__ void ldsm4t(uint32_t* r, uint32_t a) {
    asm volatile("ldmatrix.sync.aligned.m8n8.x4.trans.shared.b16 {%0,%1,%2,%3}, [%4];"
                 : "=r"(r[0]), "=r"(r[1]), "=r"(r[2]), "=r"(r[3]) : "r"(a));
}
__device__ __forceinline__ void mma16(float* c, const uint32_t* a, const uint32_t* b) {
    asm volatile("mma.sync.aligned.m16n8k16.row.col.f32.bf16.bf16.f32 "
                 "{%0,%1,%2,%3},{%4,%5,%6,%7},{%8,%9},{%0,%1,%2,%3};"
                 : "+f"(c[0]), "+f"(c[1]), "+f"(c[2]), "+f"(c[3])
                 : "r"(a[0]), "r"(a[1]), "r"(a[2]), "r"(a[3]), "r"(b[0]), "r"(b[1]));
}
__device__ __forceinline__ void cpa16(uint32_t dst, const void* src) {
    asm volatile("cp.async.cg.shared.global [%0], [%1], 16;" :: "r"(dst), "l"(src));
}
#define CP_COMMIT() asm volatile("cp.async.commit_group;")
#define CP_WAIT2()  asm volatile("cp.async.wait_group 2;")

#define ABUF_OFF 0
#define BBUF_OFF 10240
#define BUFSTEP  20480
#define STAGES   4
#define SMEM_DYN (STAGES * BUFSTEP)

template<int AT, int BT, int OUTBF, int EXPO, int NORM>
__global__ __launch_bounds__(128, 2) void gemm_ca(
    int N, int K,
    const __nv_bfloat16* __restrict__ A, size_t Abs, int lda,
    const __nv_bfloat16* __restrict__ Bp, size_t Bbs, int ldb,
    void* __restrict__ Cvp, size_t Cbs,
    const float* __restrict__ bias, int bias_on_n,
    const float* __restrict__ resid, size_t Rbs,
    float* __restrict__ rsum)
{
    const int bz = blockIdx.z;
    A  += (size_t)bz * Abs;
    Bp += (size_t)bz * Bbs;
    if (resid) resid += (size_t)bz * Rbs;

    extern __shared__ __align__(16) unsigned char sm[];
    const uint32_t sb = (uint32_t)__cvta_generic_to_shared(sm);

    const int tid = threadIdx.x;
    const int m0 = blockIdx.y * 128;
    const int n0 = blockIdx.x * 128;
    const int warp = tid >> 5, lane = tid & 31;
    const int wm = warp >> 1, wn = warp & 1;     // 2x2 warp grid, 64x64 tiles
    const int gid = lane >> 2, tig = lane & 3;

    float acc[4][8][4];
    #pragma unroll
    for (int i = 0; i < 4; i++)
        #pragma unroll
        for (int j = 0; j < 8; j++)
            #pragma unroll
            for (int r = 0; r < 4; r++) acc[i][j][r] = 0.f;

    // --- cp.async: 128 threads, 4 passes each for A (8KB) and B (8KB) ---
    const __nv_bfloat16 *aS, *bS;
    uint32_t aD, bD;
    size_t aStep, bStep, aPassS, bPassS;
    uint32_t aPassD, bPassD;
    if (AT == 0) {
        aS = A + (size_t)(m0 + (tid >> 2)) * lda + (tid & 3) * 8;
        aD = ABUF_OFF + (tid >> 2) * 80 + (tid & 3) * 16;
        aPassS = (size_t)32 * lda; aPassD = 32 * 80;
        aStep = 32;
    } else {
        aS = A + (size_t)(tid >> 4) * lda + m0 + (tid & 15) * 8;
        aD = ABUF_OFF + (tid >> 4) * 272 + (tid & 15) * 16;
        aPassS = (size_t)8 * lda; aPassD = 8 * 272;
        aStep = (size_t)32 * lda;
    }
    if (BT == 0) {
        bS = Bp + (size_t)(n0 + (tid >> 2)) * ldb + (tid & 3) * 8;
        bD = BBUF_OFF + (tid >> 2) * 80 + (tid & 3) * 16;
        bPassS = (size_t)32 * ldb; bPassD = 32 * 80;
        bStep = 32;
    } else {
        bS = Bp + (size_t)(tid >> 4) * ldb + n0 + (tid & 15) * 8;
        bD = BBUF_OFF + (tid >> 4) * 272 + (tid & 15) * 16;
        bPassS = (size_t)8 * ldb; bPassD = 8 * 272;
        bStep = (size_t)32 * ldb;
    }
    auto issueBuf = [&](uint32_t bufb) {
        #pragma unroll
        for (int p = 0; p < 4; p++)
            cpa16(bufb + aD + p * aPassD, aS + p * aPassS);
        #pragma unroll
        for (int p = 0; p < 4; p++)
            cpa16(bufb + bD + p * bPassD, bS + p * bPassS);
        aS += aStep; bS += bStep;
    };

    // ldmatrix base addresses (buffer 0)
    const uint32_t aBase = (AT == 0)
        ? sb + ABUF_OFF + (uint32_t)(wm * 64 + (lane & 15)) * 80 + ((lane >> 4) & 1) * 16
        : sb + ABUF_OFF + (uint32_t)(((lane >> 4) & 1) * 8 + (lane & 7)) * 272
                        + (uint32_t)(wm * 64 + ((lane >> 3) & 1) * 8) * 2;
    const uint32_t bBase = (BT == 0)
        ? sb + BBUF_OFF + (uint32_t)(wn * 64 + ((lane >> 4) & 1) * 8 + (lane & 7)) * 80
                        + ((lane >> 3) & 1) * 16
        : sb + BBUF_OFF + (uint32_t)(((lane >> 3) & 1) * 8 + (lane & 7)) * 272
                        + (uint32_t)(wn * 64 + ((lane >> 4) & 1) * 8) * 2;

    const int nIter = K >> 5;     // multiple of 4 for all our shapes
    issueBuf(sb + 0 * BUFSTEP); CP_COMMIT();
    issueBuf(sb + 1 * BUFSTEP); CP_COMMIT();
    issueBuf(sb + 2 * BUFSTEP); CP_COMMIT();

    for (int itb = 0; itb < nIter; itb += 4) {
        #pragma unroll
        for (int u = 0; u < 4; u++) {
            const int it = itb + u;
            CP_WAIT2();
            __syncthreads();

            const uint32_t aB = aBase + u * BUFSTEP;
            const uint32_t bB = bBase + u * BUFSTEP;

            // ---- load all fragments (both kk halves) up front ----
            uint32_t af[2][4][4], bf[2][4][4];
            #pragma unroll
            for (int mi = 0; mi < 4; mi++) {
                const uint32_t ad = (AT == 0) ? aB + mi * 1280 : aB + mi * 32;
                if (AT == 0) ldsm4(af[0][mi], ad); else ldsm4t(af[0][mi], ad);
            }
            #pragma unroll
            for (int np = 0; np < 4; np++) {
                const uint32_t bd = (BT == 0) ? bB + np * 1280 : bB + np * 32;
                if (BT == 0) ldsm4(bf[0][np], bd); else ldsm4t(bf[0][np], bd);
            }
            if (it + 3 < nIter) issueBuf(sb + ((u + 3) & 3) * BUFSTEP);
            CP_COMMIT();
            #pragma unroll
            for (int mi = 0; mi < 4; mi++) {
                const uint32_t ad = (AT == 0) ? aB + mi * 1280 + 32
                                              : aB + 4352 + mi * 32;
                if (AT == 0) ldsm4(af[1][mi], ad); else ldsm4t(af[1][mi], ad);
            }
            #pragma unroll
            for (int np = 0; np < 4; np++) {
                const uint32_t bd = (BT == 0) ? bB + np * 1280 + 32
                                              : bB + 4352 + np * 32;
                if (BT == 0) ldsm4(bf[1][np], bd); else ldsm4t(bf[1][np], bd);
            }

            // ---- 128 MMAs back-to-back ----
            #pragma unroll
            for (int kk = 0; kk < 2; kk++)
                #pragma unroll
                for (int mi = 0; mi < 4; mi++)
                    #pragma unroll
                    for (int nj = 0; nj < 8; nj++)
                        mma16(acc[mi][nj], af[kk][mi], &bf[kk][nj >> 1][(nj & 1) * 2]);
        }
    }

    // ---- epilogue ----
    #pragma unroll
    for (int mi = 0; mi < 4; mi++) {
        float rs[2] = {0.f, 0.f};
        float invr[2] = {1.f, 1.f};
        if (NORM) {
            #pragma unroll
            for (int hh = 0; hh < 2; hh++) {
                const int row = m0 + wm * 64 + mi * 16 + gid + hh * 8;
                invr[hh] = 1.0f / rsum[(size_t)bz * T_ + row];
            }
        }
        #pragma unroll
        for (int nj = 0; nj < 8; nj++) {
            const int cc = n0 + wn * 64 + nj * 8 + tig * 2;
            float bn0 = 0.f, bn1 = 0.f;
            if (bias && bias_on_n) { bn0 = bias[cc]; bn1 = bias[cc + 1]; }
            #pragma unroll
            for (int hh = 0; hh < 2; hh++) {
                const int row = m0 + wm * 64 + mi * 16 + gid + hh * 8;
                float v0 = acc[mi][nj][hh * 2 + 0];
                float v1 = acc[mi][nj][hh * 2 + 1];
                if (bias) {
                    if (bias_on_n) { v0 += bn0; v1 += bn1; }
                    else { const float bm = bias[row]; v0 += bm; v1 += bm; }
                }
                if (EXPO) {
                    v0 = __expf(v0); v1 = __expf(v1);
                    rs[hh] += v0 + v1;
                }
                if (NORM) { v0 *= invr[hh]; v1 *= invr[hh]; }
                if (resid) {
                    const float2 rr = *(const float2*)&resid[(size_t)row * N + cc];
                    v0 += rr.x; v1 += rr.y;
                }
                if (OUTBF) {
                    __nv_bfloat16* Cb = (__nv_bfloat16*)Cvp + (size_t)bz * Cbs;
                    *(uint32_t*)&Cb[(size_t)row * N + cc] = pk2(v0, v1);
                } else {
                    float* Cf = (float*)Cvp + (size_t)bz * Cbs;
                    float2 o; o.x = v0; o.y = v1;
                    *(float2*)&Cf[(size_t)row * N + cc] = o;
                }
            }
        }
        if (EXPO) {
            #pragma unroll
            for (int hh = 0; hh < 2; hh++) {
                float v = rs[hh];
                v += __shfl_xor_sync(0xffffffffu, v, 1);
                v += __shfl_xor_sync(0xffffffffu, v, 2);
                if (tig == 0) {
                    const int row = m0 + wm * 64 + mi * 16 + gid + hh * 8;
                    atomicAdd(&rsum[(size_t)bz * T_ + row], v);
                }
            }
        }
    }
}

// ---------------------------------------------------------------------------
// Launch: two-stream fork-join, batches split 8/8 per stream.
// ---------------------------------------------------------------------------
extern "C" void kernel_launch(void* const* d_in, const int* in_sizes, int n_in,
                              void* d_out, int out_size)
{
    const float* x     = (const float*)d_in[0];
    const float* gamma = (const float*)d_in[1];
    const float* beta  = (const float*)d_in[2];
    const float* Wq    = (const float*)d_in[3];
    const float* bq    = (const float*)d_in[4];
    const float* Wk    = (const float*)d_in[5];
    const float* bk    = (const float*)d_in[6];
    const float* Wv    = (const float*)d_in[7];
    const float* bv    = (const float*)d_in[8];
    const float* Wp    = (const float*)d_in[9];
    const float* bp    = (const float*)d_in[10];
    float* out = (float*)d_out;

    static bool inited = false;
    static __nv_bfloat16 *p_hb, *p_qkv, *p_wb, *p_ab, *p_wtb, *p_wpb;
    static float *p_rs, *p_bt;
    static cudaStream_t s1;
    static cudaEvent_t evFork, evGN, evPack, evJoin;
    if (!inited) {
        cudaGetSymbolAddress((void**)&p_hb,  g_hb);
        cudaGetSymbolAddress((void**)&p_qkv, g_qkv);
        cudaGetSymbolAddress((void**)&p_wb,  g_wb);
        cudaGetSymbolAddress((void**)&p_rs,  g_rs);
        cudaGetSymbolAddress((void**)&p_ab,  g_ab);
        cudaGetSymbolAddress((void**)&p_wtb, g_wtb);
        cudaGetSymbolAddress((void**)&p_wpb, g_wpb);
        cudaGetSymbolAddress((void**)&p_bt,  g_bt);
        cudaFuncSetAttribute(gemm_ca<1, 0, 1, 0, 0>, cudaFuncAttributeMaxDynamicSharedMemorySize, SMEM_DYN);
        cudaFuncSetAttribute(gemm_ca<0, 0, 1, 1, 0>, cudaFuncAttributeMaxDynamicSharedMemorySize, SMEM_DYN);
        cudaFuncSetAttribute(gemm_ca<0, 1, 1, 0, 1>, cudaFuncAttributeMaxDynamicSharedMemorySize, SMEM_DYN);
        cudaFuncSetAttribute(gemm_ca<0, 0, 0, 0, 0>, cudaFuncAttributeMaxDynamicSharedMemorySize, SMEM_DYN);
        cudaStreamCreateWithFlags(&s1, cudaStreamNonBlocking);
        cudaEventCreateWithFlags(&evFork, cudaEventDisableTiming);
        cudaEventCreateWithFlags(&evGN,   cudaEventDisableTiming);
        cudaEventCreateWithFlags(&evPack, cudaEventDisableTiming);
        cudaEventCreateWithFlags(&evJoin, cudaEventDisableTiming);
        inited = true;
    }

    const size_t sBCT = (size_t)C_ * T_;
    const size_t sQKV = (size_t)T_ * 3 * C_;
    const size_t sBTT = (size_t)T_ * T_;
    const size_t sBTC = (size_t)T_ * C_;
    // group-B (batches 8..15) pointer offsets
    const size_t oHB  = (size_t)BH_ * sBCT;
    const size_t oQKV = (size_t)BH_ * sQKV;
    const size_t oWB  = (size_t)BH_ * sBTT;
    const size_t oAB  = (size_t)BH_ * sBTC;
    const size_t oRS  = (size_t)BH_ * T_;
    const size_t oX   = (size_t)BH_ * sBCT;

    // ---- stream0 preamble ----
    cudaEventRecord(evFork, 0);
    cudaStreamWaitEvent(s1, evFork, 0);

    cudaMemsetAsync(p_rs, 0, (size_t)B_ * T_ * sizeof(float));
    groupnorm_kernel<<<B_ * G_, 256>>>(x, gamma, beta, p_hb);
    cudaEventRecord(evGN, 0);

    // pack on s1 (independent of GN)
    pack_w_kernel<<<(4 * C_ * C_ / 4) / 256, 256, 0, s1>>>(
        Wq, bq, Wk, bk, Wv, bv, Wp, p_wtb, p_wpb, p_bt);
    cudaEventRecord(evPack, s1);

    // cross deps: group A (stream0) needs pack; group B (s1) needs GN (+memset)
    cudaStreamWaitEvent(0, evPack, 0);
    cudaStreamWaitEvent(s1, evGN, 0);

    dim3 gQKV((3 * C_) / 128, T_ / 128, BH_);
    dim3 gSco(T_ / 128, T_ / 128, BH_);
    dim3 gApp(C_ / 128, T_ / 128, BH_);
    dim3 gPro(T_ / 128, C_ / 128, BH_);

    // ---- group A: batches 0..7 on stream0 ----
    gemm_ca<1, 0, 1, 0, 0><<<gQKV, 128, SMEM_DYN>>>(3 * C_, C_,
        p_hb, sBCT, T_,  p_wtb, 0, C_,
        p_qkv, sQKV, p_bt, 1, nullptr, 0, nullptr);
    gemm_ca<0, 0, 1, 1, 0><<<gSco, 128, SMEM_DYN>>>(T_, C_,
        p_qkv, sQKV, 3 * C_,  p_qkv + C_, sQKV, 3 * C_,
        p_wb, sBTT, nullptr, 0, nullptr, 0, p_rs);
    gemm_ca<0, 1, 1, 0, 1><<<gApp, 128, SMEM_DYN>>>(C_, T_,
        p_wb, sBTT, T_,  p_qkv + 2 * C_, sQKV, 3 * C_,
        p_ab, sBTC, nullptr, 0, nullptr, 0, p_rs);
    gemm_ca<0, 0, 0, 0, 0><<<gPro, 128, SMEM_DYN>>>(T_, C_,
        p_wpb, 0, C_,  p_ab, sBTC, C_,
        out, sBCT, bp, 0, x, sBCT, nullptr);

    // ---- group B: batches 8..15 on s1 ----
    gemm_ca<1, 0, 1, 0, 0><<<gQKV, 128, SMEM_DYN, s1>>>(3 * C_, C_,
        p_hb + oHB, sBCT, T_,  p_wtb, 0, C_,
        p_qkv + oQKV, sQKV, p_bt, 1, nullptr, 0, nullptr);
    gemm_ca<0, 0, 1, 1, 0><<<gSco, 128, SMEM_DYN, s1>>>(T_, C_,
        p_qkv + oQKV, sQKV, 3 * C_,  p_qkv + oQKV + C_, sQKV, 3 * C_,
        p_wb + oWB, sBTT, nullptr, 0, nullptr, 0, p_rs + oRS);
    gemm_ca<0, 1, 1, 0, 1><<<gApp, 128, SMEM_DYN, s1>>>(C_, T_,
        p_wb + oWB, sBTT, T_,  p_qkv + oQKV + 2 * C_, sQKV, 3 * C_,
        p_ab + oAB, sBTC, nullptr, 0, nullptr, 0, p_rs + oRS);
    gemm_ca<0, 0, 0, 0, 0><<<gPro, 128, SMEM_DYN, s1>>>(T_, C_,
        p_wpb, 0, C_,  p_ab + oAB, sBTC, C_,
        out + oX, sBCT, bp, 0, x + oX, sBCT, nullptr);

    // ---- join ----
    cudaEventRecord(evJoin, s1);
    cudaStreamWaitEvent(0, evJoin, 0);
}

// round 11
// speedup vs baseline: 10.1772x; 1.0057x over previous
#include <cuda_runtime.h>
#include <cuda_bf16.h>
#include <cstdint>

#define B_   16
#define C_   512
#define T_   1024
#define G_   32
#define CPG  (C_ / G_)
#define EPS  1e-5f
#define QSCALE 0.04419417382415922f   // C^-1/2
#define NGRP 4
#define BG_  (B_ / NGRP)              // 4 batches per stream group

// ---------------------------------------------------------------------------
// Scratch (static __device__ — no allocation allowed)
// ---------------------------------------------------------------------------
__device__ __nv_bfloat16 g_hb [(size_t)B_ * C_ * T_];        // GN out [B,C,T]
__device__ __nv_bfloat16 g_qkv[(size_t)B_ * T_ * 3 * C_];    // [B,T,1536]
__device__ __nv_bfloat16 g_wb [(size_t)B_ * T_ * T_];        // exp(scores) bf16
__device__ float         g_rs [(size_t)B_ * T_];             // softmax row sums
__device__ __nv_bfloat16 g_ab [(size_t)B_ * T_ * C_];        // attn out [B,T,C]
__device__ __nv_bfloat16 g_wtb[(size_t)3 * C_ * C_];         // qkv weights [3C][C]
__device__ __nv_bfloat16 g_wpb[(size_t)C_ * C_];             // proj weight [C][C]
__device__ float         g_bt [3 * C_];

__device__ __forceinline__ uint32_t pk2(float a, float b) {
    __nv_bfloat162 t = __floats2bfloat162_rn(a, b);
    return *reinterpret_cast<uint32_t*>(&t);
}

// ---------------------------------------------------------------------------
// GroupNorm (per batch-group): fp32 in, bf16 out. grid = BG_*G_ blocks.
// ---------------------------------------------------------------------------
__global__ __launch_bounds__(256) void groupnorm_kernel(
    const float* __restrict__ x,
    const float* __restrict__ gamma,
    const float* __restrict__ beta,
    __nv_bfloat16* __restrict__ h)
{
    const int b = blockIdx.x >> 5;
    const int g = blockIdx.x & 31;
    const size_t base = ((size_t)b * C_ + (size_t)g * CPG) * T_;
    const float4* xp = (const float4*)(x + base);
    const int N4 = CPG * T_ / 4;
    const int tid = threadIdx.x;

    float s = 0.f, s2 = 0.f;
    for (int i = tid; i < N4; i += 256) {
        float4 v = xp[i];
        s  += v.x + v.y + v.z + v.w;
        s2 += v.x * v.x + v.y * v.y + v.z * v.z + v.w * v.w;
    }
    #pragma unroll
    for (int o = 16; o > 0; o >>= 1) {
        s  += __shfl_xor_sync(0xffffffffu, s, o);
        s2 += __shfl_xor_sync(0xffffffffu, s2, o);
    }
    __shared__ float sh1[8], sh2[8];
    const int wid = tid >> 5, lane = tid & 31;
    if (lane == 0) { sh1[wid] = s; sh2[wid] = s2; }
    __syncthreads();
    if (tid == 0) {
        float a = 0.f, bb = 0.f;
        #pragma unroll
        for (int i = 0; i < 8; i++) { a += sh1[i]; bb += sh2[i]; }
        sh1[0] = a; sh2[0] = bb;
    }
    __syncthreads();
    const float inv_n = 1.0f / (float)(CPG * T_);
    const float mean = sh1[0] * inv_n;
    const float var  = sh2[0] * inv_n - mean * mean;
    const float inv  = rsqrtf(var + EPS);

    for (int i = tid; i < N4; i += 256) {
        const int c = g * CPG + (i >> 8);
        const float ga = gamma[c] * inv;
        const float be = beta[c];
        float4 v = xp[i];
        uint2 o;
        o.x = pk2((v.x - mean) * ga + be, (v.y - mean) * ga + be);
        o.y = pk2((v.z - mean) * ga + be, (v.w - mean) * ga + be);
        *(uint2*)(h + base + (size_t)i * 4) = o;
    }
}

// ---------------------------------------------------------------------------
// Pack all weights to bf16: Wq(scaled)|Wk|Wv -> g_wtb, Wp -> g_wpb.
// ---------------------------------------------------------------------------
__global__ __launch_bounds__(256) void pack_w_kernel(
    const float* __restrict__ Wq, const float* __restrict__ bq,
    const float* __restrict__ Wk, const float* __restrict__ bk,
    const float* __restrict__ Wv, const float* __restrict__ bv,
    const float* __restrict__ Wp,
    __nv_bfloat16* __restrict__ Wt, __nv_bfloat16* __restrict__ Wpb,
    float* __restrict__ bt)
{
    const int idx = blockIdx.x * 256 + threadIdx.x;   // float4 idx, 2048*128
    const int o  = idx >> 7;
    const int c4 = idx & 127;
    const float* src; float s = 1.f; __nv_bfloat16* dst;
    if (o < C_)          { src = Wq + (size_t)o * C_; s = QSCALE; dst = Wt + (size_t)o * C_; }
    else if (o < 2 * C_) { src = Wk + (size_t)(o - C_) * C_;      dst = Wt + (size_t)o * C_; }
    else if (o < 3 * C_) { src = Wv + (size_t)(o - 2 * C_) * C_;  dst = Wt + (size_t)o * C_; }
    else                 { src = Wp + (size_t)(o - 3 * C_) * C_;  dst = Wpb + (size_t)(o - 3 * C_) * C_; }
    float4 v = *(const float4*)(src + c4 * 4);
    uint2 p; p.x = pk2(v.x * s, v.y * s); p.y = pk2(v.z * s, v.w * s);
    *(uint2*)(dst + c4 * 4) = p;
    if (idx < 3 * C_) {
        bt[idx] = (idx < C_) ? bq[idx] * QSCALE
                : (idx < 2 * C_) ? bk[idx - C_] : bv[idx - 2 * C_];
    }
}

// ---------------------------------------------------------------------------
// bf16 GEMM, cp.async 4-stage pipeline. Block tile 128x128, BK=32,
// 128 threads / 4 warps (2x2), warp tile 64x64. 2 CTAs/SM.
// AT/BT: 0 = [row][k] k-contig, 1 = [k][row] row-contig (trans ldmatrix).
// OUTBF: bf16 output.  EXPO: epilogue exp + row-sum atomics into rsum.
// NORM: epilogue multiplies by 1/rsum[row] (softmax normalization).
// ---------------------------------------------------------------------------
__device__ __forceinline__ void ldsm4(uint32_t* r, uint32_t a) {
    asm volatile("ldmatrix.sync.aligned.m8n8.x4.shared.b16 {%0,%1,%2,%3}, [%4];"
                 : "=r"(r[0]), "=r"(r[1]), "=r"(r[2]), "=r"(r[3]) : "r"(a));
}
__device__ __forceinline__ void ldsm4t(uint32_t* r, uint32_t a) {
    asm volatile("ldmatrix.sync.aligned.m8n8.x4.trans.shared.b16 {%0,%1,%2,%3}, [%4];"
                 : "=r"(r[0]), "=r"(r[1]), "=r"(r[2]), "=r"(r[3]) : "r"(a));
}
__device__ __forceinline__ void mma16(float* c, const uint32_t* a, const uint32_t* b) {
    asm volatile("mma.sync.aligned.m16n8k16.row.col.f32.bf16.bf16.f32 "
                 "{%0,%1,%2,%3},{%4,%5,%6,%7},{%8,%9},{%0,%1,%2,%3};"
                 : "+f"(c[0]), "+f"(c[1]), "+f"(c[2]), "+f"(c[3])
                 : "r"(a[0]), "r"(a[1]), "r"(a[2]), "r"(a[3]), "r"(b[0]), "r"(b[1]));
}
__device__ __forceinline__ void cpa16(uint32_t dst, const void* src) {
    asm volatile("cp.async.cg.shared.global [%0], [%1], 16;" :: "r"(dst), "l"(src));
}
#define CP_COMMIT() asm volatile("cp.async.commit_group;")
#define CP_WAIT2()  asm volatile("cp.async.wait_group 2;")

#define ABUF_OFF 0
#define BBUF_OFF 10240
#define BUFSTEP  20480
#define STAGES   4
#define SMEM_DYN (STAGES * BUFSTEP)

template<int AT, int BT, int OUTBF, int EXPO, int NORM>
__global__ __launch_bounds__(128, 2) void gemm_ca(
    int N, int K,
    const __nv_bfloat16* __restrict__ A, size_t Abs, int lda,
    const __nv_bfloat16* __restrict__ Bp, size_t Bbs, int ldb,
    void* __restrict__ Cvp, size_t Cbs,
    const float* __restrict__ bias, int bias_on_n,
    const float* __restrict__ resid, size_t Rbs,
    float* __restrict__ rsum)
{
    const int bz = blockIdx.z;
    A  += (size_t)bz * Abs;
    Bp += (size_t)bz * Bbs;
    if (resid) resid += (size_t)bz * Rbs;

    extern __shared__ __align__(16) unsigned char sm[];
    const uint32_t sb = (uint32_t)__cvta_generic_to_shared(sm);

    const int tid = threadIdx.x;
    const int m0 = blockIdx.y * 128;
    const int n0 = blockIdx.x * 128;
    const int warp = tid >> 5, lane = tid & 31;
    const int wm = warp >> 1, wn = warp & 1;     // 2x2 warp grid, 64x64 tiles
    const int gid = lane >> 2, tig = lane & 3;

    float acc[4][8][4];
    #pragma unroll
    for (int i = 0; i < 4; i++)
        #pragma unroll
        for (int j = 0; j < 8; j++)
            #pragma unroll
            for (int r = 0; r < 4; r++) acc[i][j][r] = 0.f;

    // --- cp.async: 128 threads, 4 passes each for A (8KB) and B (8KB) ---
    const __nv_bfloat16 *aS, *bS;
    uint32_t aD, bD;
    size_t aStep, bStep, aPassS, bPassS;
    uint32_t aPassD, bPassD;
    if (AT == 0) {
        aS = A + (size_t)(m0 + (tid >> 2)) * lda + (tid & 3) * 8;
        aD = ABUF_OFF + (tid >> 2) * 80 + (tid & 3) * 16;
        aPassS = (size_t)32 * lda; aPassD = 32 * 80;
        aStep = 32;
    } else {
        aS = A + (size_t)(tid >> 4) * lda + m0 + (tid & 15) * 8;
        aD = ABUF_OFF + (tid >> 4) * 272 + (tid & 15) * 16;
        aPassS = (size_t)8 * lda; aPassD = 8 * 272;
        aStep = (size_t)32 * lda;
    }
    if (BT == 0) {
        bS = Bp + (size_t)(n0 + (tid >> 2)) * ldb + (tid & 3) * 8;
        bD = BBUF_OFF + (tid >> 2) * 80 + (tid & 3) * 16;
        bPassS = (size_t)32 * ldb; bPassD = 32 * 80;
        bStep = 32;
    } else {
        bS = Bp + (size_t)(tid >> 4) * ldb + n0 + (tid & 15) * 8;
        bD = BBUF_OFF + (tid >> 4) * 272 + (tid & 15) * 16;
        bPassS = (size_t)8 * ldb; bPassD = 8 * 272;
        bStep = (size_t)32 * ldb;
    }
    auto issueBuf = [&](uint32_t bufb) {
        #pragma unroll
        for (int p = 0; p < 4; p++)
            cpa16(bufb + aD + p * aPassD, aS + p * aPassS);
        #pragma unroll
        for (int p = 0; p < 4; p++)
            cpa16(bufb + bD + p * bPassD, bS + p * bPassS);
        aS += aStep; bS += bStep;
    };

    // ldmatrix base addresses (buffer 0)
    const uint32_t aBase = (AT == 0)
        ? sb + ABUF_OFF + (uint32_t)(wm * 64 + (lane & 15)) * 80 + ((lane >> 4) & 1) * 16
        : sb + ABUF_OFF + (uint32_t)(((lane >> 4) & 1) * 8 + (lane & 7)) * 272
                        + (uint32_t)(wm * 64 + ((lane >> 3) & 1) * 8) * 2;
    const uint32_t bBase = (BT == 0)
        ? sb + BBUF_OFF + (uint32_t)(wn * 64 + ((lane >> 4) & 1) * 8 + (lane & 7)) * 80
                        + ((lane >> 3) & 1) * 16
        : sb + BBUF_OFF + (uint32_t)(((lane >> 3) & 1) * 8 + (lane & 7)) * 272
                        + (uint32_t)(wn * 64 + ((lane >> 4) & 1) * 8) * 2;

    const int nIter = K >> 5;     // multiple of 4 for all our shapes
    issueBuf(sb + 0 * BUFSTEP); CP_COMMIT();
    issueBuf(sb + 1 * BUFSTEP); CP_COMMIT();
    issueBuf(sb + 2 * BUFSTEP); CP_COMMIT();

    for (int itb = 0; itb < nIter; itb += 4) {
        #pragma unroll
        for (int u = 0; u < 4; u++) {
            const int it = itb + u;
            CP_WAIT2();
            __syncthreads();

            const uint32_t aB = aBase + u * BUFSTEP;
            const uint32_t bB = bBase + u * BUFSTEP;

            // ---- load all fragments (both kk halves) up front ----
            uint32_t af[2][4][4], bf[2][4][4];
            #pragma unroll
            for (int mi = 0; mi < 4; mi++) {
                const uint32_t ad = (AT == 0) ? aB + mi * 1280 : aB + mi * 32;
                if (AT == 0) ldsm4(af[0][mi], ad); else ldsm4t(af[0][mi], ad);
            }
            #pragma unroll
            for (int np = 0; np < 4; np++) {
                const uint32_t bd = (BT == 0) ? bB + np * 1280 : bB + np * 32;
                if (BT == 0) ldsm4(bf[0][np], bd); else ldsm4t(bf[0][np], bd);
            }
            if (it + 3 < nIter) issueBuf(sb + ((u + 3) & 3) * BUFSTEP);
            CP_COMMIT();
            #pragma unroll
            for (int mi = 0; mi < 4; mi++) {
                const uint32_t ad = (AT == 0) ? aB + mi * 1280 + 32
                                              : aB + 4352 + mi * 32;
                if (AT == 0) ldsm4(af[1][mi], ad); else ldsm4t(af[1][mi], ad);
            }
            #pragma unroll
            for (int np = 0; np < 4; np++) {
                const uint32_t bd = (BT == 0) ? bB + np * 1280 + 32
                                              : bB + 4352 + np * 32;
                if (BT == 0) ldsm4(bf[1][np], bd); else ldsm4t(bf[1][np], bd);
            }

            // ---- 128 MMAs back-to-back ----
            #pragma unroll
            for (int kk = 0; kk < 2; kk++)
                #pragma unroll
                for (int mi = 0; mi < 4; mi++)
                    #pragma unroll
                    for (int nj = 0; nj < 8; nj++)
                        mma16(acc[mi][nj], af[kk][mi], &bf[kk][nj >> 1][(nj & 1) * 2]);
        }
    }

    // ---- epilogue ----
    #pragma unroll
    for (int mi = 0; mi < 4; mi++) {
        float rs[2] = {0.f, 0.f};
        float invr[2] = {1.f, 1.f};
        if (NORM) {
            #pragma unroll
            for (int hh = 0; hh < 2; hh++) {
                const int row = m0 + wm * 64 + mi * 16 + gid + hh * 8;
                invr[hh] = 1.0f / rsum[(size_t)bz * T_ + row];
            }
        }
        #pragma unroll
        for (int nj = 0; nj < 8; nj++) {
            const int cc = n0 + wn * 64 + nj * 8 + tig * 2;
            float bn0 = 0.f, bn1 = 0.f;
            if (bias && bias_on_n) { bn0 = bias[cc]; bn1 = bias[cc + 1]; }
            #pragma unroll
            for (int hh = 0; hh < 2; hh++) {
                const int row = m0 + wm * 64 + mi * 16 + gid + hh * 8;
                float v0 = acc[mi][nj][hh * 2 + 0];
                float v1 = acc[mi][nj][hh * 2 + 1];
                if (bias) {
                    if (bias_on_n) { v0 += bn0; v1 += bn1; }
                    else { const float bm = bias[row]; v0 += bm; v1 += bm; }
                }
                if (EXPO) {
                    v0 = __expf(v0); v1 = __expf(v1);
                    rs[hh] += v0 + v1;
                }
                if (NORM) { v0 *= invr[hh]; v1 *= invr[hh]; }
                if (resid) {
                    const float2 rr = *(const float2*)&resid[(size_t)row * N + cc];
                    v0 += rr.x; v1 += rr.y;
                }
                if (OUTBF) {
                    __nv_bfloat16* Cb = (__nv_bfloat16*)Cvp + (size_t)bz * Cbs;
                    *(uint32_t*)&Cb[(size_t)row * N + cc] = pk2(v0, v1);
                } else {
                    float* Cf = (float*)Cvp + (size_t)bz * Cbs;
                    float2 o; o.x = v0; o.y = v1;
                    *(float2*)&Cf[(size_t)row * N + cc] = o;
                }
            }
        }
        if (EXPO) {
            #pragma unroll
            for (int hh = 0; hh < 2; hh++) {
                float v = rs[hh];
                v += __shfl_xor_sync(0xffffffffu, v, 1);
                v += __shfl_xor_sync(0xffffffffu, v, 2);
                if (tig == 0) {
                    const int row = m0 + wm * 64 + mi * 16 + gid + hh * 8;
                    atomicAdd(&rsum[(size_t)bz * T_ + row], v);
                }
            }
        }
    }
}

// ---------------------------------------------------------------------------
// Launch: 4 stream-groups of 4 batches, per-group GN inside the chain.
// ---------------------------------------------------------------------------
extern "C" void kernel_launch(void* const* d_in, const int* in_sizes, int n_in,
                              void* d_out, int out_size)
{
    const float* x     = (const float*)d_in[0];
    const float* gamma = (const float*)d_in[1];
    const float* beta  = (const float*)d_in[2];
    const float* Wq    = (const float*)d_in[3];
    const float* bq    = (const float*)d_in[4];
    const float* Wk    = (const float*)d_in[5];
    const float* bk    = (const float*)d_in[6];
    const float* Wv    = (const float*)d_in[7];
    const float* bv    = (const float*)d_in[8];
    const float* Wp    = (const float*)d_in[9];
    const float* bp    = (const float*)d_in[10];
    float* out = (float*)d_out;

    static bool inited = false;
    static __nv_bfloat16 *p_hb, *p_qkv, *p_wb, *p_ab, *p_wtb, *p_wpb;
    static float *p_rs, *p_bt;
    static cudaStream_t st[NGRP];          // st[0] = capture/default stream
    static cudaEvent_t evFork, evInit, evJoin[NGRP];
    if (!inited) {
        cudaGetSymbolAddress((void**)&p_hb,  g_hb);
        cudaGetSymbolAddress((void**)&p_qkv, g_qkv);
        cudaGetSymbolAddress((void**)&p_wb,  g_wb);
        cudaGetSymbolAddress((void**)&p_rs,  g_rs);
        cudaGetSymbolAddress((void**)&p_ab,  g_ab);
        cudaGetSymbolAddress((void**)&p_wtb, g_wtb);
        cudaGetSymbolAddress((void**)&p_wpb, g_wpb);
        cudaGetSymbolAddress((void**)&p_bt,  g_bt);
        cudaFuncSetAttribute(gemm_ca<1, 0, 1, 0, 0>, cudaFuncAttributeMaxDynamicSharedMemorySize, SMEM_DYN);
        cudaFuncSetAttribute(gemm_ca<0, 0, 1, 1, 0>, cudaFuncAttributeMaxDynamicSharedMemorySize, SMEM_DYN);
        cudaFuncSetAttribute(gemm_ca<0, 1, 1, 0, 1>, cudaFuncAttributeMaxDynamicSharedMemorySize, SMEM_DYN);
        cudaFuncSetAttribute(gemm_ca<0, 0, 0, 0, 0>, cudaFuncAttributeMaxDynamicSharedMemorySize, SMEM_DYN);
        st[0] = 0;
        for (int i = 1; i < NGRP; i++)
            cudaStreamCreateWithFlags(&st[i], cudaStreamNonBlocking);
        cudaEventCreateWithFlags(&evFork, cudaEventDisableTiming);
        cudaEventCreateWithFlags(&evInit, cudaEventDisableTiming);
        for (int i = 1; i < NGRP; i++)
            cudaEventCreateWithFlags(&evJoin[i], cudaEventDisableTiming);
        inited = true;
    }

    const size_t sBCT = (size_t)C_ * T_;
    const size_t sQKV = (size_t)T_ * 3 * C_;
    const size_t sBTT = (size_t)T_ * T_;
    const size_t sBTC = (size_t)T_ * C_;

    // ---- fork ----
    cudaEventRecord(evFork, 0);
    for (int i = 1; i < NGRP; i++) cudaStreamWaitEvent(st[i], evFork, 0);

    // init on stream 0: rsum memset + weight pack
    cudaMemsetAsync(p_rs, 0, (size_t)B_ * T_ * sizeof(float), 0);
    pack_w_kernel<<<(4 * C_ * C_ / 4) / 256, 256>>>(
        Wq, bq, Wk, bk, Wv, bv, Wp, p_wtb, p_wpb, p_bt);
    cudaEventRecord(evInit, 0);

    dim3 gQKV((3 * C_) / 128, T_ / 128, BG_);
    dim3 gSco(T_ / 128, T_ / 128, BG_);
    dim3 gApp(C_ / 128, T_ / 128, BG_);
    dim3 gPro(T_ / 128, C_ / 128, BG_);

    for (int g = 0; g < NGRP; g++) {
        cudaStream_t s = st[g];
        const size_t oHB  = (size_t)g * BG_ * sBCT;
        const size_t oQKV = (size_t)g * BG_ * sQKV;
        const size_t oWB  = (size_t)g * BG_ * sBTT;
        const size_t oAB  = (size_t)g * BG_ * sBTC;
        const size_t oRS  = (size_t)g * BG_ * T_;
        const size_t oX   = oHB;

        // GN for this group's 4 batches (no init dependency)
        groupnorm_kernel<<<BG_ * G_, 256, 0, s>>>(x + oX, gamma, beta, p_hb + oHB);
        // QKV and onward need pack/memset
        if (g > 0) cudaStreamWaitEvent(s, evInit, 0);

        gemm_ca<1, 0, 1, 0, 0><<<gQKV, 128, SMEM_DYN, s>>>(3 * C_, C_,
            p_hb + oHB, sBCT, T_,  p_wtb, 0, C_,
            p_qkv + oQKV, sQKV, p_bt, 1, nullptr, 0, nullptr);
        gemm_ca<0, 0, 1, 1, 0><<<gSco, 128, SMEM_DYN, s>>>(T_, C_,
            p_qkv + oQKV, sQKV, 3 * C_,  p_qkv + oQKV + C_, sQKV, 3 * C_,
            p_wb + oWB, sBTT, nullptr, 0, nullptr, 0, p_rs + oRS);
        gemm_ca<0, 1, 1, 0, 1><<<gApp, 128, SMEM_DYN, s>>>(C_, T_,
            p_wb + oWB, sBTT, T_,  p_qkv + oQKV + 2 * C_, sQKV, 3 * C_,
            p_ab + oAB, sBTC, nullptr, 0, nullptr, 0, p_rs + oRS);
        gemm_ca<0, 0, 0, 0, 0><<<gPro, 128, SMEM_DYN, s>>>(T_, C_,
            p_wpb, 0, C_,  p_ab + oAB, sBTC, C_,
            out + oX, sBCT, bp, 0, x + oX, sBCT, nullptr);

        if (g > 0) cudaEventRecord(evJoin[g], s);
    }

    // ---- join ----
    for (int i = 1; i < NGRP; i++) cudaStreamWaitEvent(0, evJoin[i], 0);
}